// round 9
// baseline (speedup 1.0000x reference)
#include <cuda_runtime.h>
#include <cuda_fp16.h>
#include <math.h>
#include <stdint.h>

#define TT   32768
#define HH   1024
#define DIN  16
#define ACD  32
#define NHH  12
#define KDIM 768
#define VDIM 1536
#define PRE  2304          // KDIM + VDIM, concatenated GEMM output width
#define HKD  64
#define HVD  128
#define NSEG 16
#define SCH  40

// ---------------- scratch ----------------
static __device__ float  d_hn   [TT * HH];
static __device__ __half d_hnf  [TT * HH];
static __device__ __half d_wcat [PRE * HH];     // rows 0..767 = Wk^T, 768..2303 = Wv^T
static __device__ float  d_pre  [TT * PRE];     // concat (kpre | vpre)
static __device__ float  d_k    [TT * KDIM];
static __device__ float  d_v    [TT * VDIM];
static __device__ float4 d_scd  [TT * NHH];     // (lam, beta, needf, 0)
static __device__ int    d_seg  [TT];
static __device__ int    d_flags[TT];
static __device__ float  d_hrows[NSEG * HH];
static __device__ float  d_q    [NSEG * KDIM];
static __device__ float  d_o    [NSEG * VDIM];
static __device__ float  d_og   [NSEG * VDIM];
static __device__ float  d_wowh [VDIM];

__device__ __forceinline__ float sigmoidf_(float x) { return 1.f / (1.f + expf(-x)); }

// ---------------- PTX helpers (base sm_103 features only) ----------------
__device__ __forceinline__ uint32_t smem_u32(const void* p) {
    uint32_t a;
    asm("{ .reg .u64 t; cvta.to.shared.u64 t, %1; cvt.u32.u64 %0, t; }" : "=r"(a) : "l"(p));
    return a;
}
__device__ __forceinline__ void cpa16s(uint32_t s, const void* g) {
    asm volatile("cp.async.cg.shared.global [%0], [%1], 16;" :: "r"(s), "l"(g));
}
__device__ __forceinline__ void cpa16(void* s, const void* g) { cpa16s(smem_u32(s), g); }
#define CPA_COMMIT asm volatile("cp.async.commit_group;")
#define CPA_WAIT0  asm volatile("cp.async.wait_group 0;")
#define CPA_WAIT1  asm volatile("cp.async.wait_group 1;")
#define CPA_WAIT2  asm volatile("cp.async.wait_group 2;")

#define LDM4(r, addr) \
    asm volatile("ldmatrix.sync.aligned.m8n8.x4.shared.b16 {%0,%1,%2,%3}, [%4];" \
        : "=r"((r)[0]), "=r"((r)[1]), "=r"((r)[2]), "=r"((r)[3]) : "r"(addr))

#define MMAH(d, a, b0, b1) \
    asm volatile("mma.sync.aligned.m16n8k16.row.col.f32.f16.f16.f32 " \
        "{%0,%1,%2,%3}, {%4,%5,%6,%7}, {%8,%9}, {%0,%1,%2,%3};" \
        : "+f"((d)[0]), "+f"((d)[1]), "+f"((d)[2]), "+f"((d)[3]) \
        : "r"((a)[0]), "r"((a)[1]), "r"((a)[2]), "r"((a)[3]), "r"(b0), "r"(b1))

// packed fp32x2 (Blackwell base ISA, sm_100+)
#define FMA2(d, a, b, c) asm("fma.rn.f32x2 %0, %1, %2, %3;" : "=l"(d) : "l"(a), "l"(b), "l"(c))
#define MUL2(d, a, b)    asm("mul.rn.f32x2 %0, %1, %2;" : "=l"(d) : "l"(a), "l"(b))
#define ADD2(d, a, b)    asm("add.rn.f32x2 %0, %1, %2;" : "=l"(d) : "l"(a), "l"(b))
#define PACKF2(d, lo, hi) asm("mov.b64 %0, {%1, %2};" : "=l"(d) : "f"(lo), "f"(hi))
#define UNPACKF2(lo, hi, s) asm("mov.b64 {%0, %1}, %2;" : "=f"(lo), "=f"(hi) : "l"(s))
#define LDSV2U64(a, b, addr) \
    asm volatile("ld.shared.v2.b64 {%0, %1}, [%2];" : "=l"(a), "=l"(b) : "r"(addr))

// ---------------- seg ids + flags ----------------
__global__ void k_prep(const int* __restrict__ cu) {
    int t = blockIdx.x * 256 + threadIdx.x;
    if (t >= TT) return;
    int seg = 0;
#pragma unroll
    for (int s = 1; s <= NSEG; ++s) if (t >= cu[s]) seg = s;
    d_seg[t] = seg;
    int fl = (t == cu[seg]) ? 1 : 0;
#pragma unroll
    for (int s = 0; s < NSEG; ++s) if (t == cu[s + 1] - 1) fl |= ((s + 1) << 1);
    d_flags[t] = fl;
}

// ---------------- embed + rmsnorm + fp16 conversion ----------------
__global__ void k_embed(const float* __restrict__ x, const int* __restrict__ acidx,
                        const float* __restrict__ actab, const float* __restrict__ Win,
                        const float* __restrict__ bin, const float* __restrict__ nw) {
    __shared__ float sx[8][48];
    __shared__ float sps[8][256];
    __shared__ float srms[8];
    int t0 = blockIdx.x * 8;
    int tid = threadIdx.x;
    for (int idx = tid; idx < 8 * 48; idx += 256) {
        int r = idx / 48, i = idx % 48;
        int t = t0 + r;
        float v;
        if (i < DIN) v = x[t * DIN + i];
        else v = actab[acidx[d_seg[t]] * ACD + (i - DIN)];
        sx[r][i] = v;
    }
    __syncthreads();

    float hreg[4][8];
    float ps[8];
#pragma unroll
    for (int r = 0; r < 8; ++r) ps[r] = 0.f;

#pragma unroll
    for (int jj = 0; jj < 4; ++jj) {
        int j = tid + jj * 256;
        float acc[8];
        float bb = bin[j];
#pragma unroll
        for (int r = 0; r < 8; ++r) acc[r] = bb;
        for (int i = 0; i < 48; ++i) {
            float w = Win[i * HH + j];
#pragma unroll
            for (int r = 0; r < 8; ++r) acc[r] = fmaf(sx[r][i], w, acc[r]);
        }
#pragma unroll
        for (int r = 0; r < 8; ++r) { hreg[jj][r] = acc[r]; ps[r] = fmaf(acc[r], acc[r], ps[r]); }
    }
#pragma unroll
    for (int r = 0; r < 8; ++r) sps[r][tid] = ps[r];
    __syncthreads();
    int w = tid >> 5, lane = tid & 31;
    float s = sps[w][lane];
#pragma unroll
    for (int i = 1; i < 8; ++i) s += sps[w][lane + 32 * i];
#pragma unroll
    for (int off = 16; off; off >>= 1) s += __shfl_xor_sync(0xffffffffu, s, off);
    if (lane == 0) srms[w] = rsqrtf(s / (float)HH + 1e-6f);
    __syncthreads();

    int needr[8];
#pragma unroll
    for (int r = 0; r < 8; ++r) needr[r] = d_flags[t0 + r] >> 1;

#pragma unroll
    for (int jj = 0; jj < 4; ++jj) {
        int j = tid + jj * 256;
        float nwj = 1.0f + nw[j];
#pragma unroll
        for (int r = 0; r < 8; ++r) {
            int t = t0 + r;
            float val = hreg[jj][r] * srms[r] * nwj;
            d_hn[t * HH + j] = val;
            d_hnf[(size_t)t * HH + j] = __float2half(val);
            if (needr[r]) d_hrows[(needr[r] - 1) * HH + j] = hreg[jj][r];
        }
    }
}

// ---------------- weight transpose + fp16: W[1024,N] -> out[N,1024] ----------------
__global__ void k_wcvt(const float* __restrict__ W, __half* __restrict__ outw, int N) {
    __shared__ float tile[32][33];
    int n0 = blockIdx.x * 32, k0 = blockIdx.y * 32;
    int tx = threadIdx.x, ty = threadIdx.y;
    for (int i = ty; i < 32; i += 8)
        tile[i][tx] = W[(size_t)(k0 + i) * N + n0 + tx];
    __syncthreads();
    for (int i = ty; i < 32; i += 8)
        outw[(size_t)(n0 + i) * HH + k0 + tx] = __float2half(tile[tx][i]);
}

// ---------------- fp16 mma.sync GEMM: d_pre[T x 2304] = hn @ [Wk|Wv] ----------------
// BM=128, BN=128, BK=32, 8 warps (2x4), warp tile 64x32, 4-stage, 1 barrier/chunk.
#define MM_ROW   40
#define MM_ATEN  (128 * MM_ROW)
#define MM_BTEN  (128 * MM_ROW)
#define MM_STG   (MM_ATEN + MM_BTEN)
#define MM_NSTG  4
#define MM_SMEM  (MM_NSTG * MM_STG * 2)    // 81920 bytes
#define MM_NCH   (HH / 32)

__global__ void __launch_bounds__(256, 2)
k_mma(const __half* __restrict__ A_, const __half* __restrict__ B_,
      float* __restrict__ C, int N) {
    extern __shared__ __align__(128) __half sm[];
    uint32_t sb = smem_u32(sm);
    int tid = threadIdx.x, lane = tid & 31, wid = tid >> 5;
    int wm = wid & 1, wn = wid >> 1;
    int ntile = blockIdx.x, mtile = blockIdx.y;

    const __half* Af = A_ + (size_t)(mtile * 128) * HH;
    const __half* Bf = B_ + (size_t)(ntile * 128) * HH;

    float acc[4][4][4];
#pragma unroll
    for (int m = 0; m < 4; ++m)
#pragma unroll
        for (int n = 0; n < 4; ++n)
#pragma unroll
            for (int i = 0; i < 4; ++i) acc[m][n][i] = 0.f;

    int ab[4];
#pragma unroll
    for (int m = 0; m < 4; ++m)
        ab[m] = (wm * 64 + m * 16 + (lane & 15)) * MM_ROW + (lane >> 4) * 8;
    int bb[2];
#pragma unroll
    for (int p = 0; p < 2; ++p)
        bb[p] = (wn * 32 + p * 16 + (lane & 7) + ((lane >> 4) & 1) * 8) * MM_ROW + ((lane >> 3) & 1) * 8;

    auto load_stage = [&](int stg, int k0) {
        uint32_t base = sb + 2 * (stg * MM_STG);
#pragma unroll
        for (int it = 0; it < 2; ++it) {
            int idx = tid + it * 256;
            int r = idx >> 2, cc = idx & 3;
            cpa16s(base + 2 * (r * MM_ROW + cc * 8), Af + (size_t)r * HH + k0 + cc * 8);
        }
#pragma unroll
        for (int it = 0; it < 2; ++it) {
            int idx = tid + it * 256;
            int r = idx >> 2, cc = idx & 3;
            cpa16s(base + 2 * (MM_ATEN + r * MM_ROW + cc * 8), Bf + (size_t)r * HH + k0 + cc * 8);
        }
    };

    load_stage(0, 0);  CPA_COMMIT;
    load_stage(1, 32); CPA_COMMIT;
    load_stage(2, 64); CPA_COMMIT;

    for (int c = 0; c < MM_NCH; ++c) {
        int stg = c & 3;
        CPA_WAIT2;              // stage c landed (always-commit keeps group count in sync)
        __syncthreads();        // all warps done with stage (c-1)%4 and see stage c
        if (c + 3 < MM_NCH) load_stage((c + 3) & 3, (c + 3) * 32);
        CPA_COMMIT;             // commit (possibly empty group)

        uint32_t base = sb + 2 * (stg * MM_STG);
#pragma unroll
        for (int ks = 0; ks < 2; ++ks) {
            uint32_t a4[4][4];
#pragma unroll
            for (int m = 0; m < 4; ++m) LDM4(a4[m], base + 2 * (ab[m] + ks * 16));
#pragma unroll
            for (int p = 0; p < 2; ++p) {
                uint32_t rb[4];
                LDM4(rb, base + 2 * (MM_ATEN + bb[p] + ks * 16));
#pragma unroll
                for (int m = 0; m < 4; ++m) {
                    MMAH(acc[m][2 * p],     a4[m], rb[0], rb[1]);
                    MMAH(acc[m][2 * p + 1], a4[m], rb[2], rb[3]);
                }
            }
        }
    }

#pragma unroll
    for (int m = 0; m < 4; ++m) {
        int row = mtile * 128 + wm * 64 + m * 16 + (lane >> 2);
#pragma unroll
        for (int n = 0; n < 4; ++n) {
            int col = ntile * 128 + wn * 32 + n * 8 + (lane & 3) * 2;
            float2 v0 = make_float2(acc[m][n][0], acc[m][n][1]);
            float2 v1 = make_float2(acc[m][n][2], acc[m][n][3]);
            *(float2*)&C[(size_t)row * N + col] = v0;
            *(float2*)&C[(size_t)(row + 8) * N + col] = v1;
        }
    }
}

// ---------------- hn@Wa, hn@Wb -> (lam, beta, need) ----------------
__global__ void k_ab(const float* __restrict__ Wa, const float* __restrict__ Wb,
                     const float* __restrict__ Alog, const float* __restrict__ dtb) {
    int row = blockIdx.x * 8 + (threadIdx.x >> 5);
    int lane = threadIdx.x & 31;
    float aA[NHH], aB[NHH];
#pragma unroll
    for (int c = 0; c < NHH; ++c) { aA[c] = 0.f; aB[c] = 0.f; }
    const float4* hp = (const float4*)(d_hn + (size_t)row * HH);
    for (int it = 0; it < 8; ++it) {
        float4 hv = hp[lane + it * 32];
        int kk = (lane + it * 32) * 4;
        const float* wa = Wa + kk * NHH;
        const float* wb = Wb + kk * NHH;
#pragma unroll
        for (int c = 0; c < NHH; ++c) {
            aA[c] = fmaf(hv.x, wa[c], aA[c]);
            aA[c] = fmaf(hv.y, wa[NHH + c], aA[c]);
            aA[c] = fmaf(hv.z, wa[2 * NHH + c], aA[c]);
            aA[c] = fmaf(hv.w, wa[3 * NHH + c], aA[c]);
            aB[c] = fmaf(hv.x, wb[c], aB[c]);
            aB[c] = fmaf(hv.y, wb[NHH + c], aB[c]);
            aB[c] = fmaf(hv.z, wb[2 * NHH + c], aB[c]);
            aB[c] = fmaf(hv.w, wb[3 * NHH + c], aB[c]);
        }
    }
#pragma unroll
    for (int c = 0; c < NHH; ++c) {
#pragma unroll
        for (int off = 16; off; off >>= 1) {
            aA[c] += __shfl_xor_sync(0xffffffffu, aA[c], off);
            aB[c] += __shfl_xor_sync(0xffffffffu, aB[c], off);
        }
    }
    if (lane < NHH) {
        float xx = aA[lane] + dtb[lane];
        float sp = (xx > 20.f) ? xx : log1pf(expf(xx));
        float g = -expf(Alog[lane]) * sp;
        int fl = d_flags[row];
        float4 o;
        o.x = (fl & 1) ? 0.f : expf(g);
        o.y = sigmoidf_(aB[lane]);
        o.z = (float)(fl >> 1);
        o.w = 0.f;
        d_scd[(size_t)row * NHH + lane] = o;
    }
}

// ---------------- k-path conv + silu + l2norm, float4 streaming ----------------
// 192 threads cover all 768 channels as float4; 16 timesteps per block; no smem.
__global__ void __launch_bounds__(192) k_convk(const float* __restrict__ cw) {
    int tid = threadIdx.x;
    int c = tid * 4;
    int t0 = blockIdx.x * 16;
    float4 w0, w1, w2, w3;
    {
        const float4* cwp = (const float4*)(cw + c * 4);
        float4 a = cwp[0], b = cwp[1], cc2 = cwp[2], d = cwp[3];
        w0 = make_float4(a.x, b.x, cc2.x, d.x);
        w1 = make_float4(a.y, b.y, cc2.y, d.y);
        w2 = make_float4(a.z, b.z, cc2.z, d.z);
        w3 = make_float4(a.w, b.w, cc2.w, d.w);
    }
    float4 xm1 = {0,0,0,0}, xm2 = {0,0,0,0}, xm3 = {0,0,0,0};
    int st1 = 1, st2 = 1;
    if (t0 >= 1) { xm1 = *(const float4*)&d_pre[(size_t)(t0 - 1) * PRE + c]; st1 = d_flags[t0 - 1] & 1; }
    if (t0 >= 2) { xm2 = *(const float4*)&d_pre[(size_t)(t0 - 2) * PRE + c]; st2 = d_flags[t0 - 2] & 1; }
    if (t0 >= 3) { xm3 = *(const float4*)&d_pre[(size_t)(t0 - 3) * PRE + c]; }

    float4 val[16];
    float ssq[16];
#pragma unroll
    for (int tt = 0; tt < 16; ++tt) {
        int t = t0 + tt;
        float4 xt = *(const float4*)&d_pre[(size_t)t * PRE + c];
        int st = d_flags[t] & 1;
        float4 a;
        a.x = xt.x * w3.x; a.y = xt.y * w3.y; a.z = xt.z * w3.z; a.w = xt.w * w3.w;
        if (!st) {
            a.x = fmaf(xm1.x, w2.x, a.x); a.y = fmaf(xm1.y, w2.y, a.y);
            a.z = fmaf(xm1.z, w2.z, a.z); a.w = fmaf(xm1.w, w2.w, a.w);
            if (!st1) {
                a.x = fmaf(xm2.x, w1.x, a.x); a.y = fmaf(xm2.y, w1.y, a.y);
                a.z = fmaf(xm2.z, w1.z, a.z); a.w = fmaf(xm2.w, w1.w, a.w);
                if (!st2) {
                    a.x = fmaf(xm3.x, w0.x, a.x); a.y = fmaf(xm3.y, w0.y, a.y);
                    a.z = fmaf(xm3.z, w0.z, a.z); a.w = fmaf(xm3.w, w0.w, a.w);
                }
            }
        }
        float4 v;
        v.x = a.x * sigmoidf_(a.x); v.y = a.y * sigmoidf_(a.y);
        v.z = a.z * sigmoidf_(a.z); v.w = a.w * sigmoidf_(a.w);
        val[tt] = v;
        ssq[tt] = fmaf(v.x, v.x, fmaf(v.y, v.y, fmaf(v.z, v.z, v.w * v.w)));
        xm3 = xm2; xm2 = xm1; xm1 = xt;
        st2 = st1; st1 = st;
    }
    // per-head (16-lane group) reduction + normalize + store
#pragma unroll
    for (int tt = 0; tt < 16; ++tt) {
        float s = ssq[tt];
        s += __shfl_xor_sync(0xffffffffu, s, 1);
        s += __shfl_xor_sync(0xffffffffu, s, 2);
        s += __shfl_xor_sync(0xffffffffu, s, 4);
        s += __shfl_xor_sync(0xffffffffu, s, 8);
        float r = rsqrtf(s + 1e-6f);
        float4 v = val[tt];
        v.x *= r; v.y *= r; v.z *= r; v.w *= r;
        *(float4*)&d_k[(size_t)(t0 + tt) * KDIM + c] = v;
    }
}

// ---------------- v-path conv + silu, float4 streaming ----------------
__global__ void __launch_bounds__(192) k_conv2(const float* __restrict__ cw) {
    int c4 = blockIdx.x * 192 + threadIdx.x;   // 0..383
    int cv = c4 * 4;                           // v-channel
    int c = KDIM + cv;                         // column in d_pre
    int t0 = blockIdx.y * 16;
    float4 w0, w1, w2, w3;
    {
        const float4* cwp = (const float4*)(cw + cv * 4);
        float4 a = cwp[0], b = cwp[1], cc2 = cwp[2], d = cwp[3];
        w0 = make_float4(a.x, b.x, cc2.x, d.x);
        w1 = make_float4(a.y, b.y, cc2.y, d.y);
        w2 = make_float4(a.z, b.z, cc2.z, d.z);
        w3 = make_float4(a.w, b.w, cc2.w, d.w);
    }
    float4 xm1 = {0,0,0,0}, xm2 = {0,0,0,0}, xm3 = {0,0,0,0};
    int st1 = 1, st2 = 1;
    if (t0 >= 1) { xm1 = *(const float4*)&d_pre[(size_t)(t0 - 1) * PRE + c]; st1 = d_flags[t0 - 1] & 1; }
    if (t0 >= 2) { xm2 = *(const float4*)&d_pre[(size_t)(t0 - 2) * PRE + c]; st2 = d_flags[t0 - 2] & 1; }
    if (t0 >= 3) { xm3 = *(const float4*)&d_pre[(size_t)(t0 - 3) * PRE + c]; }
#pragma unroll
    for (int tt = 0; tt < 16; ++tt) {
        int t = t0 + tt;
        float4 xt = *(const float4*)&d_pre[(size_t)t * PRE + c];
        int st = d_flags[t] & 1;
        float4 a;
        a.x = xt.x * w3.x; a.y = xt.y * w3.y; a.z = xt.z * w3.z; a.w = xt.w * w3.w;
        if (!st) {
            a.x = fmaf(xm1.x, w2.x, a.x); a.y = fmaf(xm1.y, w2.y, a.y);
            a.z = fmaf(xm1.z, w2.z, a.z); a.w = fmaf(xm1.w, w2.w, a.w);
            if (!st1) {
                a.x = fmaf(xm2.x, w1.x, a.x); a.y = fmaf(xm2.y, w1.y, a.y);
                a.z = fmaf(xm2.z, w1.z, a.z); a.w = fmaf(xm2.w, w1.w, a.w);
                if (!st2) {
                    a.x = fmaf(xm3.x, w0.x, a.x); a.y = fmaf(xm3.y, w0.y, a.y);
                    a.z = fmaf(xm3.z, w0.z, a.z); a.w = fmaf(xm3.w, w0.w, a.w);
                }
            }
        }
        float4 v;
        v.x = a.x * sigmoidf_(a.x); v.y = a.y * sigmoidf_(a.y);
        v.z = a.z * sigmoidf_(a.z); v.w = a.w * sigmoidf_(a.w);
        *(float4*)&d_v[(size_t)t * VDIM + cv] = v;
        xm3 = xm2; xm2 = xm1; xm1 = xt;
        st2 = st1; st1 = st;
    }
}

// ---------------- q at the 16 pooled positions ----------------
__global__ void k_q16(const int* __restrict__ cu, const float* __restrict__ Wq,
                      const float* __restrict__ cw) {
    __shared__ float shn[4][HH];
    __shared__ float sq[KDIM];
    int s = blockIdx.x;
    int pos = cu[s + 1] - 1;
    int seg = d_seg[pos];
    int tid = threadIdx.x;
    int valid[4];
#pragma unroll
    for (int r = 0; r < 4; ++r) {
        int t = pos - r;
        valid[r] = (t >= 0 && d_seg[t] == seg);
    }
#pragma unroll
    for (int r = 0; r < 4; ++r) {
        int t = pos - r;
        if (valid[r]) for (int i = tid; i < HH; i += 256) shn[r][i] = d_hn[(size_t)t * HH + i];
        else          for (int i = tid; i < HH; i += 256) shn[r][i] = 0.f;
    }
    __syncthreads();
    for (int c = tid; c < KDIM; c += 256) {
        float a0 = 0.f, a1 = 0.f, a2 = 0.f, a3 = 0.f;
        for (int i = 0; i < HH; ++i) {
            float wv = Wq[(size_t)i * KDIM + c];
            a0 = fmaf(shn[0][i], wv, a0);
            a1 = fmaf(shn[1][i], wv, a1);
            a2 = fmaf(shn[2][i], wv, a2);
            a3 = fmaf(shn[3][i], wv, a3);
        }
        float acc = a0 * cw[c * 4 + 3] + a1 * cw[c * 4 + 2] + a2 * cw[c * 4 + 1] + a3 * cw[c * 4 + 0];
        sq[c] = acc * sigmoidf_(acc);
    }
    __syncthreads();
    int w = tid >> 5, lane = tid & 31;
    for (int h = w; h < NHH; h += 8) {
        float ssq = 0.f;
        for (int i = lane; i < HKD; i += 32) { float v = sq[h * HKD + i]; ssq = fmaf(v, v, ssq); }
#pragma unroll
        for (int off = 16; off; off >>= 1) ssq += __shfl_xor_sync(0xffffffffu, ssq, off);
        float r = rsqrtf(ssq + 1e-6f) * 0.125f;
        for (int i = lane; i < HKD; i += 32)
            d_q[s * KDIM + h * HKD + i] = sq[h * HKD + i] * r;
    }
}

// ---------------- segment-parallel scan, packed f32x2 ----------------
__global__ void __launch_bounds__(128) k_scan(const int* __restrict__ cu) {
    __shared__ float  sk[2][SCH][64];
    __shared__ float  svv[2][SCH][64];
    __shared__ float4 scd[2][SCH];

    int half = blockIdx.x;
    int h    = blockIdx.y;
    int s    = blockIdx.z;
    int tid  = threadIdx.x;
    int colL = tid >> 1;
    int e    = tid & 1;
    int col  = half * 64 + colL;

    int start = cu[s];
    int end   = cu[s + 1];
    int len   = end - start;

    auto load_chunk = [&](int buf, int c0) {
        int rem = len - c0; if (rem > SCH) rem = SCH;
        for (int idx = tid; idx < rem * 16; idx += 128) {
            int i = idx >> 4, j = idx & 15;
            cpa16(&sk[buf][i][j * 4], d_k + (size_t)(start + c0 + i) * KDIM + h * HKD + j * 4);
        }
        for (int idx = tid; idx < rem * 16; idx += 128) {
            int i = idx >> 4, j = idx & 15;
            cpa16(&svv[buf][i][j * 4], d_v + (size_t)(start + c0 + i) * VDIM + h * HVD + half * 64 + j * 4);
        }
        if (tid < rem)
            cpa16(&scd[buf][tid], d_scd + (size_t)(start + c0 + tid) * NHH + h);
    };

    uint64_t S2[16];
#pragma unroll
    for (int i = 0; i < 16; ++i) S2[i] = 0ull;

    load_chunk(0, 0);
    CPA_COMMIT;

    int buf = 0;
    for (int c0 = 0; c0 < len; c0 += SCH, buf ^= 1) {
        __syncthreads();
        if (c0 + SCH < len) load_chunk(buf ^ 1, c0 + SCH);
        CPA_COMMIT;
        CPA_WAIT1;
        __syncthreads();

        int rem = len - c0; if (rem > SCH) rem = SCH;

        uint64_t nk[16];
#pragma unroll
        for (int j = 0; j < 8; ++j) {
            uint32_t addr = smem_u32(&sk[buf][0][e * 32 + j * 4]);
            LDSV2U64(nk[2 * j], nk[2 * j + 1], addr);
        }
        float  nv  = svv[buf][0][colL];
        float4 ncd = scd[buf][0];

        for (int i = 0; i < rem; ++i) {
            uint64_t K2[16];
#pragma unroll
            for (int j = 0; j < 16; ++j) K2[j] = nk[j];
            float  vv = nv;
            float4 cd = ncd;
            int ip = (i + 1 < rem) ? i + 1 : i;
#pragma unroll
            for (int j = 0; j < 8; ++j) {
                uint32_t addr = smem_u32(&sk[buf][ip][e * 32 + j * 4]);
                LDSV2U64(nk[2 * j], nk[2 * j + 1], addr);
            }
            nv  = svv[buf][ip][colL];
            ncd = scd[buf][ip];

            uint64_t a0 = 0ull, a1 = 0ull;
#pragma unroll
            for (int j = 0; j < 16; j += 2) {
                FMA2(a0, S2[j],     K2[j],     a0);
                FMA2(a1, S2[j + 1], K2[j + 1], a1);
            }
            ADD2(a0, a0, a1);
            float lo, hi;
            UNPACKF2(lo, hi, a0);
            float dot = lo + hi;
            dot += __shfl_xor_sync(0xffffffffu, dot, 1);

            float lam = cd.x;
            float delta = cd.y * fmaf(-lam, dot, vv);
            uint64_t lam2, d2;
            PACKF2(lam2, lam, lam);
            PACKF2(d2, delta, delta);
#pragma unroll
            for (int j = 0; j < 16; ++j) {
                uint64_t t;
                MUL2(t, K2[j], d2);
                FMA2(S2[j], lam2, S2[j], t);
            }

            if (cd.z != 0.f) {
                int need = (int)cd.z - 1;
                const float4* qp = (const float4*)(d_q + (size_t)need * KDIM + h * HKD + e * 32);
                uint64_t oa = 0ull;
#pragma unroll
                for (int j = 0; j < 8; ++j) {
                    float4 qv = qp[j];
                    uint64_t q0, q1;
                    PACKF2(q0, qv.x, qv.y);
                    PACKF2(q1, qv.z, qv.w);
                    FMA2(oa, S2[2 * j],     q0, oa);
                    FMA2(oa, S2[2 * j + 1], q1, oa);
                }
                float olo, ohi;
                UNPACKF2(olo, ohi, oa);
                float od = olo + ohi;
                od += __shfl_xor_sync(0xffffffffu, od, 1);
                if (e == 0) d_o[need * VDIM + h * HVD + col] = od;
            }
        }
    }
}

// ---------------- Wo @ W_head ----------------
__global__ void k_wowh(const float* __restrict__ Wo, const float* __restrict__ Wh) {
    int j = blockIdx.x * 8 + (threadIdx.x >> 5);
    int lane = threadIdx.x & 31;
    float a = 0.f;
    for (int k = lane; k < HH; k += 32) a = fmaf(Wo[(size_t)j * HH + k], Wh[k], a);
#pragma unroll
    for (int off = 16; off; off >>= 1) a += __shfl_xor_sync(0xffffffffu, a, off);
    if (lane == 0) d_wowh[j] = a;
}

// ---------------- gating at pooled positions ----------------
__global__ void k_gate(const int* __restrict__ cu, const float* __restrict__ Wg,
                       const float* __restrict__ onw) {
    __shared__ float shn[HH];
    __shared__ float sred[128];
    int hd = blockIdx.x;
    int s = blockIdx.y;
    int pos = cu[s + 1] - 1;
    int tid = threadIdx.x;
    for (int i = tid; i < HH; i += 128) shn[i] = d_hn[(size_t)pos * HH + i];
    __syncthreads();
    float gate = 0.f;
    for (int i = 0; i < HH; ++i)
        gate = fmaf(shn[i], Wg[(size_t)i * VDIM + hd * HVD + tid], gate);
    float ov = d_o[s * VDIM + hd * HVD + tid];
    sred[tid] = ov * ov;
    __syncthreads();
    for (int st = 64; st; st >>= 1) {
        if (tid < st) sred[tid] += sred[tid + st];
        __syncthreads();
    }
    float rms = rsqrtf(sred[0] / (float)HVD + 1e-5f);
    float gs = gate * sigmoidf_(gate);
    d_og[s * VDIM + hd * HVD + tid] = ov * rms * onw[tid] * gs;
}

// ---------------- final head ----------------
__global__ void k_final(const float* __restrict__ Wh, const float* __restrict__ bh,
                        float* __restrict__ out) {
    __shared__ float sred[256];
    int s = blockIdx.x;
    int tid = threadIdx.x;
    float a = 0.f;
    for (int j = tid; j < VDIM; j += 256) a = fmaf(d_og[s * VDIM + j], d_wowh[j], a);
    for (int k = tid; k < HH; k += 256) a = fmaf(d_hrows[s * HH + k], Wh[k], a);
    sred[tid] = a;
    __syncthreads();
    for (int st = 128; st; st >>= 1) {
        if (tid < st) sred[tid] += sred[tid + st];
        __syncthreads();
    }
    if (tid == 0) out[s] = sred[0] + bh[0];
}

// ---------------- launch ----------------
extern "C" void kernel_launch(void* const* d_in, const int* in_sizes, int n_in,
                              void* d_out, int out_size) {
    const float* x     = (const float*)d_in[0];
    const int*   cu    = (const int*)d_in[1];
    const int*   acidx = (const int*)d_in[2];
    const float* actab = (const float*)d_in[3];
    const float* Win   = (const float*)d_in[4];
    const float* bin   = (const float*)d_in[5];
    const float* nw    = (const float*)d_in[6];
    const float* Wq    = (const float*)d_in[7];
    const float* Wk    = (const float*)d_in[8];
    const float* Wv    = (const float*)d_in[9];
    const float* cqw   = (const float*)d_in[10];
    const float* ckw   = (const float*)d_in[11];
    const float* cvw   = (const float*)d_in[12];
    const float* Wb    = (const float*)d_in[13];
    const float* Wa    = (const float*)d_in[14];
    const float* Alog  = (const float*)d_in[15];
    const float* dtb   = (const float*)d_in[16];
    const float* Wg    = (const float*)d_in[17];
    const float* onw   = (const float*)d_in[18];
    const float* Wo    = (const float*)d_in[19];
    const float* Wh    = (const float*)d_in[20];
    const float* bh    = (const float*)d_in[21];
    float* out = (float*)d_out;

    cudaFuncSetAttribute(k_mma, cudaFuncAttributeMaxDynamicSharedMemorySize, MM_SMEM);

    __half *wcat, *hnf;
    cudaGetSymbolAddress((void**)&wcat, d_wcat);
    cudaGetSymbolAddress((void**)&hnf, d_hnf);
    float *pre;
    cudaGetSymbolAddress((void**)&pre, d_pre);

    k_prep<<<TT / 256, 256>>>(cu);
    k_embed<<<TT / 8, 256>>>(x, acidx, actab, Win, bin, nw);

    k_wcvt<<<dim3(KDIM / 32, HH / 32), dim3(32, 8)>>>(Wk, wcat, KDIM);
    k_wcvt<<<dim3(VDIM / 32, HH / 32), dim3(32, 8)>>>(Wv, wcat + (size_t)KDIM * HH, VDIM);

    k_mma<<<dim3(PRE / 128, TT / 128), 256, MM_SMEM>>>(hnf, wcat, pre, PRE);

    k_convk<<<TT / 16, 192>>>(ckw);
    k_conv2<<<dim3(2, TT / 16), 192>>>(cvw);
    k_ab<<<TT / 8, 256>>>(Wa, Wb, Alog, dtb);
    k_q16<<<NSEG, 256>>>(cu, Wq, cqw);

    k_scan<<<dim3(2, NHH, NSEG), 128>>>(cu);

    k_wowh<<<VDIM / 8, 256>>>(Wo, Wh);
    k_gate<<<dim3(NHH, NSEG), 128>>>(cu, Wg, onw);
    k_final<<<NSEG, 256>>>(Wh, bh, out);
}

// round 10
// speedup vs baseline: 1.3378x; 1.3378x over previous
#include <cuda_runtime.h>
#include <cuda_fp16.h>
#include <math.h>
#include <stdint.h>

#define TT   32768
#define HH   1024
#define DIN  16
#define ACD  32
#define NHH  12
#define KDIM 768
#define VDIM 1536
#define HKD  64
#define HVD  128
#define NSEG 16
#define SCH  40

// ---------------- scratch ----------------
static __device__ float  d_hn   [TT * HH];
static __device__ __half d_hnf  [TT * HH];
static __device__ __half d_wkf  [KDIM * HH];
static __device__ __half d_wvf  [VDIM * HH];
static __device__ float  d_kpre [TT * KDIM];
static __device__ float  d_vpre [TT * VDIM];
static __device__ float  d_k    [TT * KDIM];
static __device__ float  d_v    [TT * VDIM];
static __device__ float4 d_scd  [TT * NHH];     // (lam, beta, needf, 0)
static __device__ int    d_seg  [TT];
static __device__ int    d_flags[TT];
static __device__ float  d_hrows[NSEG * HH];
static __device__ float  d_q    [NSEG * KDIM];
static __device__ float  d_o    [NSEG * VDIM];
static __device__ float  d_og   [NSEG * VDIM];
static __device__ float  d_wowh [VDIM];

__device__ __forceinline__ float sigmoidf_(float x) { return 1.f / (1.f + expf(-x)); }

// ---------------- PTX helpers (base sm_103 features only) ----------------
__device__ __forceinline__ uint32_t smem_u32(const void* p) {
    uint32_t a;
    asm("{ .reg .u64 t; cvta.to.shared.u64 t, %1; cvt.u32.u64 %0, t; }" : "=r"(a) : "l"(p));
    return a;
}
__device__ __forceinline__ void cpa16s(uint32_t s, const void* g) {
    asm volatile("cp.async.cg.shared.global [%0], [%1], 16;" :: "r"(s), "l"(g));
}
__device__ __forceinline__ void cpa16(void* s, const void* g) { cpa16s(smem_u32(s), g); }
#define CPA_COMMIT asm volatile("cp.async.commit_group;")
#define CPA_WAIT0  asm volatile("cp.async.wait_group 0;")
#define CPA_WAIT1  asm volatile("cp.async.wait_group 1;")

#define LDM4(r, addr) \
    asm volatile("ldmatrix.sync.aligned.m8n8.x4.shared.b16 {%0,%1,%2,%3}, [%4];" \
        : "=r"((r)[0]), "=r"((r)[1]), "=r"((r)[2]), "=r"((r)[3]) : "r"(addr))

#define MMAH(d, a, b0, b1) \
    asm volatile("mma.sync.aligned.m16n8k16.row.col.f32.f16.f16.f32 " \
        "{%0,%1,%2,%3}, {%4,%5,%6,%7}, {%8,%9}, {%0,%1,%2,%3};" \
        : "+f"((d)[0]), "+f"((d)[1]), "+f"((d)[2]), "+f"((d)[3]) \
        : "r"((a)[0]), "r"((a)[1]), "r"((a)[2]), "r"((a)[3]), "r"(b0), "r"(b1))

// packed fp32x2 (Blackwell base ISA, sm_100+)
#define FMA2(d, a, b, c) asm("fma.rn.f32x2 %0, %1, %2, %3;" : "=l"(d) : "l"(a), "l"(b), "l"(c))
#define MUL2(d, a, b)    asm("mul.rn.f32x2 %0, %1, %2;" : "=l"(d) : "l"(a), "l"(b))
#define ADD2(d, a, b)    asm("add.rn.f32x2 %0, %1, %2;" : "=l"(d) : "l"(a), "l"(b))
#define PACKF2(d, lo, hi) asm("mov.b64 %0, {%1, %2};" : "=l"(d) : "f"(lo), "f"(hi))
#define UNPACKF2(lo, hi, s) asm("mov.b64 {%0, %1}, %2;" : "=f"(lo), "=f"(hi) : "l"(s))
#define LDSV2U64(a, b, addr) \
    asm volatile("ld.shared.v2.b64 {%0, %1}, [%2];" : "=l"(a), "=l"(b) : "r"(addr))

// ---------------- seg ids + flags ----------------
__global__ void k_prep(const int* __restrict__ cu) {
    int t = blockIdx.x * 256 + threadIdx.x;
    if (t >= TT) return;
    int seg = 0;
#pragma unroll
    for (int s = 1; s <= NSEG; ++s) if (t >= cu[s]) seg = s;
    d_seg[t] = seg;
    int fl = (t == cu[seg]) ? 1 : 0;
#pragma unroll
    for (int s = 0; s < NSEG; ++s) if (t == cu[s + 1] - 1) fl |= ((s + 1) << 1);
    d_flags[t] = fl;
}

// ---------------- embed + rmsnorm + fp16 conversion ----------------
__global__ void k_embed(const float* __restrict__ x, const int* __restrict__ acidx,
                        const float* __restrict__ actab, const float* __restrict__ Win,
                        const float* __restrict__ bin, const float* __restrict__ nw) {
    __shared__ float sx[8][48];
    __shared__ float sps[8][256];
    __shared__ float srms[8];
    int t0 = blockIdx.x * 8;
    int tid = threadIdx.x;
    for (int idx = tid; idx < 8 * 48; idx += 256) {
        int r = idx / 48, i = idx % 48;
        int t = t0 + r;
        float v;
        if (i < DIN) v = x[t * DIN + i];
        else v = actab[acidx[d_seg[t]] * ACD + (i - DIN)];
        sx[r][i] = v;
    }
    __syncthreads();

    float hreg[4][8];
    float ps[8];
#pragma unroll
    for (int r = 0; r < 8; ++r) ps[r] = 0.f;

#pragma unroll
    for (int jj = 0; jj < 4; ++jj) {
        int j = tid + jj * 256;
        float acc[8];
        float bb = bin[j];
#pragma unroll
        for (int r = 0; r < 8; ++r) acc[r] = bb;
        for (int i = 0; i < 48; ++i) {
            float w = Win[i * HH + j];
#pragma unroll
            for (int r = 0; r < 8; ++r) acc[r] = fmaf(sx[r][i], w, acc[r]);
        }
#pragma unroll
        for (int r = 0; r < 8; ++r) { hreg[jj][r] = acc[r]; ps[r] = fmaf(acc[r], acc[r], ps[r]); }
    }
#pragma unroll
    for (int r = 0; r < 8; ++r) sps[r][tid] = ps[r];
    __syncthreads();
    int w = tid >> 5, lane = tid & 31;
    float s = sps[w][lane];
#pragma unroll
    for (int i = 1; i < 8; ++i) s += sps[w][lane + 32 * i];
#pragma unroll
    for (int off = 16; off; off >>= 1) s += __shfl_xor_sync(0xffffffffu, s, off);
    if (lane == 0) srms[w] = rsqrtf(s / (float)HH + 1e-6f);
    __syncthreads();

    int needr[8];
#pragma unroll
    for (int r = 0; r < 8; ++r) needr[r] = d_flags[t0 + r] >> 1;

#pragma unroll
    for (int jj = 0; jj < 4; ++jj) {
        int j = tid + jj * 256;
        float nwj = 1.0f + nw[j];
#pragma unroll
        for (int r = 0; r < 8; ++r) {
            int t = t0 + r;
            float val = hreg[jj][r] * srms[r] * nwj;
            d_hn[t * HH + j] = val;
            d_hnf[(size_t)t * HH + j] = __float2half(val);
            if (needr[r]) d_hrows[(needr[r] - 1) * HH + j] = hreg[jj][r];
        }
    }
}

// ---------------- weight transpose + fp16 ----------------
__global__ void k_wcvt(const float* __restrict__ W, __half* __restrict__ outw, int N) {
    __shared__ float tile[32][33];
    int n0 = blockIdx.x * 32, k0 = blockIdx.y * 32;
    int tx = threadIdx.x, ty = threadIdx.y;
    for (int i = ty; i < 32; i += 8)
        tile[i][tx] = W[(size_t)(k0 + i) * N + n0 + tx];
    __syncthreads();
    for (int i = ty; i < 32; i += 8)
        outw[(size_t)(n0 + i) * HH + k0 + tx] = __float2half(tile[tx][i]);
}

// ---------------- fp16 mma.sync GEMM (exact R8 version) ----------------
#define MM_ROW   40
#define MM_ATEN  (128 * MM_ROW)
#define MM_BTEN  (128 * MM_ROW)
#define MM_STG   (MM_ATEN + MM_BTEN)
#define MM_NSTG  3
#define MM_SMEM  (MM_NSTG * MM_STG * 2)
#define MM_NCH   (HH / 32)

__global__ void __launch_bounds__(256, 2)
k_mma(const __half* __restrict__ A_, const __half* __restrict__ B_,
      float* __restrict__ C, int N) {
    extern __shared__ __align__(128) __half sm[];
    uint32_t sb = smem_u32(sm);
    int tid = threadIdx.x, lane = tid & 31, wid = tid >> 5;
    int wm = wid & 1, wn = wid >> 1;
    int ntile = blockIdx.x, mtile = blockIdx.y;

    const __half* Af = A_ + (size_t)(mtile * 128) * HH;
    const __half* Bf = B_ + (size_t)(ntile * 128) * HH;

    float acc[4][4][4];
#pragma unroll
    for (int m = 0; m < 4; ++m)
#pragma unroll
        for (int n = 0; n < 4; ++n)
#pragma unroll
            for (int i = 0; i < 4; ++i) acc[m][n][i] = 0.f;

    int ab[4];
#pragma unroll
    for (int m = 0; m < 4; ++m)
        ab[m] = (wm * 64 + m * 16 + (lane & 15)) * MM_ROW + (lane >> 4) * 8;
    int bb[2];
#pragma unroll
    for (int p = 0; p < 2; ++p)
        bb[p] = (wn * 32 + p * 16 + (lane & 7) + ((lane >> 4) & 1) * 8) * MM_ROW + ((lane >> 3) & 1) * 8;

    auto load_stage = [&](int stg, int k0) {
        uint32_t base = sb + 2 * (stg * MM_STG);
#pragma unroll
        for (int it = 0; it < 2; ++it) {
            int idx = tid + it * 256;
            int r = idx >> 2, cc = idx & 3;
            cpa16s(base + 2 * (r * MM_ROW + cc * 8), Af + (size_t)r * HH + k0 + cc * 8);
        }
#pragma unroll
        for (int it = 0; it < 2; ++it) {
            int idx = tid + it * 256;
            int r = idx >> 2, cc = idx & 3;
            cpa16s(base + 2 * (MM_ATEN + r * MM_ROW + cc * 8), Bf + (size_t)r * HH + k0 + cc * 8);
        }
    };

    load_stage(0, 0);
    CPA_COMMIT;
    load_stage(1, 32);
    CPA_COMMIT;

    for (int c = 0; c < MM_NCH; ++c) {
        int stg = c % MM_NSTG;
        if (c + 1 < MM_NCH) { CPA_WAIT1; } else { CPA_WAIT0; }
        __syncthreads();
        if (c + 2 < MM_NCH) {
            load_stage((c + 2) % MM_NSTG, (c + 2) * 32);
            CPA_COMMIT;
        }

        uint32_t base = sb + 2 * (stg * MM_STG);
#pragma unroll
        for (int ks = 0; ks < 2; ++ks) {
            uint32_t a4[4][4];
#pragma unroll
            for (int m = 0; m < 4; ++m) LDM4(a4[m], base + 2 * (ab[m] + ks * 16));
#pragma unroll
            for (int p = 0; p < 2; ++p) {
                uint32_t rb[4];
                LDM4(rb, base + 2 * (MM_ATEN + bb[p] + ks * 16));
#pragma unroll
                for (int m = 0; m < 4; ++m) {
                    MMAH(acc[m][2 * p],     a4[m], rb[0], rb[1]);
                    MMAH(acc[m][2 * p + 1], a4[m], rb[2], rb[3]);
                }
            }
        }
        __syncthreads();
    }

#pragma unroll
    for (int m = 0; m < 4; ++m) {
        int row = mtile * 128 + wm * 64 + m * 16 + (lane >> 2);
#pragma unroll
        for (int n = 0; n < 4; ++n) {
            int col = ntile * 128 + wn * 32 + n * 8 + (lane & 3) * 2;
            float2 v0 = make_float2(acc[m][n][0], acc[m][n][1]);
            float2 v1 = make_float2(acc[m][n][2], acc[m][n][3]);
            *(float2*)&C[(size_t)row * N + col] = v0;
            *(float2*)&C[(size_t)(row + 8) * N + col] = v1;
        }
    }
}

// ---------------- hn@Wa, hn@Wb -> (lam, beta, need) (exact R8) ----------------
__global__ void k_ab(const float* __restrict__ Wa, const float* __restrict__ Wb,
                     const float* __restrict__ Alog, const float* __restrict__ dtb) {
    int row = blockIdx.x * 8 + (threadIdx.x >> 5);
    int lane = threadIdx.x & 31;
    float aA[NHH], aB[NHH];
#pragma unroll
    for (int c = 0; c < NHH; ++c) { aA[c] = 0.f; aB[c] = 0.f; }
    for (int kk = lane; kk < HH; kk += 32) {
        float hv = d_hn[(size_t)row * HH + kk];
        const float* wa = Wa + kk * NHH;
        const float* wb = Wb + kk * NHH;
#pragma unroll
        for (int c = 0; c < NHH; ++c) {
            aA[c] = fmaf(hv, wa[c], aA[c]);
            aB[c] = fmaf(hv, wb[c], aB[c]);
        }
    }
#pragma unroll
    for (int c = 0; c < NHH; ++c) {
#pragma unroll
        for (int off = 16; off; off >>= 1) {
            aA[c] += __shfl_xor_sync(0xffffffffu, aA[c], off);
            aB[c] += __shfl_xor_sync(0xffffffffu, aB[c], off);
        }
    }
    if (lane < NHH) {
        float xx = aA[lane] + dtb[lane];
        float sp = (xx > 20.f) ? xx : log1pf(expf(xx));
        float g = -expf(Alog[lane]) * sp;
        int fl = d_flags[row];
        float4 o;
        o.x = (fl & 1) ? 0.f : expf(g);
        o.y = sigmoidf_(aB[lane]);
        o.z = (float)(fl >> 1);
        o.w = 0.f;
        d_scd[(size_t)row * NHH + lane] = o;
    }
}

// ---------------- k-path conv + silu + l2norm, float4, 8 timesteps ----------------
// 192 threads = all 768 channels as float4. Per-head l2norm via 16-lane shfl.
#define KTCH 8
__global__ void __launch_bounds__(192) k_convk(const float* __restrict__ cw) {
    int tid = threadIdx.x;
    int c = tid * 4;
    int t0 = blockIdx.x * KTCH;
    float4 w0, w1, w2, w3;
    {
        const float4* cwp = (const float4*)(cw + c * 4);
        float4 a = cwp[0], b = cwp[1], cc2 = cwp[2], d = cwp[3];
        w0 = make_float4(a.x, b.x, cc2.x, d.x);
        w1 = make_float4(a.y, b.y, cc2.y, d.y);
        w2 = make_float4(a.z, b.z, cc2.z, d.z);
        w3 = make_float4(a.w, b.w, cc2.w, d.w);
    }
    float4 xm1 = {0,0,0,0}, xm2 = {0,0,0,0}, xm3 = {0,0,0,0};
    int st1 = 1, st2 = 1;
    if (t0 >= 1) { xm1 = *(const float4*)&d_kpre[(size_t)(t0 - 1) * KDIM + c]; st1 = d_flags[t0 - 1] & 1; }
    if (t0 >= 2) { xm2 = *(const float4*)&d_kpre[(size_t)(t0 - 2) * KDIM + c]; st2 = d_flags[t0 - 2] & 1; }
    if (t0 >= 3) { xm3 = *(const float4*)&d_kpre[(size_t)(t0 - 3) * KDIM + c]; }

    float4 val[KTCH];
    float ssq[KTCH];
#pragma unroll
    for (int tt = 0; tt < KTCH; ++tt) {
        int t = t0 + tt;
        float4 xt = *(const float4*)&d_kpre[(size_t)t * KDIM + c];
        int st = d_flags[t] & 1;
        float4 a;
        a.x = xt.x * w3.x; a.y = xt.y * w3.y; a.z = xt.z * w3.z; a.w = xt.w * w3.w;
        if (!st) {
            a.x = fmaf(xm1.x, w2.x, a.x); a.y = fmaf(xm1.y, w2.y, a.y);
            a.z = fmaf(xm1.z, w2.z, a.z); a.w = fmaf(xm1.w, w2.w, a.w);
            if (!st1) {
                a.x = fmaf(xm2.x, w1.x, a.x); a.y = fmaf(xm2.y, w1.y, a.y);
                a.z = fmaf(xm2.z, w1.z, a.z); a.w = fmaf(xm2.w, w1.w, a.w);
                if (!st2) {
                    a.x = fmaf(xm3.x, w0.x, a.x); a.y = fmaf(xm3.y, w0.y, a.y);
                    a.z = fmaf(xm3.z, w0.z, a.z); a.w = fmaf(xm3.w, w0.w, a.w);
                }
            }
        }
        float4 v;
        v.x = a.x * sigmoidf_(a.x); v.y = a.y * sigmoidf_(a.y);
        v.z = a.z * sigmoidf_(a.z); v.w = a.w * sigmoidf_(a.w);
        val[tt] = v;
        ssq[tt] = fmaf(v.x, v.x, fmaf(v.y, v.y, fmaf(v.z, v.z, v.w * v.w)));
        xm3 = xm2; xm2 = xm1; xm1 = xt;
        st2 = st1; st1 = st;
    }
#pragma unroll
    for (int tt = 0; tt < KTCH; ++tt) {
        float s = ssq[tt];
        s += __shfl_xor_sync(0xffffffffu, s, 1);
        s += __shfl_xor_sync(0xffffffffu, s, 2);
        s += __shfl_xor_sync(0xffffffffu, s, 4);
        s += __shfl_xor_sync(0xffffffffu, s, 8);
        float r = rsqrtf(s + 1e-6f);
        float4 v = val[tt];
        v.x *= r; v.y *= r; v.z *= r; v.w *= r;
        *(float4*)&d_k[(size_t)(t0 + tt) * KDIM + c] = v;
    }
}

// ---------------- v-path conv + silu, float4, immediate store ----------------
#define VTCH 16
__global__ void __launch_bounds__(192) k_conv2(const float* __restrict__ cw) {
    int c = (blockIdx.x * 192 + threadIdx.x) * 4;   // v-channel, 0..1532
    int t0 = blockIdx.y * VTCH;
    float4 w0, w1, w2, w3;
    {
        const float4* cwp = (const float4*)(cw + c * 4);
        float4 a = cwp[0], b = cwp[1], cc2 = cwp[2], d = cwp[3];
        w0 = make_float4(a.x, b.x, cc2.x, d.x);
        w1 = make_float4(a.y, b.y, cc2.y, d.y);
        w2 = make_float4(a.z, b.z, cc2.z, d.z);
        w3 = make_float4(a.w, b.w, cc2.w, d.w);
    }
    float4 xm1 = {0,0,0,0}, xm2 = {0,0,0,0}, xm3 = {0,0,0,0};
    int st1 = 1, st2 = 1;
    if (t0 >= 1) { xm1 = *(const float4*)&d_vpre[(size_t)(t0 - 1) * VDIM + c]; st1 = d_flags[t0 - 1] & 1; }
    if (t0 >= 2) { xm2 = *(const float4*)&d_vpre[(size_t)(t0 - 2) * VDIM + c]; st2 = d_flags[t0 - 2] & 1; }
    if (t0 >= 3) { xm3 = *(const float4*)&d_vpre[(size_t)(t0 - 3) * VDIM + c]; }
#pragma unroll 4
    for (int tt = 0; tt < VTCH; ++tt) {
        int t = t0 + tt;
        float4 xt = *(const float4*)&d_vpre[(size_t)t * VDIM + c];
        int st = d_flags[t] & 1;
        float4 a;
        a.x = xt.x * w3.x; a.y = xt.y * w3.y; a.z = xt.z * w3.z; a.w = xt.w * w3.w;
        if (!st) {
            a.x = fmaf(xm1.x, w2.x, a.x); a.y = fmaf(xm1.y, w2.y, a.y);
            a.z = fmaf(xm1.z, w2.z, a.z); a.w = fmaf(xm1.w, w2.w, a.w);
            if (!st1) {
                a.x = fmaf(xm2.x, w1.x, a.x); a.y = fmaf(xm2.y, w1.y, a.y);
                a.z = fmaf(xm2.z, w1.z, a.z); a.w = fmaf(xm2.w, w1.w, a.w);
                if (!st2) {
                    a.x = fmaf(xm3.x, w0.x, a.x); a.y = fmaf(xm3.y, w0.y, a.y);
                    a.z = fmaf(xm3.z, w0.z, a.z); a.w = fmaf(xm3.w, w0.w, a.w);
                }
            }
        }
        float4 v;
        v.x = a.x * sigmoidf_(a.x); v.y = a.y * sigmoidf_(a.y);
        v.z = a.z * sigmoidf_(a.z); v.w = a.w * sigmoidf_(a.w);
        *(float4*)&d_v[(size_t)t * VDIM + c] = v;
        xm3 = xm2; xm2 = xm1; xm1 = xt;
        st2 = st1; st1 = st;
    }
}

// ---------------- q at the 16 pooled positions ----------------
__global__ void k_q16(const int* __restrict__ cu, const float* __restrict__ Wq,
                      const float* __restrict__ cw) {
    __shared__ float shn[4][HH];
    __shared__ float sq[KDIM];
    int s = blockIdx.x;
    int pos = cu[s + 1] - 1;
    int seg = d_seg[pos];
    int tid = threadIdx.x;
    int valid[4];
#pragma unroll
    for (int r = 0; r < 4; ++r) {
        int t = pos - r;
        valid[r] = (t >= 0 && d_seg[t] == seg);
    }
#pragma unroll
    for (int r = 0; r < 4; ++r) {
        int t = pos - r;
        if (valid[r]) for (int i = tid; i < HH; i += 256) shn[r][i] = d_hn[(size_t)t * HH + i];
        else          for (int i = tid; i < HH; i += 256) shn[r][i] = 0.f;
    }
    __syncthreads();
    for (int c = tid; c < KDIM; c += 256) {
        float a0 = 0.f, a1 = 0.f, a2 = 0.f, a3 = 0.f;
        for (int i = 0; i < HH; ++i) {
            float wv = Wq[(size_t)i * KDIM + c];
            a0 = fmaf(shn[0][i], wv, a0);
            a1 = fmaf(shn[1][i], wv, a1);
            a2 = fmaf(shn[2][i], wv, a2);
            a3 = fmaf(shn[3][i], wv, a3);
        }
        float acc = a0 * cw[c * 4 + 3] + a1 * cw[c * 4 + 2] + a2 * cw[c * 4 + 1] + a3 * cw[c * 4 + 0];
        sq[c] = acc * sigmoidf_(acc);
    }
    __syncthreads();
    int w = tid >> 5, lane = tid & 31;
    for (int h = w; h < NHH; h += 8) {
        float ssq = 0.f;
        for (int i = lane; i < HKD; i += 32) { float v = sq[h * HKD + i]; ssq = fmaf(v, v, ssq); }
#pragma unroll
        for (int off = 16; off; off >>= 1) ssq += __shfl_xor_sync(0xffffffffu, ssq, off);
        float r = rsqrtf(ssq + 1e-6f) * 0.125f;
        for (int i = lane; i < HKD; i += 32)
            d_q[s * KDIM + h * HKD + i] = sq[h * HKD + i] * r;
    }
}

// ---------------- segment-parallel scan, packed f32x2 (exact R8) ----------------
__global__ void __launch_bounds__(128) k_scan(const int* __restrict__ cu) {
    __shared__ float  sk[2][SCH][64];
    __shared__ float  svv[2][SCH][64];
    __shared__ float4 scd[2][SCH];

    int half = blockIdx.x;
    int h    = blockIdx.y;
    int s    = blockIdx.z;
    int tid  = threadIdx.x;
    int colL = tid >> 1;
    int e    = tid & 1;
    int col  = half * 64 + colL;

    int start = cu[s];
    int end   = cu[s + 1];
    int len   = end - start;

    auto load_chunk = [&](int buf, int c0) {
        int rem = len - c0; if (rem > SCH) rem = SCH;
        for (int idx = tid; idx < rem * 16; idx += 128) {
            int i = idx >> 4, j = idx & 15;
            cpa16(&sk[buf][i][j * 4], d_k + (size_t)(start + c0 + i) * KDIM + h * HKD + j * 4);
        }
        for (int idx = tid; idx < rem * 16; idx += 128) {
            int i = idx >> 4, j = idx & 15;
            cpa16(&svv[buf][i][j * 4], d_v + (size_t)(start + c0 + i) * VDIM + h * HVD + half * 64 + j * 4);
        }
        if (tid < rem)
            cpa16(&scd[buf][tid], d_scd + (size_t)(start + c0 + tid) * NHH + h);
    };

    uint64_t S2[16];
#pragma unroll
    for (int i = 0; i < 16; ++i) S2[i] = 0ull;

    load_chunk(0, 0);
    CPA_COMMIT;

    int buf = 0;
    for (int c0 = 0; c0 < len; c0 += SCH, buf ^= 1) {
        __syncthreads();
        if (c0 + SCH < len) load_chunk(buf ^ 1, c0 + SCH);
        CPA_COMMIT;
        CPA_WAIT1;
        __syncthreads();

        int rem = len - c0; if (rem > SCH) rem = SCH;

        uint64_t nk[16];
#pragma unroll
        for (int j = 0; j < 8; ++j) {
            uint32_t addr = smem_u32(&sk[buf][0][e * 32 + j * 4]);
            LDSV2U64(nk[2 * j], nk[2 * j + 1], addr);
        }
        float  nv  = svv[buf][0][colL];
        float4 ncd = scd[buf][0];

        for (int i = 0; i < rem; ++i) {
            uint64_t K2[16];
#pragma unroll
            for (int j = 0; j < 16; ++j) K2[j] = nk[j];
            float  vv = nv;
            float4 cd = ncd;
            int ip = (i + 1 < rem) ? i + 1 : i;
#pragma unroll
            for (int j = 0; j < 8; ++j) {
                uint32_t addr = smem_u32(&sk[buf][ip][e * 32 + j * 4]);
                LDSV2U64(nk[2 * j], nk[2 * j + 1], addr);
            }
            nv  = svv[buf][ip][colL];
            ncd = scd[buf][ip];

            uint64_t a0 = 0ull, a1 = 0ull;
#pragma unroll
            for (int j = 0; j < 16; j += 2) {
                FMA2(a0, S2[j],     K2[j],     a0);
                FMA2(a1, S2[j + 1], K2[j + 1], a1);
            }
            ADD2(a0, a0, a1);
            float lo, hi;
            UNPACKF2(lo, hi, a0);
            float dot = lo + hi;
            dot += __shfl_xor_sync(0xffffffffu, dot, 1);

            float lam = cd.x;
            float delta = cd.y * fmaf(-lam, dot, vv);
            uint64_t lam2, d2;
            PACKF2(lam2, lam, lam);
            PACKF2(d2, delta, delta);
#pragma unroll
            for (int j = 0; j < 16; ++j) {
                uint64_t t;
                MUL2(t, K2[j], d2);
                FMA2(S2[j], lam2, S2[j], t);
            }

            if (cd.z != 0.f) {
                int need = (int)cd.z - 1;
                const float4* qp = (const float4*)(d_q + (size_t)need * KDIM + h * HKD + e * 32);
                uint64_t oa = 0ull;
#pragma unroll
                for (int j = 0; j < 8; ++j) {
                    float4 qv = qp[j];
                    uint64_t q0, q1;
                    PACKF2(q0, qv.x, qv.y);
                    PACKF2(q1, qv.z, qv.w);
                    FMA2(oa, S2[2 * j],     q0, oa);
                    FMA2(oa, S2[2 * j + 1], q1, oa);
                }
                float olo, ohi;
                UNPACKF2(olo, ohi, oa);
                float od = olo + ohi;
                od += __shfl_xor_sync(0xffffffffu, od, 1);
                if (e == 0) d_o[need * VDIM + h * HVD + col] = od;
            }
        }
    }
}

// ---------------- Wo @ W_head ----------------
__global__ void k_wowh(const float* __restrict__ Wo, const float* __restrict__ Wh) {
    int j = blockIdx.x * 8 + (threadIdx.x >> 5);
    int lane = threadIdx.x & 31;
    float a = 0.f;
    for (int k = lane; k < HH; k += 32) a = fmaf(Wo[(size_t)j * HH + k], Wh[k], a);
#pragma unroll
    for (int off = 16; off; off >>= 1) a += __shfl_xor_sync(0xffffffffu, a, off);
    if (lane == 0) d_wowh[j] = a;
}

// ---------------- gating at pooled positions ----------------
__global__ void k_gate(const int* __restrict__ cu, const float* __restrict__ Wg,
                       const float* __restrict__ onw) {
    __shared__ float shn[HH];
    __shared__ float sred[128];
    int hd = blockIdx.x;
    int s = blockIdx.y;
    int pos = cu[s + 1] - 1;
    int tid = threadIdx.x;
    for (int i = tid; i < HH; i += 128) shn[i] = d_hn[(size_t)pos * HH + i];
    __syncthreads();
    float gate = 0.f;
    for (int i = 0; i < HH; ++i)
        gate = fmaf(shn[i], Wg[(size_t)i * VDIM + hd * HVD + tid], gate);
    float ov = d_o[s * VDIM + hd * HVD + tid];
    sred[tid] = ov * ov;
    __syncthreads();
    for (int st = 64; st; st >>= 1) {
        if (tid < st) sred[tid] += sred[tid + st];
        __syncthreads();
    }
    float rms = rsqrtf(sred[0] / (float)HVD + 1e-5f);
    float gs = gate * sigmoidf_(gate);
    d_og[s * VDIM + hd * HVD + tid] = ov * rms * onw[tid] * gs;
}

// ---------------- final head ----------------
__global__ void k_final(const float* __restrict__ Wh, const float* __restrict__ bh,
                        float* __restrict__ out) {
    __shared__ float sred[256];
    int s = blockIdx.x;
    int tid = threadIdx.x;
    float a = 0.f;
    for (int j = tid; j < VDIM; j += 256) a = fmaf(d_og[s * VDIM + j], d_wowh[j], a);
    for (int k = tid; k < HH; k += 256) a = fmaf(d_hrows[s * HH + k], Wh[k], a);
    sred[tid] = a;
    __syncthreads();
    for (int st = 128; st; st >>= 1) {
        if (tid < st) sred[tid] += sred[tid + st];
        __syncthreads();
    }
    if (tid == 0) out[s] = sred[0] + bh[0];
}

// ---------------- launch ----------------
extern "C" void kernel_launch(void* const* d_in, const int* in_sizes, int n_in,
                              void* d_out, int out_size) {
    const float* x     = (const float*)d_in[0];
    const int*   cu    = (const int*)d_in[1];
    const int*   acidx = (const int*)d_in[2];
    const float* actab = (const float*)d_in[3];
    const float* Win   = (const float*)d_in[4];
    const float* bin   = (const float*)d_in[5];
    const float* nw    = (const float*)d_in[6];
    const float* Wq    = (const float*)d_in[7];
    const float* Wk    = (const float*)d_in[8];
    const float* Wv    = (const float*)d_in[9];
    const float* cqw   = (const float*)d_in[10];
    const float* ckw   = (const float*)d_in[11];
    const float* cvw   = (const float*)d_in[12];
    const float* Wb    = (const float*)d_in[13];
    const float* Wa    = (const float*)d_in[14];
    const float* Alog  = (const float*)d_in[15];
    const float* dtb   = (const float*)d_in[16];
    const float* Wg    = (const float*)d_in[17];
    const float* onw   = (const float*)d_in[18];
    const float* Wo    = (const float*)d_in[19];
    const float* Wh    = (const float*)d_in[20];
    const float* bh    = (const float*)d_in[21];
    float* out = (float*)d_out;

    cudaFuncSetAttribute(k_mma, cudaFuncAttributeMaxDynamicSharedMemorySize, MM_SMEM);

    __half *wkf, *wvf, *hnf;
    cudaGetSymbolAddress((void**)&wkf, d_wkf);
    cudaGetSymbolAddress((void**)&wvf, d_wvf);
    cudaGetSymbolAddress((void**)&hnf, d_hnf);
    float *kpre, *vpre;
    cudaGetSymbolAddress((void**)&kpre, d_kpre);
    cudaGetSymbolAddress((void**)&vpre, d_vpre);

    k_prep<<<TT / 256, 256>>>(cu);
    k_embed<<<TT / 8, 256>>>(x, acidx, actab, Win, bin, nw);

    k_wcvt<<<dim3(VDIM / 32, HH / 32), dim3(32, 8)>>>(Wv, wvf, VDIM);
    k_mma<<<dim3(VDIM / 128, TT / 128), 256, MM_SMEM>>>(hnf, wvf, vpre, VDIM);
    k_wcvt<<<dim3(KDIM / 32, HH / 32), dim3(32, 8)>>>(Wk, wkf, KDIM);
    k_mma<<<dim3(KDIM / 128, TT / 128), 256, MM_SMEM>>>(hnf, wkf, kpre, KDIM);

    k_ab<<<TT / 8, 256>>>(Wa, Wb, Alog, dtb);
    k_convk<<<TT / KTCH, 192>>>(ckw);
    k_conv2<<<dim3(VDIM / (192 * 4), TT / VTCH), 192>>>(cvw);
    k_q16<<<NSEG, 256>>>(cu, Wq, cqw);

    k_scan<<<dim3(2, NHH, NSEG), 128>>>(cu);

    k_wowh<<<VDIM / 8, 256>>>(Wo, Wh);
    k_gate<<<dim3(NHH, NSEG), 128>>>(cu, Wg, onw);
    k_final<<<NSEG, 256>>>(Wh, bh, out);
}

// round 11
// speedup vs baseline: 1.4569x; 1.0890x over previous
#include <cuda_runtime.h>
#include <cuda_fp16.h>
#include <math.h>
#include <stdint.h>

#define TT   32768
#define HH   1024
#define DIN  16
#define ACD  32
#define NHH  12
#define KDIM 768
#define VDIM 1536
#define HKD  64
#define HVD  128
#define NSEG 16
#define SCH  40

// ---------------- scratch ----------------
static __device__ float  d_hn   [TT * HH];
static __device__ __half d_hnf  [TT * HH];
static __device__ __half d_wkf  [KDIM * HH];
static __device__ __half d_wvf  [VDIM * HH];
static __device__ float  d_kpre [TT * KDIM];
static __device__ float  d_vpre [TT * VDIM];
static __device__ float  d_k    [TT * KDIM];
static __device__ float  d_v    [TT * VDIM];
static __device__ float4 d_scd  [TT * NHH];     // (lam, beta, needf, 0)
static __device__ float  d_wt   [24 * HH];      // [Wa^T | Wb^T]
static __device__ int    d_seg  [TT];
static __device__ int    d_flags[TT];
static __device__ float  d_hrows[NSEG * HH];
static __device__ float  d_q    [NSEG * KDIM];
static __device__ float  d_o    [NSEG * VDIM];
static __device__ float  d_og   [NSEG * VDIM];
static __device__ float  d_wowh [VDIM];

__device__ __forceinline__ float sigmoidf_(float x) { return 1.f / (1.f + expf(-x)); }

// ---------------- PTX helpers (base sm_103 features only) ----------------
__device__ __forceinline__ uint32_t smem_u32(const void* p) {
    uint32_t a;
    asm("{ .reg .u64 t; cvta.to.shared.u64 t, %1; cvt.u32.u64 %0, t; }" : "=r"(a) : "l"(p));
    return a;
}
__device__ __forceinline__ void cpa16s(uint32_t s, const void* g) {
    asm volatile("cp.async.cg.shared.global [%0], [%1], 16;" :: "r"(s), "l"(g));
}
__device__ __forceinline__ void cpa16(void* s, const void* g) { cpa16s(smem_u32(s), g); }
#define CPA_COMMIT asm volatile("cp.async.commit_group;")
#define CPA_WAIT0  asm volatile("cp.async.wait_group 0;")
#define CPA_WAIT1  asm volatile("cp.async.wait_group 1;")

#define LDM4(r, addr) \
    asm volatile("ldmatrix.sync.aligned.m8n8.x4.shared.b16 {%0,%1,%2,%3}, [%4];" \
        : "=r"((r)[0]), "=r"((r)[1]), "=r"((r)[2]), "=r"((r)[3]) : "r"(addr))

#define MMAH(d, a, b0, b1) \
    asm volatile("mma.sync.aligned.m16n8k16.row.col.f32.f16.f16.f32 " \
        "{%0,%1,%2,%3}, {%4,%5,%6,%7}, {%8,%9}, {%0,%1,%2,%3};" \
        : "+f"((d)[0]), "+f"((d)[1]), "+f"((d)[2]), "+f"((d)[3]) \
        : "r"((a)[0]), "r"((a)[1]), "r"((a)[2]), "r"((a)[3]), "r"(b0), "r"(b1))

// packed fp32x2 (Blackwell base ISA, sm_100+)
#define FMA2(d, a, b, c) asm("fma.rn.f32x2 %0, %1, %2, %3;" : "=l"(d) : "l"(a), "l"(b), "l"(c))
#define MUL2(d, a, b)    asm("mul.rn.f32x2 %0, %1, %2;" : "=l"(d) : "l"(a), "l"(b))
#define ADD2(d, a, b)    asm("add.rn.f32x2 %0, %1, %2;" : "=l"(d) : "l"(a), "l"(b))
#define PACKF2(d, lo, hi) asm("mov.b64 %0, {%1, %2};" : "=l"(d) : "f"(lo), "f"(hi))
#define UNPACKF2(lo, hi, s) asm("mov.b64 {%0, %1}, %2;" : "=f"(lo), "=f"(hi) : "l"(s))
#define LDSV2U64(a, b, addr) \
    asm volatile("ld.shared.v2.b64 {%0, %1}, [%2];" : "=l"(a), "=l"(b) : "r"(addr))

// ---------------- seg ids + flags ----------------
__global__ void k_prep(const int* __restrict__ cu) {
    int t = blockIdx.x * 256 + threadIdx.x;
    if (t >= TT) return;
    int seg = 0;
#pragma unroll
    for (int s = 1; s <= NSEG; ++s) if (t >= cu[s]) seg = s;
    d_seg[t] = seg;
    int fl = (t == cu[seg]) ? 1 : 0;
#pragma unroll
    for (int s = 0; s < NSEG; ++s) if (t == cu[s + 1] - 1) fl |= ((s + 1) << 1);
    d_flags[t] = fl;
}

// ---------------- embed + rmsnorm + fp16 conversion ----------------
__global__ void k_embed(const float* __restrict__ x, const int* __restrict__ acidx,
                        const float* __restrict__ actab, const float* __restrict__ Win,
                        const float* __restrict__ bin, const float* __restrict__ nw) {
    __shared__ float sx[8][48];
    __shared__ float sps[8][256];
    __shared__ float srms[8];
    int t0 = blockIdx.x * 8;
    int tid = threadIdx.x;
    for (int idx = tid; idx < 8 * 48; idx += 256) {
        int r = idx / 48, i = idx % 48;
        int t = t0 + r;
        float v;
        if (i < DIN) v = x[t * DIN + i];
        else v = actab[acidx[d_seg[t]] * ACD + (i - DIN)];
        sx[r][i] = v;
    }
    __syncthreads();

    float hreg[4][8];
    float ps[8];
#pragma unroll
    for (int r = 0; r < 8; ++r) ps[r] = 0.f;

#pragma unroll
    for (int jj = 0; jj < 4; ++jj) {
        int j = tid + jj * 256;
        float acc[8];
        float bb = bin[j];
#pragma unroll
        for (int r = 0; r < 8; ++r) acc[r] = bb;
        for (int i = 0; i < 48; ++i) {
            float w = Win[i * HH + j];
#pragma unroll
            for (int r = 0; r < 8; ++r) acc[r] = fmaf(sx[r][i], w, acc[r]);
        }
#pragma unroll
        for (int r = 0; r < 8; ++r) { hreg[jj][r] = acc[r]; ps[r] = fmaf(acc[r], acc[r], ps[r]); }
    }
#pragma unroll
    for (int r = 0; r < 8; ++r) sps[r][tid] = ps[r];
    __syncthreads();
    int w = tid >> 5, lane = tid & 31;
    float s = sps[w][lane];
#pragma unroll
    for (int i = 1; i < 8; ++i) s += sps[w][lane + 32 * i];
#pragma unroll
    for (int off = 16; off; off >>= 1) s += __shfl_xor_sync(0xffffffffu, s, off);
    if (lane == 0) srms[w] = rsqrtf(s / (float)HH + 1e-6f);
    __syncthreads();

    int needr[8];
#pragma unroll
    for (int r = 0; r < 8; ++r) needr[r] = d_flags[t0 + r] >> 1;

#pragma unroll
    for (int jj = 0; jj < 4; ++jj) {
        int j = tid + jj * 256;
        float nwj = 1.0f + nw[j];
#pragma unroll
        for (int r = 0; r < 8; ++r) {
            int t = t0 + r;
            float val = hreg[jj][r] * srms[r] * nwj;
            d_hn[t * HH + j] = val;
            d_hnf[(size_t)t * HH + j] = __float2half(val);
            if (needr[r]) d_hrows[(needr[r] - 1) * HH + j] = hreg[jj][r];
        }
    }
}

// ---------------- weight transpose + fp16 ----------------
__global__ void k_wcvt(const float* __restrict__ W, __half* __restrict__ outw, int N) {
    __shared__ float tile[32][33];
    int n0 = blockIdx.x * 32, k0 = blockIdx.y * 32;
    int tx = threadIdx.x, ty = threadIdx.y;
    for (int i = ty; i < 32; i += 8)
        tile[i][tx] = W[(size_t)(k0 + i) * N + n0 + tx];
    __syncthreads();
    for (int i = ty; i < 32; i += 8)
        outw[(size_t)(n0 + i) * HH + k0 + tx] = __float2half(tile[tx][i]);
}

// ---------------- Wa/Wb transpose: d_wt[c][k] ----------------
__global__ void k_wt(const float* __restrict__ Wa, const float* __restrict__ Wb) {
    int c = blockIdx.x;          // 0..23
    int tid = threadIdx.x;       // 256
    const float* src = (c < NHH) ? Wa : Wb;
    int cc = (c < NHH) ? c : c - NHH;
    for (int k = tid; k < HH; k += 256)
        d_wt[c * HH + k] = src[(size_t)k * NHH + cc];
}

// ---------------- fp16 mma.sync GEMM (exact R8 version) ----------------
#define MM_ROW   40
#define MM_ATEN  (128 * MM_ROW)
#define MM_BTEN  (128 * MM_ROW)
#define MM_STG   (MM_ATEN + MM_BTEN)
#define MM_NSTG  3
#define MM_SMEM  (MM_NSTG * MM_STG * 2)
#define MM_NCH   (HH / 32)

__global__ void __launch_bounds__(256, 2)
k_mma(const __half* __restrict__ A_, const __half* __restrict__ B_,
      float* __restrict__ C, int N) {
    extern __shared__ __align__(128) __half sm[];
    uint32_t sb = smem_u32(sm);
    int tid = threadIdx.x, lane = tid & 31, wid = tid >> 5;
    int wm = wid & 1, wn = wid >> 1;
    int ntile = blockIdx.x, mtile = blockIdx.y;

    const __half* Af = A_ + (size_t)(mtile * 128) * HH;
    const __half* Bf = B_ + (size_t)(ntile * 128) * HH;

    float acc[4][4][4];
#pragma unroll
    for (int m = 0; m < 4; ++m)
#pragma unroll
        for (int n = 0; n < 4; ++n)
#pragma unroll
            for (int i = 0; i < 4; ++i) acc[m][n][i] = 0.f;

    int ab[4];
#pragma unroll
    for (int m = 0; m < 4; ++m)
        ab[m] = (wm * 64 + m * 16 + (lane & 15)) * MM_ROW + (lane >> 4) * 8;
    int bb[2];
#pragma unroll
    for (int p = 0; p < 2; ++p)
        bb[p] = (wn * 32 + p * 16 + (lane & 7) + ((lane >> 4) & 1) * 8) * MM_ROW + ((lane >> 3) & 1) * 8;

    auto load_stage = [&](int stg, int k0) {
        uint32_t base = sb + 2 * (stg * MM_STG);
#pragma unroll
        for (int it = 0; it < 2; ++it) {
            int idx = tid + it * 256;
            int r = idx >> 2, cc = idx & 3;
            cpa16s(base + 2 * (r * MM_ROW + cc * 8), Af + (size_t)r * HH + k0 + cc * 8);
        }
#pragma unroll
        for (int it = 0; it < 2; ++it) {
            int idx = tid + it * 256;
            int r = idx >> 2, cc = idx & 3;
            cpa16s(base + 2 * (MM_ATEN + r * MM_ROW + cc * 8), Bf + (size_t)r * HH + k0 + cc * 8);
        }
    };

    load_stage(0, 0);
    CPA_COMMIT;
    load_stage(1, 32);
    CPA_COMMIT;

    for (int c = 0; c < MM_NCH; ++c) {
        int stg = c % MM_NSTG;
        if (c + 1 < MM_NCH) { CPA_WAIT1; } else { CPA_WAIT0; }
        __syncthreads();
        if (c + 2 < MM_NCH) {
            load_stage((c + 2) % MM_NSTG, (c + 2) * 32);
            CPA_COMMIT;
        }

        uint32_t base = sb + 2 * (stg * MM_STG);
#pragma unroll
        for (int ks = 0; ks < 2; ++ks) {
            uint32_t a4[4][4];
#pragma unroll
            for (int m = 0; m < 4; ++m) LDM4(a4[m], base + 2 * (ab[m] + ks * 16));
#pragma unroll
            for (int p = 0; p < 2; ++p) {
                uint32_t rb[4];
                LDM4(rb, base + 2 * (MM_ATEN + bb[p] + ks * 16));
#pragma unroll
                for (int m = 0; m < 4; ++m) {
                    MMAH(acc[m][2 * p],     a4[m], rb[0], rb[1]);
                    MMAH(acc[m][2 * p + 1], a4[m], rb[2], rb[3]);
                }
            }
        }
        __syncthreads();
    }

#pragma unroll
    for (int m = 0; m < 4; ++m) {
        int row = mtile * 128 + wm * 64 + m * 16 + (lane >> 2);
#pragma unroll
        for (int n = 0; n < 4; ++n) {
            int col = ntile * 128 + wn * 32 + n * 8 + (lane & 3) * 2;
            float2 v0 = make_float2(acc[m][n][0], acc[m][n][1]);
            float2 v1 = make_float2(acc[m][n][2], acc[m][n][3]);
            *(float2*)&C[(size_t)row * N + col] = v0;
            *(float2*)&C[(size_t)(row + 8) * N + col] = v1;
        }
    }
}

// ---------------- hn@[Wa|Wb] with coalesced transposed weights ----------------
__global__ void k_ab2(const float* __restrict__ Alog, const float* __restrict__ dtb) {
    int row = blockIdx.x * 8 + (threadIdx.x >> 5);
    int lane = threadIdx.x & 31;
    float4 hv[8];
    const float4* hp = (const float4*)(d_hn + (size_t)row * HH);
#pragma unroll
    for (int i = 0; i < 8; ++i) hv[i] = hp[lane + 32 * i];

    float res[24];
#pragma unroll
    for (int c = 0; c < 24; ++c) {
        const float4* wp = (const float4*)(d_wt + c * HH);
        float a0 = 0.f, a1 = 0.f, a2 = 0.f, a3 = 0.f;
#pragma unroll
        for (int i = 0; i < 8; ++i) {
            float4 w = wp[lane + 32 * i];
            a0 = fmaf(hv[i].x, w.x, a0);
            a1 = fmaf(hv[i].y, w.y, a1);
            a2 = fmaf(hv[i].z, w.z, a2);
            a3 = fmaf(hv[i].w, w.w, a3);
        }
        res[c] = (a0 + a1) + (a2 + a3);
    }
#pragma unroll
    for (int c = 0; c < 24; ++c) {
#pragma unroll
        for (int off = 16; off; off >>= 1)
            res[c] += __shfl_xor_sync(0xffffffffu, res[c], off);
    }
    if (lane < NHH) {
        float xx = res[lane] + dtb[lane];
        float sp = (xx > 20.f) ? xx : log1pf(expf(xx));
        float g = -expf(Alog[lane]) * sp;
        int fl = d_flags[row];
        float4 o;
        o.x = (fl & 1) ? 0.f : expf(g);
        o.y = sigmoidf_(res[12 + lane]);
        o.z = (float)(fl >> 1);
        o.w = 0.f;
        d_scd[(size_t)row * NHH + lane] = o;
    }
}

// ---------------- k-path conv + silu + l2norm, float4, 8 timesteps ----------------
#define KTCH 8
__global__ void __launch_bounds__(192) k_convk(const float* __restrict__ cw) {
    int tid = threadIdx.x;
    int c = tid * 4;
    int t0 = blockIdx.x * KTCH;
    float4 w0, w1, w2, w3;
    {
        const float4* cwp = (const float4*)(cw + c * 4);
        float4 a = cwp[0], b = cwp[1], cc2 = cwp[2], d = cwp[3];
        w0 = make_float4(a.x, b.x, cc2.x, d.x);
        w1 = make_float4(a.y, b.y, cc2.y, d.y);
        w2 = make_float4(a.z, b.z, cc2.z, d.z);
        w3 = make_float4(a.w, b.w, cc2.w, d.w);
    }
    float4 xm1 = {0,0,0,0}, xm2 = {0,0,0,0}, xm3 = {0,0,0,0};
    int st1 = 1, st2 = 1;
    if (t0 >= 1) { xm1 = *(const float4*)&d_kpre[(size_t)(t0 - 1) * KDIM + c]; st1 = d_flags[t0 - 1] & 1; }
    if (t0 >= 2) { xm2 = *(const float4*)&d_kpre[(size_t)(t0 - 2) * KDIM + c]; st2 = d_flags[t0 - 2] & 1; }
    if (t0 >= 3) { xm3 = *(const float4*)&d_kpre[(size_t)(t0 - 3) * KDIM + c]; }

    float4 val[KTCH];
    float ssq[KTCH];
#pragma unroll
    for (int tt = 0; tt < KTCH; ++tt) {
        int t = t0 + tt;
        float4 xt = *(const float4*)&d_kpre[(size_t)t * KDIM + c];
        int st = d_flags[t] & 1;
        float4 a;
        a.x = xt.x * w3.x; a.y = xt.y * w3.y; a.z = xt.z * w3.z; a.w = xt.w * w3.w;
        if (!st) {
            a.x = fmaf(xm1.x, w2.x, a.x); a.y = fmaf(xm1.y, w2.y, a.y);
            a.z = fmaf(xm1.z, w2.z, a.z); a.w = fmaf(xm1.w, w2.w, a.w);
            if (!st1) {
                a.x = fmaf(xm2.x, w1.x, a.x); a.y = fmaf(xm2.y, w1.y, a.y);
                a.z = fmaf(xm2.z, w1.z, a.z); a.w = fmaf(xm2.w, w1.w, a.w);
                if (!st2) {
                    a.x = fmaf(xm3.x, w0.x, a.x); a.y = fmaf(xm3.y, w0.y, a.y);
                    a.z = fmaf(xm3.z, w0.z, a.z); a.w = fmaf(xm3.w, w0.w, a.w);
                }
            }
        }
        float4 v;
        v.x = a.x * sigmoidf_(a.x); v.y = a.y * sigmoidf_(a.y);
        v.z = a.z * sigmoidf_(a.z); v.w = a.w * sigmoidf_(a.w);
        val[tt] = v;
        ssq[tt] = fmaf(v.x, v.x, fmaf(v.y, v.y, fmaf(v.z, v.z, v.w * v.w)));
        xm3 = xm2; xm2 = xm1; xm1 = xt;
        st2 = st1; st1 = st;
    }
#pragma unroll
    for (int tt = 0; tt < KTCH; ++tt) {
        float s = ssq[tt];
        s += __shfl_xor_sync(0xffffffffu, s, 1);
        s += __shfl_xor_sync(0xffffffffu, s, 2);
        s += __shfl_xor_sync(0xffffffffu, s, 4);
        s += __shfl_xor_sync(0xffffffffu, s, 8);
        float r = rsqrtf(s + 1e-6f);
        float4 v = val[tt];
        v.x *= r; v.y *= r; v.z *= r; v.w *= r;
        *(float4*)&d_k[(size_t)(t0 + tt) * KDIM + c] = v;
    }
}

// ---------------- v-path conv + silu, float4, immediate store ----------------
#define VTCH 16
__global__ void __launch_bounds__(192) k_conv2(const float* __restrict__ cw) {
    int c = (blockIdx.x * 192 + threadIdx.x) * 4;
    int t0 = blockIdx.y * VTCH;
    float4 w0, w1, w2, w3;
    {
        const float4* cwp = (const float4*)(cw + c * 4);
        float4 a = cwp[0], b = cwp[1], cc2 = cwp[2], d = cwp[3];
        w0 = make_float4(a.x, b.x, cc2.x, d.x);
        w1 = make_float4(a.y, b.y, cc2.y, d.y);
        w2 = make_float4(a.z, b.z, cc2.z, d.z);
        w3 = make_float4(a.w, b.w, cc2.w, d.w);
    }
    float4 xm1 = {0,0,0,0}, xm2 = {0,0,0,0}, xm3 = {0,0,0,0};
    int st1 = 1, st2 = 1;
    if (t0 >= 1) { xm1 = *(const float4*)&d_vpre[(size_t)(t0 - 1) * VDIM + c]; st1 = d_flags[t0 - 1] & 1; }
    if (t0 >= 2) { xm2 = *(const float4*)&d_vpre[(size_t)(t0 - 2) * VDIM + c]; st2 = d_flags[t0 - 2] & 1; }
    if (t0 >= 3) { xm3 = *(const float4*)&d_vpre[(size_t)(t0 - 3) * VDIM + c]; }
#pragma unroll 4
    for (int tt = 0; tt < VTCH; ++tt) {
        int t = t0 + tt;
        float4 xt = *(const float4*)&d_vpre[(size_t)t * VDIM + c];
        int st = d_flags[t] & 1;
        float4 a;
        a.x = xt.x * w3.x; a.y = xt.y * w3.y; a.z = xt.z * w3.z; a.w = xt.w * w3.w;
        if (!st) {
            a.x = fmaf(xm1.x, w2.x, a.x); a.y = fmaf(xm1.y, w2.y, a.y);
            a.z = fmaf(xm1.z, w2.z, a.z); a.w = fmaf(xm1.w, w2.w, a.w);
            if (!st1) {
                a.x = fmaf(xm2.x, w1.x, a.x); a.y = fmaf(xm2.y, w1.y, a.y);
                a.z = fmaf(xm2.z, w1.z, a.z); a.w = fmaf(xm2.w, w1.w, a.w);
                if (!st2) {
                    a.x = fmaf(xm3.x, w0.x, a.x); a.y = fmaf(xm3.y, w0.y, a.y);
                    a.z = fmaf(xm3.z, w0.z, a.z); a.w = fmaf(xm3.w, w0.w, a.w);
                }
            }
        }
        float4 v;
        v.x = a.x * sigmoidf_(a.x); v.y = a.y * sigmoidf_(a.y);
        v.z = a.z * sigmoidf_(a.z); v.w = a.w * sigmoidf_(a.w);
        *(float4*)&d_v[(size_t)t * VDIM + c] = v;
        xm3 = xm2; xm2 = xm1; xm1 = xt;
        st2 = st1; st1 = st;
    }
}

// ---------------- q at the 16 pooled positions ----------------
__global__ void k_q16(const int* __restrict__ cu, const float* __restrict__ Wq,
                      const float* __restrict__ cw) {
    __shared__ float shn[4][HH];
    __shared__ float sq[KDIM];
    int s = blockIdx.x;
    int pos = cu[s + 1] - 1;
    int seg = d_seg[pos];
    int tid = threadIdx.x;
    int valid[4];
#pragma unroll
    for (int r = 0; r < 4; ++r) {
        int t = pos - r;
        valid[r] = (t >= 0 && d_seg[t] == seg);
    }
#pragma unroll
    for (int r = 0; r < 4; ++r) {
        int t = pos - r;
        if (valid[r]) for (int i = tid; i < HH; i += 256) shn[r][i] = d_hn[(size_t)t * HH + i];
        else          for (int i = tid; i < HH; i += 256) shn[r][i] = 0.f;
    }
    __syncthreads();
    for (int c = tid; c < KDIM; c += 256) {
        float a0 = 0.f, a1 = 0.f, a2 = 0.f, a3 = 0.f;
        for (int i = 0; i < HH; ++i) {
            float wv = Wq[(size_t)i * KDIM + c];
            a0 = fmaf(shn[0][i], wv, a0);
            a1 = fmaf(shn[1][i], wv, a1);
            a2 = fmaf(shn[2][i], wv, a2);
            a3 = fmaf(shn[3][i], wv, a3);
        }
        float acc = a0 * cw[c * 4 + 3] + a1 * cw[c * 4 + 2] + a2 * cw[c * 4 + 1] + a3 * cw[c * 4 + 0];
        sq[c] = acc * sigmoidf_(acc);
    }
    __syncthreads();
    int w = tid >> 5, lane = tid & 31;
    for (int h = w; h < NHH; h += 8) {
        float ssq = 0.f;
        for (int i = lane; i < HKD; i += 32) { float v = sq[h * HKD + i]; ssq = fmaf(v, v, ssq); }
#pragma unroll
        for (int off = 16; off; off >>= 1) ssq += __shfl_xor_sync(0xffffffffu, ssq, off);
        float r = rsqrtf(ssq + 1e-6f) * 0.125f;
        for (int i = lane; i < HKD; i += 32)
            d_q[s * KDIM + h * HKD + i] = sq[h * HKD + i] * r;
    }
}

// ---------------- segment-parallel scan, packed f32x2 ----------------
__global__ void __launch_bounds__(128) k_scan(const int* __restrict__ cu) {
    __shared__ float  sk[2][SCH][64];
    __shared__ float  svv[2][SCH][64];
    __shared__ float4 scd[2][SCH];

    int half = blockIdx.x;
    int h    = blockIdx.y;
    int s    = blockIdx.z;
    int tid  = threadIdx.x;
    int colL = tid >> 1;
    int e    = tid & 1;
    int col  = half * 64 + colL;

    int start = cu[s];
    int end   = cu[s + 1];
    int len   = end - start;

    auto load_chunk = [&](int buf, int c0) {
        int rem = len - c0; if (rem > SCH) rem = SCH;
        for (int idx = tid; idx < rem * 16; idx += 128) {
            int i = idx >> 4, j = idx & 15;
            cpa16(&sk[buf][i][j * 4], d_k + (size_t)(start + c0 + i) * KDIM + h * HKD + j * 4);
        }
        for (int idx = tid; idx < rem * 16; idx += 128) {
            int i = idx >> 4, j = idx & 15;
            cpa16(&svv[buf][i][j * 4], d_v + (size_t)(start + c0 + i) * VDIM + h * HVD + half * 64 + j * 4);
        }
        if (tid < rem)
            cpa16(&scd[buf][tid], d_scd + (size_t)(start + c0 + tid) * NHH + h);
    };

    uint64_t S2[16];
#pragma unroll
    for (int i = 0; i < 16; ++i) S2[i] = 0ull;

    load_chunk(0, 0);
    CPA_COMMIT;

    int buf = 0;
    for (int c0 = 0; c0 < len; c0 += SCH, buf ^= 1) {
        __syncthreads();
        if (c0 + SCH < len) load_chunk(buf ^ 1, c0 + SCH);
        CPA_COMMIT;
        CPA_WAIT1;
        __syncthreads();

        int rem = len - c0; if (rem > SCH) rem = SCH;

        uint64_t nk[16];
#pragma unroll
        for (int j = 0; j < 8; ++j) {
            uint32_t addr = smem_u32(&sk[buf][0][e * 32 + j * 4]);
            LDSV2U64(nk[2 * j], nk[2 * j + 1], addr);
        }
        float  nv  = svv[buf][0][colL];
        float4 ncd = scd[buf][0];

        for (int i = 0; i < rem; ++i) {
            uint64_t K2[16];
#pragma unroll
            for (int j = 0; j < 16; ++j) K2[j] = nk[j];
            float  vv = nv;
            float4 cd = ncd;
            int ip = (i + 1 < rem) ? i + 1 : i;
#pragma unroll
            for (int j = 0; j < 8; ++j) {
                uint32_t addr = smem_u32(&sk[buf][ip][e * 32 + j * 4]);
                LDSV2U64(nk[2 * j], nk[2 * j + 1], addr);
            }
            nv  = svv[buf][ip][colL];
            ncd = scd[buf][ip];

            uint64_t a0 = 0ull, a1 = 0ull;
#pragma unroll
            for (int j = 0; j < 16; j += 2) {
                FMA2(a0, S2[j],     K2[j],     a0);
                FMA2(a1, S2[j + 1], K2[j + 1], a1);
            }
            ADD2(a0, a0, a1);
            float lo, hi;
            UNPACKF2(lo, hi, a0);
            float dot = lo + hi;
            dot += __shfl_xor_sync(0xffffffffu, dot, 1);

            float lam = cd.x;
            float delta = cd.y * fmaf(-lam, dot, vv);
            uint64_t lam2, d2;
            PACKF2(lam2, lam, lam);
            PACKF2(d2, delta, delta);
#pragma unroll
            for (int j = 0; j < 16; ++j) {
                uint64_t t;
                MUL2(t, K2[j], d2);
                FMA2(S2[j], lam2, S2[j], t);
            }

            if (cd.z != 0.f) {
                int need = (int)cd.z - 1;
                const float4* qp = (const float4*)(d_q + (size_t)need * KDIM + h * HKD + e * 32);
                uint64_t oa = 0ull;
#pragma unroll
                for (int j = 0; j < 8; ++j) {
                    float4 qv = qp[j];
                    uint64_t q0, q1;
                    PACKF2(q0, qv.x, qv.y);
                    PACKF2(q1, qv.z, qv.w);
                    FMA2(oa, S2[2 * j],     q0, oa);
                    FMA2(oa, S2[2 * j + 1], q1, oa);
                }
                float olo, ohi;
                UNPACKF2(olo, ohi, oa);
                float od = olo + ohi;
                od += __shfl_xor_sync(0xffffffffu, od, 1);
                if (e == 0) d_o[need * VDIM + h * HVD + col] = od;
            }
        }
    }
}

// ---------------- Wo @ W_head ----------------
__global__ void k_wowh(const float* __restrict__ Wo, const float* __restrict__ Wh) {
    int j = blockIdx.x * 8 + (threadIdx.x >> 5);
    int lane = threadIdx.x & 31;
    float a = 0.f;
    for (int k = lane; k < HH; k += 32) a = fmaf(Wo[(size_t)j * HH + k], Wh[k], a);
#pragma unroll
    for (int off = 16; off; off >>= 1) a += __shfl_xor_sync(0xffffffffu, a, off);
    if (lane == 0) d_wowh[j] = a;
}

// ---------------- gating at pooled positions ----------------
__global__ void k_gate(const int* __restrict__ cu, const float* __restrict__ Wg,
                       const float* __restrict__ onw) {
    __shared__ float shn[HH];
    __shared__ float sred[128];
    int hd = blockIdx.x;
    int s = blockIdx.y;
    int pos = cu[s + 1] - 1;
    int tid = threadIdx.x;
    for (int i = tid; i < HH; i += 128) shn[i] = d_hn[(size_t)pos * HH + i];
    __syncthreads();
    float gate = 0.f;
    for (int i = 0; i < HH; ++i)
        gate = fmaf(shn[i], Wg[(size_t)i * VDIM + hd * HVD + tid], gate);
    float ov = d_o[s * VDIM + hd * HVD + tid];
    sred[tid] = ov * ov;
    __syncthreads();
    for (int st = 64; st; st >>= 1) {
        if (tid < st) sred[tid] += sred[tid + st];
        __syncthreads();
    }
    float rms = rsqrtf(sred[0] / (float)HVD + 1e-5f);
    float gs = gate * sigmoidf_(gate);
    d_og[s * VDIM + hd * HVD + tid] = ov * rms * onw[tid] * gs;
}

// ---------------- final head ----------------
__global__ void k_final(const float* __restrict__ Wh, const float* __restrict__ bh,
                        float* __restrict__ out) {
    __shared__ float sred[256];
    int s = blockIdx.x;
    int tid = threadIdx.x;
    float a = 0.f;
    for (int j = tid; j < VDIM; j += 256) a = fmaf(d_og[s * VDIM + j], d_wowh[j], a);
    for (int k = tid; k < HH; k += 256) a = fmaf(d_hrows[s * HH + k], Wh[k], a);
    sred[tid] = a;
    __syncthreads();
    for (int st = 128; st; st >>= 1) {
        if (tid < st) sred[tid] += sred[tid + st];
        __syncthreads();
    }
    if (tid == 0) out[s] = sred[0] + bh[0];
}

// ---------------- launch ----------------
extern "C" void kernel_launch(void* const* d_in, const int* in_sizes, int n_in,
                              void* d_out, int out_size) {
    const float* x     = (const float*)d_in[0];
    const int*   cu    = (const int*)d_in[1];
    const int*   acidx = (const int*)d_in[2];
    const float* actab = (const float*)d_in[3];
    const float* Win   = (const float*)d_in[4];
    const float* bin   = (const float*)d_in[5];
    const float* nw    = (const float*)d_in[6];
    const float* Wq    = (const float*)d_in[7];
    const float* Wk    = (const float*)d_in[8];
    const float* Wv    = (const float*)d_in[9];
    const float* cqw   = (const float*)d_in[10];
    const float* ckw   = (const float*)d_in[11];
    const float* cvw   = (const float*)d_in[12];
    const float* Wb    = (const float*)d_in[13];
    const float* Wa    = (const float*)d_in[14];
    const float* Alog  = (const float*)d_in[15];
    const float* dtb   = (const float*)d_in[16];
    const float* Wg    = (const float*)d_in[17];
    const float* onw   = (const float*)d_in[18];
    const float* Wo    = (const float*)d_in[19];
    const float* Wh    = (const float*)d_in[20];
    const float* bh    = (const float*)d_in[21];
    float* out = (float*)d_out;

    cudaFuncSetAttribute(k_mma, cudaFuncAttributeMaxDynamicSharedMemorySize, MM_SMEM);

    __half *wkf, *wvf, *hnf;
    cudaGetSymbolAddress((void**)&wkf, d_wkf);
    cudaGetSymbolAddress((void**)&wvf, d_wvf);
    cudaGetSymbolAddress((void**)&hnf, d_hnf);
    float *kpre, *vpre;
    cudaGetSymbolAddress((void**)&kpre, d_kpre);
    cudaGetSymbolAddress((void**)&vpre, d_vpre);

    k_prep<<<TT / 256, 256>>>(cu);
    k_embed<<<TT / 8, 256>>>(x, acidx, actab, Win, bin, nw);

    k_wcvt<<<dim3(VDIM / 32, HH / 32), dim3(32, 8)>>>(Wv, wvf, VDIM);
    k_mma<<<dim3(VDIM / 128, TT / 128), 256, MM_SMEM>>>(hnf, wvf, vpre, VDIM);
    k_wcvt<<<dim3(KDIM / 32, HH / 32), dim3(32, 8)>>>(Wk, wkf, KDIM);
    k_mma<<<dim3(KDIM / 128, TT / 128), 256, MM_SMEM>>>(hnf, wkf, kpre, KDIM);

    k_wt<<<24, 256>>>(Wa, Wb);
    k_ab2<<<TT / 8, 256>>>(Alog, dtb);
    k_convk<<<TT / KTCH, 192>>>(ckw);
    k_conv2<<<dim3(VDIM / (192 * 4), TT / VTCH), 192>>>(cvw);
    k_q16<<<NSEG, 256>>>(cu, Wq, cqw);

    k_scan<<<dim3(2, NHH, NSEG), 128>>>(cu);

    k_wowh<<<VDIM / 8, 256>>>(Wo, Wh);
    k_gate<<<dim3(NHH, NSEG), 128>>>(cu, Wg, onw);
    k_final<<<NSEG, 256>>>(Wh, bh, out);
}

// round 12
// speedup vs baseline: 1.5558x; 1.0679x over previous
#include <cuda_runtime.h>
#include <cuda_fp16.h>
#include <math.h>
#include <stdint.h>

#define TT   32768
#define HH   1024
#define DIN  16
#define ACD  32
#define NHH  12
#define KDIM 768
#define VDIM 1536
#define HKD  64
#define HVD  128
#define NSEG 16
#define SCH  40

// ---------------- scratch ----------------
static __device__ float  d_hn   [TT * HH];
static __device__ __half d_hnf  [TT * HH];
static __device__ __half d_wkf  [KDIM * HH];
static __device__ __half d_wvf  [VDIM * HH];
static __device__ float  d_kpre [TT * KDIM];
static __device__ float  d_vpre [TT * VDIM];
static __device__ float  d_k    [TT * KDIM];
static __device__ float  d_v    [TT * VDIM];
static __device__ float4 d_scd  [TT * NHH];     // (lam, beta, needf, 0)
static __device__ float  d_wt   [24 * HH];      // [Wa^T | Wb^T]
static __device__ int    d_seg  [TT];
static __device__ int    d_flags[TT];
static __device__ float  d_hrows[NSEG * HH];
static __device__ float  d_q    [NSEG * KDIM];
static __device__ float  d_o    [NSEG * VDIM];
static __device__ float  d_og   [NSEG * VDIM];  // silu-gated gate values
static __device__ float  d_wowh [VDIM];

__device__ __forceinline__ float sigmoidf_(float x) { return 1.f / (1.f + expf(-x)); }

// ---------------- PTX helpers (base sm_103 features only) ----------------
__device__ __forceinline__ uint32_t smem_u32(const void* p) {
    uint32_t a;
    asm("{ .reg .u64 t; cvta.to.shared.u64 t, %1; cvt.u32.u64 %0, t; }" : "=r"(a) : "l"(p));
    return a;
}
__device__ __forceinline__ void cpa16s(uint32_t s, const void* g) {
    asm volatile("cp.async.cg.shared.global [%0], [%1], 16;" :: "r"(s), "l"(g));
}
__device__ __forceinline__ void cpa16(void* s, const void* g) { cpa16s(smem_u32(s), g); }
#define CPA_COMMIT asm volatile("cp.async.commit_group;")
#define CPA_WAIT0  asm volatile("cp.async.wait_group 0;")
#define CPA_WAIT1  asm volatile("cp.async.wait_group 1;")

#define LDM4(r, addr) \
    asm volatile("ldmatrix.sync.aligned.m8n8.x4.shared.b16 {%0,%1,%2,%3}, [%4];" \
        : "=r"((r)[0]), "=r"((r)[1]), "=r"((r)[2]), "=r"((r)[3]) : "r"(addr))

#define MMAH(d, a, b0, b1) \
    asm volatile("mma.sync.aligned.m16n8k16.row.col.f32.f16.f16.f32 " \
        "{%0,%1,%2,%3}, {%4,%5,%6,%7}, {%8,%9}, {%0,%1,%2,%3};" \
        : "+f"((d)[0]), "+f"((d)[1]), "+f"((d)[2]), "+f"((d)[3]) \
        : "r"((a)[0]), "r"((a)[1]), "r"((a)[2]), "r"((a)[3]), "r"(b0), "r"(b1))

// packed fp32x2 (Blackwell base ISA, sm_100+)
#define FMA2(d, a, b, c) asm("fma.rn.f32x2 %0, %1, %2, %3;" : "=l"(d) : "l"(a), "l"(b), "l"(c))
#define MUL2(d, a, b)    asm("mul.rn.f32x2 %0, %1, %2;" : "=l"(d) : "l"(a), "l"(b))
#define ADD2(d, a, b)    asm("add.rn.f32x2 %0, %1, %2;" : "=l"(d) : "l"(a), "l"(b))
#define PACKF2(d, lo, hi) asm("mov.b64 %0, {%1, %2};" : "=l"(d) : "f"(lo), "f"(hi))
#define UNPACKF2(lo, hi, s) asm("mov.b64 {%0, %1}, %2;" : "=f"(lo), "=f"(hi) : "l"(s))
#define LDSV2U64(a, b, addr) \
    asm volatile("ld.shared.v2.b64 {%0, %1}, [%2];" : "=l"(a), "=l"(b) : "r"(addr))

// ---------------- seg ids + flags ----------------
__global__ void k_prep(const int* __restrict__ cu) {
    int t = blockIdx.x * 256 + threadIdx.x;
    if (t >= TT) return;
    int seg = 0;
#pragma unroll
    for (int s = 1; s <= NSEG; ++s) if (t >= cu[s]) seg = s;
    d_seg[t] = seg;
    int fl = (t == cu[seg]) ? 1 : 0;
#pragma unroll
    for (int s = 0; s < NSEG; ++s) if (t == cu[s + 1] - 1) fl |= ((s + 1) << 1);
    d_flags[t] = fl;
}

// ---------------- embed + rmsnorm + fp16 conversion ----------------
__global__ void k_embed(const float* __restrict__ x, const int* __restrict__ acidx,
                        const float* __restrict__ actab, const float* __restrict__ Win,
                        const float* __restrict__ bin, const float* __restrict__ nw) {
    __shared__ float sx[8][48];
    __shared__ float sps[8][256];
    __shared__ float srms[8];
    int t0 = blockIdx.x * 8;
    int tid = threadIdx.x;
    for (int idx = tid; idx < 8 * 48; idx += 256) {
        int r = idx / 48, i = idx % 48;
        int t = t0 + r;
        float v;
        if (i < DIN) v = x[t * DIN + i];
        else v = actab[acidx[d_seg[t]] * ACD + (i - DIN)];
        sx[r][i] = v;
    }
    __syncthreads();

    float hreg[4][8];
    float ps[8];
#pragma unroll
    for (int r = 0; r < 8; ++r) ps[r] = 0.f;

#pragma unroll
    for (int jj = 0; jj < 4; ++jj) {
        int j = tid + jj * 256;
        float acc[8];
        float bb = bin[j];
#pragma unroll
        for (int r = 0; r < 8; ++r) acc[r] = bb;
        for (int i = 0; i < 48; ++i) {
            float w = Win[i * HH + j];
#pragma unroll
            for (int r = 0; r < 8; ++r) acc[r] = fmaf(sx[r][i], w, acc[r]);
        }
#pragma unroll
        for (int r = 0; r < 8; ++r) { hreg[jj][r] = acc[r]; ps[r] = fmaf(acc[r], acc[r], ps[r]); }
    }
#pragma unroll
    for (int r = 0; r < 8; ++r) sps[r][tid] = ps[r];
    __syncthreads();
    int w = tid >> 5, lane = tid & 31;
    float s = sps[w][lane];
#pragma unroll
    for (int i = 1; i < 8; ++i) s += sps[w][lane + 32 * i];
#pragma unroll
    for (int off = 16; off; off >>= 1) s += __shfl_xor_sync(0xffffffffu, s, off);
    if (lane == 0) srms[w] = rsqrtf(s / (float)HH + 1e-6f);
    __syncthreads();

    int needr[8];
#pragma unroll
    for (int r = 0; r < 8; ++r) needr[r] = d_flags[t0 + r] >> 1;

#pragma unroll
    for (int jj = 0; jj < 4; ++jj) {
        int j = tid + jj * 256;
        float nwj = 1.0f + nw[j];
#pragma unroll
        for (int r = 0; r < 8; ++r) {
            int t = t0 + r;
            float val = hreg[jj][r] * srms[r] * nwj;
            d_hn[t * HH + j] = val;
            d_hnf[(size_t)t * HH + j] = __float2half(val);
            if (needr[r]) d_hrows[(needr[r] - 1) * HH + j] = hreg[jj][r];
        }
    }
}

// ---------------- weight transpose + fp16 ----------------
__global__ void k_wcvt(const float* __restrict__ W, __half* __restrict__ outw, int N) {
    __shared__ float tile[32][33];
    int n0 = blockIdx.x * 32, k0 = blockIdx.y * 32;
    int tx = threadIdx.x, ty = threadIdx.y;
    for (int i = ty; i < 32; i += 8)
        tile[i][tx] = W[(size_t)(k0 + i) * N + n0 + tx];
    __syncthreads();
    for (int i = ty; i < 32; i += 8)
        outw[(size_t)(n0 + i) * HH + k0 + tx] = __float2half(tile[tx][i]);
}

// ---------------- Wa/Wb transpose ----------------
__global__ void k_wt(const float* __restrict__ Wa, const float* __restrict__ Wb) {
    int c = blockIdx.x;
    int tid = threadIdx.x;
    const float* src = (c < NHH) ? Wa : Wb;
    int cc = (c < NHH) ? c : c - NHH;
    for (int k = tid; k < HH; k += 256)
        d_wt[c * HH + k] = src[(size_t)k * NHH + cc];
}

// ---------------- fp16 mma.sync GEMM ----------------
#define MM_ROW   40
#define MM_ATEN  (128 * MM_ROW)
#define MM_BTEN  (128 * MM_ROW)
#define MM_STG   (MM_ATEN + MM_BTEN)
#define MM_NSTG  3
#define MM_SMEM  (MM_NSTG * MM_STG * 2)
#define MM_NCH   (HH / 32)

__global__ void __launch_bounds__(256, 2)
k_mma(const __half* __restrict__ A_, const __half* __restrict__ B_,
      float* __restrict__ C, int N) {
    extern __shared__ __align__(128) __half sm[];
    uint32_t sb = smem_u32(sm);
    int tid = threadIdx.x, lane = tid & 31, wid = tid >> 5;
    int wm = wid & 1, wn = wid >> 1;
    int ntile = blockIdx.x, mtile = blockIdx.y;

    const __half* Af = A_ + (size_t)(mtile * 128) * HH;
    const __half* Bf = B_ + (size_t)(ntile * 128) * HH;

    float acc[4][4][4];
#pragma unroll
    for (int m = 0; m < 4; ++m)
#pragma unroll
        for (int n = 0; n < 4; ++n)
#pragma unroll
            for (int i = 0; i < 4; ++i) acc[m][n][i] = 0.f;

    int ab[4];
#pragma unroll
    for (int m = 0; m < 4; ++m)
        ab[m] = (wm * 64 + m * 16 + (lane & 15)) * MM_ROW + (lane >> 4) * 8;
    int bb[2];
#pragma unroll
    for (int p = 0; p < 2; ++p)
        bb[p] = (wn * 32 + p * 16 + (lane & 7) + ((lane >> 4) & 1) * 8) * MM_ROW + ((lane >> 3) & 1) * 8;

    auto load_stage = [&](int stg, int k0) {
        uint32_t base = sb + 2 * (stg * MM_STG);
#pragma unroll
        for (int it = 0; it < 2; ++it) {
            int idx = tid + it * 256;
            int r = idx >> 2, cc = idx & 3;
            cpa16s(base + 2 * (r * MM_ROW + cc * 8), Af + (size_t)r * HH + k0 + cc * 8);
        }
#pragma unroll
        for (int it = 0; it < 2; ++it) {
            int idx = tid + it * 256;
            int r = idx >> 2, cc = idx & 3;
            cpa16s(base + 2 * (MM_ATEN + r * MM_ROW + cc * 8), Bf + (size_t)r * HH + k0 + cc * 8);
        }
    };

    load_stage(0, 0);
    CPA_COMMIT;
    load_stage(1, 32);
    CPA_COMMIT;

    for (int c = 0; c < MM_NCH; ++c) {
        int stg = c % MM_NSTG;
        if (c + 1 < MM_NCH) { CPA_WAIT1; } else { CPA_WAIT0; }
        __syncthreads();
        if (c + 2 < MM_NCH) {
            load_stage((c + 2) % MM_NSTG, (c + 2) * 32);
            CPA_COMMIT;
        }

        uint32_t base = sb + 2 * (stg * MM_STG);
#pragma unroll
        for (int ks = 0; ks < 2; ++ks) {
            uint32_t a4[4][4];
#pragma unroll
            for (int m = 0; m < 4; ++m) LDM4(a4[m], base + 2 * (ab[m] + ks * 16));
#pragma unroll
            for (int p = 0; p < 2; ++p) {
                uint32_t rb[4];
                LDM4(rb, base + 2 * (MM_ATEN + bb[p] + ks * 16));
#pragma unroll
                for (int m = 0; m < 4; ++m) {
                    MMAH(acc[m][2 * p],     a4[m], rb[0], rb[1]);
                    MMAH(acc[m][2 * p + 1], a4[m], rb[2], rb[3]);
                }
            }
        }
        __syncthreads();
    }

#pragma unroll
    for (int m = 0; m < 4; ++m) {
        int row = mtile * 128 + wm * 64 + m * 16 + (lane >> 2);
#pragma unroll
        for (int n = 0; n < 4; ++n) {
            int col = ntile * 128 + wn * 32 + n * 8 + (lane & 3) * 2;
            float2 v0 = make_float2(acc[m][n][0], acc[m][n][1]);
            float2 v1 = make_float2(acc[m][n][2], acc[m][n][3]);
            *(float2*)&C[(size_t)row * N + col] = v0;
            *(float2*)&C[(size_t)(row + 8) * N + col] = v1;
        }
    }
}

// ---------------- hn@[Wa|Wb] with coalesced transposed weights ----------------
__global__ void k_ab2(const float* __restrict__ Alog, const float* __restrict__ dtb) {
    int row = blockIdx.x * 8 + (threadIdx.x >> 5);
    int lane = threadIdx.x & 31;
    float4 hv[8];
    const float4* hp = (const float4*)(d_hn + (size_t)row * HH);
#pragma unroll
    for (int i = 0; i < 8; ++i) hv[i] = hp[lane + 32 * i];

    float res[24];
#pragma unroll
    for (int c = 0; c < 24; ++c) {
        const float4* wp = (const float4*)(d_wt + c * HH);
        float a0 = 0.f, a1 = 0.f, a2 = 0.f, a3 = 0.f;
#pragma unroll
        for (int i = 0; i < 8; ++i) {
            float4 w = wp[lane + 32 * i];
            a0 = fmaf(hv[i].x, w.x, a0);
            a1 = fmaf(hv[i].y, w.y, a1);
            a2 = fmaf(hv[i].z, w.z, a2);
            a3 = fmaf(hv[i].w, w.w, a3);
        }
        res[c] = (a0 + a1) + (a2 + a3);
    }
#pragma unroll
    for (int c = 0; c < 24; ++c) {
#pragma unroll
        for (int off = 16; off; off >>= 1)
            res[c] += __shfl_xor_sync(0xffffffffu, res[c], off);
    }
    if (lane < NHH) {
        float xx = res[lane] + dtb[lane];
        float sp = (xx > 20.f) ? xx : log1pf(expf(xx));
        float g = -expf(Alog[lane]) * sp;
        int fl = d_flags[row];
        float4 o;
        o.x = (fl & 1) ? 0.f : expf(g);
        o.y = sigmoidf_(res[12 + lane]);
        o.z = (float)(fl >> 1);
        o.w = 0.f;
        d_scd[(size_t)row * NHH + lane] = o;
    }
}

// ---------------- k-path conv + silu + l2norm, float4, 8 timesteps ----------------
#define KTCH 8
__global__ void __launch_bounds__(192) k_convk(const float* __restrict__ cw) {
    int tid = threadIdx.x;
    int c = tid * 4;
    int t0 = blockIdx.x * KTCH;
    float4 w0, w1, w2, w3;
    {
        const float4* cwp = (const float4*)(cw + c * 4);
        float4 a = cwp[0], b = cwp[1], cc2 = cwp[2], d = cwp[3];
        w0 = make_float4(a.x, b.x, cc2.x, d.x);
        w1 = make_float4(a.y, b.y, cc2.y, d.y);
        w2 = make_float4(a.z, b.z, cc2.z, d.z);
        w3 = make_float4(a.w, b.w, cc2.w, d.w);
    }
    float4 xm1 = {0,0,0,0}, xm2 = {0,0,0,0}, xm3 = {0,0,0,0};
    int st1 = 1, st2 = 1;
    if (t0 >= 1) { xm1 = *(const float4*)&d_kpre[(size_t)(t0 - 1) * KDIM + c]; st1 = d_flags[t0 - 1] & 1; }
    if (t0 >= 2) { xm2 = *(const float4*)&d_kpre[(size_t)(t0 - 2) * KDIM + c]; st2 = d_flags[t0 - 2] & 1; }
    if (t0 >= 3) { xm3 = *(const float4*)&d_kpre[(size_t)(t0 - 3) * KDIM + c]; }

    float4 val[KTCH];
    float ssq[KTCH];
#pragma unroll
    for (int tt = 0; tt < KTCH; ++tt) {
        int t = t0 + tt;
        float4 xt = *(const float4*)&d_kpre[(size_t)t * KDIM + c];
        int st = d_flags[t] & 1;
        float4 a;
        a.x = xt.x * w3.x; a.y = xt.y * w3.y; a.z = xt.z * w3.z; a.w = xt.w * w3.w;
        if (!st) {
            a.x = fmaf(xm1.x, w2.x, a.x); a.y = fmaf(xm1.y, w2.y, a.y);
            a.z = fmaf(xm1.z, w2.z, a.z); a.w = fmaf(xm1.w, w2.w, a.w);
            if (!st1) {
                a.x = fmaf(xm2.x, w1.x, a.x); a.y = fmaf(xm2.y, w1.y, a.y);
                a.z = fmaf(xm2.z, w1.z, a.z); a.w = fmaf(xm2.w, w1.w, a.w);
                if (!st2) {
                    a.x = fmaf(xm3.x, w0.x, a.x); a.y = fmaf(xm3.y, w0.y, a.y);
                    a.z = fmaf(xm3.z, w0.z, a.z); a.w = fmaf(xm3.w, w0.w, a.w);
                }
            }
        }
        float4 v;
        v.x = a.x * sigmoidf_(a.x); v.y = a.y * sigmoidf_(a.y);
        v.z = a.z * sigmoidf_(a.z); v.w = a.w * sigmoidf_(a.w);
        val[tt] = v;
        ssq[tt] = fmaf(v.x, v.x, fmaf(v.y, v.y, fmaf(v.z, v.z, v.w * v.w)));
        xm3 = xm2; xm2 = xm1; xm1 = xt;
        st2 = st1; st1 = st;
    }
#pragma unroll
    for (int tt = 0; tt < KTCH; ++tt) {
        float s = ssq[tt];
        s += __shfl_xor_sync(0xffffffffu, s, 1);
        s += __shfl_xor_sync(0xffffffffu, s, 2);
        s += __shfl_xor_sync(0xffffffffu, s, 4);
        s += __shfl_xor_sync(0xffffffffu, s, 8);
        float r = rsqrtf(s + 1e-6f);
        float4 v = val[tt];
        v.x *= r; v.y *= r; v.z *= r; v.w *= r;
        *(float4*)&d_k[(size_t)(t0 + tt) * KDIM + c] = v;
    }
}

// ---------------- v-path conv + silu, float4, immediate store ----------------
#define VTCH 16
__global__ void __launch_bounds__(192) k_conv2(const float* __restrict__ cw) {
    int c = (blockIdx.x * 192 + threadIdx.x) * 4;
    int t0 = blockIdx.y * VTCH;
    float4 w0, w1, w2, w3;
    {
        const float4* cwp = (const float4*)(cw + c * 4);
        float4 a = cwp[0], b = cwp[1], cc2 = cwp[2], d = cwp[3];
        w0 = make_float4(a.x, b.x, cc2.x, d.x);
        w1 = make_float4(a.y, b.y, cc2.y, d.y);
        w2 = make_float4(a.z, b.z, cc2.z, d.z);
        w3 = make_float4(a.w, b.w, cc2.w, d.w);
    }
    float4 xm1 = {0,0,0,0}, xm2 = {0,0,0,0}, xm3 = {0,0,0,0};
    int st1 = 1, st2 = 1;
    if (t0 >= 1) { xm1 = *(const float4*)&d_vpre[(size_t)(t0 - 1) * VDIM + c]; st1 = d_flags[t0 - 1] & 1; }
    if (t0 >= 2) { xm2 = *(const float4*)&d_vpre[(size_t)(t0 - 2) * VDIM + c]; st2 = d_flags[t0 - 2] & 1; }
    if (t0 >= 3) { xm3 = *(const float4*)&d_vpre[(size_t)(t0 - 3) * VDIM + c]; }
#pragma unroll 4
    for (int tt = 0; tt < VTCH; ++tt) {
        int t = t0 + tt;
        float4 xt = *(const float4*)&d_vpre[(size_t)t * VDIM + c];
        int st = d_flags[t] & 1;
        float4 a;
        a.x = xt.x * w3.x; a.y = xt.y * w3.y; a.z = xt.z * w3.z; a.w = xt.w * w3.w;
        if (!st) {
            a.x = fmaf(xm1.x, w2.x, a.x); a.y = fmaf(xm1.y, w2.y, a.y);
            a.z = fmaf(xm1.z, w2.z, a.z); a.w = fmaf(xm1.w, w2.w, a.w);
            if (!st1) {
                a.x = fmaf(xm2.x, w1.x, a.x); a.y = fmaf(xm2.y, w1.y, a.y);
                a.z = fmaf(xm2.z, w1.z, a.z); a.w = fmaf(xm2.w, w1.w, a.w);
                if (!st2) {
                    a.x = fmaf(xm3.x, w0.x, a.x); a.y = fmaf(xm3.y, w0.y, a.y);
                    a.z = fmaf(xm3.z, w0.z, a.z); a.w = fmaf(xm3.w, w0.w, a.w);
                }
            }
        }
        float4 v;
        v.x = a.x * sigmoidf_(a.x); v.y = a.y * sigmoidf_(a.y);
        v.z = a.z * sigmoidf_(a.z); v.w = a.w * sigmoidf_(a.w);
        *(float4*)&d_v[(size_t)t * VDIM + c] = v;
        xm3 = xm2; xm2 = xm1; xm1 = xt;
        st2 = st1; st1 = st;
    }
}

// ---------------- q at the 16 pooled positions ----------------
__global__ void k_q16(const int* __restrict__ cu, const float* __restrict__ Wq,
                      const float* __restrict__ cw) {
    __shared__ float shn[4][HH];
    __shared__ float sq[KDIM];
    int s = blockIdx.x;
    int pos = cu[s + 1] - 1;
    int seg = d_seg[pos];
    int tid = threadIdx.x;
    int valid[4];
#pragma unroll
    for (int r = 0; r < 4; ++r) {
        int t = pos - r;
        valid[r] = (t >= 0 && d_seg[t] == seg);
    }
#pragma unroll
    for (int r = 0; r < 4; ++r) {
        int t = pos - r;
        if (valid[r]) for (int i = tid; i < HH; i += 256) shn[r][i] = d_hn[(size_t)t * HH + i];
        else          for (int i = tid; i < HH; i += 256) shn[r][i] = 0.f;
    }
    __syncthreads();
    for (int c = tid; c < KDIM; c += 256) {
        float a0 = 0.f, a1 = 0.f, a2 = 0.f, a3 = 0.f;
        for (int i = 0; i < HH; ++i) {
            float wv = Wq[(size_t)i * KDIM + c];
            a0 = fmaf(shn[0][i], wv, a0);
            a1 = fmaf(shn[1][i], wv, a1);
            a2 = fmaf(shn[2][i], wv, a2);
            a3 = fmaf(shn[3][i], wv, a3);
        }
        float acc = a0 * cw[c * 4 + 3] + a1 * cw[c * 4 + 2] + a2 * cw[c * 4 + 1] + a3 * cw[c * 4 + 0];
        sq[c] = acc * sigmoidf_(acc);
    }
    __syncthreads();
    int w = tid >> 5, lane = tid & 31;
    for (int h = w; h < NHH; h += 8) {
        float ssq = 0.f;
        for (int i = lane; i < HKD; i += 32) { float v = sq[h * HKD + i]; ssq = fmaf(v, v, ssq); }
#pragma unroll
        for (int off = 16; off; off >>= 1) ssq += __shfl_xor_sync(0xffffffffu, ssq, off);
        float r = rsqrtf(ssq + 1e-6f) * 0.125f;
        for (int i = lane; i < HKD; i += 32)
            d_q[s * KDIM + h * HKD + i] = sq[h * HKD + i] * r;
    }
}

// ---------------- segment-parallel scan, packed f32x2, unroll-2 ----------------
__global__ void __launch_bounds__(128) k_scan(const int* __restrict__ cu) {
    __shared__ float  sk[2][SCH][64];
    __shared__ float  svv[2][SCH][64];
    __shared__ float4 scd[2][SCH];

    int half = blockIdx.x;
    int h    = blockIdx.y;
    int s    = blockIdx.z;
    int tid  = threadIdx.x;
    int colL = tid >> 1;
    int e    = tid & 1;
    int col  = half * 64 + colL;

    int start = cu[s];
    int end   = cu[s + 1];
    int len   = end - start;

    auto load_chunk = [&](int buf, int c0) {
        int rem = len - c0; if (rem > SCH) rem = SCH;
        for (int idx = tid; idx < rem * 16; idx += 128) {
            int i = idx >> 4, j = idx & 15;
            cpa16(&sk[buf][i][j * 4], d_k + (size_t)(start + c0 + i) * KDIM + h * HKD + j * 4);
        }
        for (int idx = tid; idx < rem * 16; idx += 128) {
            int i = idx >> 4, j = idx & 15;
            cpa16(&svv[buf][i][j * 4], d_v + (size_t)(start + c0 + i) * VDIM + h * HVD + half * 64 + j * 4);
        }
        if (tid < rem)
            cpa16(&scd[buf][tid], d_scd + (size_t)(start + c0 + tid) * NHH + h);
    };

    uint64_t S2[16];
#pragma unroll
    for (int i = 0; i < 16; ++i) S2[i] = 0ull;

    // one scan step given k/v/cd in registers
    auto step = [&](const uint64_t* K2, float vv, float4 cd) {
        uint64_t a0 = 0ull, a1 = 0ull;
#pragma unroll
        for (int j = 0; j < 16; j += 2) {
            FMA2(a0, S2[j],     K2[j],     a0);
            FMA2(a1, S2[j + 1], K2[j + 1], a1);
        }
        ADD2(a0, a0, a1);
        float lo, hi;
        UNPACKF2(lo, hi, a0);
        float dot = lo + hi;
        dot += __shfl_xor_sync(0xffffffffu, dot, 1);

        float lam = cd.x;
        float delta = cd.y * fmaf(-lam, dot, vv);
        uint64_t lam2, d2;
        PACKF2(lam2, lam, lam);
        PACKF2(d2, delta, delta);
#pragma unroll
        for (int j = 0; j < 16; ++j) {
            uint64_t t;
            MUL2(t, K2[j], d2);
            FMA2(S2[j], lam2, S2[j], t);
        }

        if (cd.z != 0.f) {
            int need = (int)cd.z - 1;
            const float4* qp = (const float4*)(d_q + (size_t)need * KDIM + h * HKD + e * 32);
            uint64_t oa = 0ull;
#pragma unroll
            for (int j = 0; j < 8; ++j) {
                float4 qv = qp[j];
                uint64_t q0, q1;
                PACKF2(q0, qv.x, qv.y);
                PACKF2(q1, qv.z, qv.w);
                FMA2(oa, S2[2 * j],     q0, oa);
                FMA2(oa, S2[2 * j + 1], q1, oa);
            }
            float olo, ohi;
            UNPACKF2(olo, ohi, oa);
            float od = olo + ohi;
            od += __shfl_xor_sync(0xffffffffu, od, 1);
            if (e == 0) d_o[need * VDIM + h * HVD + col] = od;
        }
    };

    auto loadK = [&](uint64_t* K2, int buf, int i) {
#pragma unroll
        for (int j = 0; j < 8; ++j) {
            uint32_t addr = smem_u32(&sk[buf][i][e * 32 + j * 4]);
            LDSV2U64(K2[2 * j], K2[2 * j + 1], addr);
        }
    };

    load_chunk(0, 0);
    CPA_COMMIT;

    int buf = 0;
    for (int c0 = 0; c0 < len; c0 += SCH, buf ^= 1) {
        __syncthreads();
        if (c0 + SCH < len) load_chunk(buf ^ 1, c0 + SCH);
        CPA_COMMIT;
        CPA_WAIT1;
        __syncthreads();

        int rem = len - c0; if (rem > SCH) rem = SCH;

        uint64_t Ka[16], Kb[16];
        float  va, vb;
        float4 cda, cdb;
        loadK(Ka, buf, 0);
        va  = svv[buf][0][colL];
        cda = scd[buf][0];

        int i = 0;
        while (i < rem) {
            // stage A: prefetch i+1 into B, compute with A
            int ip = (i + 1 < rem) ? i + 1 : i;
            loadK(Kb, buf, ip);
            vb  = svv[buf][ip][colL];
            cdb = scd[buf][ip];
            step(Ka, va, cda);
            ++i;
            if (i >= rem) break;
            // stage B: prefetch i+1 into A, compute with B
            int ip2 = (i + 1 < rem) ? i + 1 : i;
            loadK(Ka, buf, ip2);
            va  = svv[buf][ip2][colL];
            cda = scd[buf][ip2];
            step(Kb, vb, cdb);
            ++i;
        }
    }
}

// ---------------- Wo @ W_head ----------------
__global__ void k_wowh(const float* __restrict__ Wo, const float* __restrict__ Wh) {
    int j = blockIdx.x * 8 + (threadIdx.x >> 5);
    int lane = threadIdx.x & 31;
    float a = 0.f;
    for (int k = lane; k < HH; k += 32) a = fmaf(Wo[(size_t)j * HH + k], Wh[k], a);
#pragma unroll
    for (int off = 16; off; off >>= 1) a += __shfl_xor_sync(0xffffffffu, a, off);
    if (lane == 0) d_wowh[j] = a;
}

// ---------------- gate precompute (scan-independent): d_og = gs ----------------
__global__ void k_gatepre(const int* __restrict__ cu, const float* __restrict__ Wg) {
    __shared__ float shn[HH];
    int hd = blockIdx.x;
    int s = blockIdx.y;
    int pos = cu[s + 1] - 1;
    int tid = threadIdx.x;
    for (int i = tid; i < HH; i += 128) shn[i] = d_hn[(size_t)pos * HH + i];
    __syncthreads();
    float gate = 0.f;
    for (int i = 0; i < HH; ++i)
        gate = fmaf(shn[i], Wg[(size_t)i * VDIM + hd * HVD + tid], gate);
    d_og[s * VDIM + hd * HVD + tid] = gate * sigmoidf_(gate);
}

// ---------------- final: o-rmsnorm + gate + head ----------------
__global__ void k_final(const float* __restrict__ Wh, const float* __restrict__ bh,
                        const float* __restrict__ onw, float* __restrict__ out) {
    __shared__ float so[VDIM];
    __shared__ float hs[NHH];
    __shared__ float sred[256];
    int s = blockIdx.x;
    int tid = threadIdx.x;
    if (tid < NHH) hs[tid] = 0.f;
    __syncthreads();
    for (int j = tid; j < VDIM; j += 256) {
        float ov = d_o[s * VDIM + j];
        so[j] = ov;
        atomicAdd(&hs[j >> 7], ov * ov);
    }
    __syncthreads();
    float a = 0.f;
    for (int j = tid; j < VDIM; j += 256) {
        float rms = rsqrtf(hs[j >> 7] / (float)HVD + 1e-5f);
        a = fmaf(so[j] * rms * onw[j & 127] * d_og[s * VDIM + j], d_wowh[j], a);
    }
    for (int k = tid; k < HH; k += 256) a = fmaf(d_hrows[s * HH + k], Wh[k], a);
    sred[tid] = a;
    __syncthreads();
    for (int st = 128; st; st >>= 1) {
        if (tid < st) sred[tid] += sred[tid + st];
        __syncthreads();
    }
    if (tid == 0) out[s] = sred[0] + bh[0];
}

// ---------------- launch ----------------
extern "C" void kernel_launch(void* const* d_in, const int* in_sizes, int n_in,
                              void* d_out, int out_size) {
    const float* x     = (const float*)d_in[0];
    const int*   cu    = (const int*)d_in[1];
    const int*   acidx = (const int*)d_in[2];
    const float* actab = (const float*)d_in[3];
    const float* Win   = (const float*)d_in[4];
    const float* bin   = (const float*)d_in[5];
    const float* nw    = (const float*)d_in[6];
    const float* Wq    = (const float*)d_in[7];
    const float* Wk    = (const float*)d_in[8];
    const float* Wv    = (const float*)d_in[9];
    const float* cqw   = (const float*)d_in[10];
    const float* ckw   = (const float*)d_in[11];
    const float* cvw   = (const float*)d_in[12];
    const float* Wb    = (const float*)d_in[13];
    const float* Wa    = (const float*)d_in[14];
    const float* Alog  = (const float*)d_in[15];
    const float* dtb   = (const float*)d_in[16];
    const float* Wg    = (const float*)d_in[17];
    const float* onw   = (const float*)d_in[18];
    const float* Wo    = (const float*)d_in[19];
    const float* Wh    = (const float*)d_in[20];
    const float* bh    = (const float*)d_in[21];
    float* out = (float*)d_out;

    cudaFuncSetAttribute(k_mma, cudaFuncAttributeMaxDynamicSharedMemorySize, MM_SMEM);

    __half *wkf, *wvf, *hnf;
    cudaGetSymbolAddress((void**)&wkf, d_wkf);
    cudaGetSymbolAddress((void**)&wvf, d_wvf);
    cudaGetSymbolAddress((void**)&hnf, d_hnf);
    float *kpre, *vpre;
    cudaGetSymbolAddress((void**)&kpre, d_kpre);
    cudaGetSymbolAddress((void**)&vpre, d_vpre);

    k_prep<<<TT / 256, 256>>>(cu);
    k_embed<<<TT / 8, 256>>>(x, acidx, actab, Win, bin, nw);

    k_wcvt<<<dim3(VDIM / 32, HH / 32), dim3(32, 8)>>>(Wv, wvf, VDIM);
    k_mma<<<dim3(VDIM / 128, TT / 128), 256, MM_SMEM>>>(hnf, wvf, vpre, VDIM);
    k_wcvt<<<dim3(KDIM / 32, HH / 32), dim3(32, 8)>>>(Wk, wkf, KDIM);
    k_mma<<<dim3(KDIM / 128, TT / 128), 256, MM_SMEM>>>(hnf, wkf, kpre, KDIM);

    k_wt<<<24, 256>>>(Wa, Wb);
    k_ab2<<<TT / 8, 256>>>(Alog, dtb);
    k_convk<<<TT / KTCH, 192>>>(ckw);
    k_conv2<<<dim3(VDIM / (192 * 4), TT / VTCH), 192>>>(cvw);
    k_q16<<<NSEG, 256>>>(cu, Wq, cqw);
    k_wowh<<<VDIM / 8, 256>>>(Wo, Wh);
    k_gatepre<<<dim3(NHH, NSEG), 128>>>(cu, Wg);

    k_scan<<<dim3(2, NHH, NSEG), 128>>>(cu);

    k_final<<<NSEG, 256>>>(Wh, bh, onw, out);
}

// round 14
// speedup vs baseline: 1.5811x; 1.0163x over previous
#include <cuda_runtime.h>
#include <cuda_fp16.h>
#include <math.h>
#include <stdint.h>

#define TT   32768
#define HH   1024
#define DIN  16
#define ACD  32
#define NHH  12
#define KDIM 768
#define VDIM 1536
#define HKD  64
#define HVD  128
#define NSEG 16
#define SCH  40

// ---------------- scratch ----------------
static __device__ float  d_hn   [TT * HH];
static __device__ __half d_hnf  [TT * HH];
static __device__ __half d_wkf  [KDIM * HH];
static __device__ __half d_wvf  [VDIM * HH];
static __device__ float  d_kpre [TT * KDIM];
static __device__ float  d_vpre [TT * VDIM];
static __device__ float  d_k    [TT * KDIM];
static __device__ float  d_v    [TT * VDIM];
static __device__ float4 d_scd  [TT * NHH];     // (lam, beta, needf, 0)
static __device__ float  d_wt   [24 * HH];      // [Wa^T | Wb^T]
static __device__ int    d_seg  [TT];
static __device__ int    d_flags[TT];
static __device__ float  d_hrows[NSEG * HH];
static __device__ float  d_q    [NSEG * KDIM];
static __device__ float  d_o    [NSEG * VDIM];
static __device__ float  d_og   [NSEG * VDIM];  // silu-gated gate values
static __device__ float  d_wowh [VDIM];

__device__ __forceinline__ float sigmoidf_(float x) { return 1.f / (1.f + expf(-x)); }

// ---------------- PTX helpers (base sm_103 features only) ----------------
__device__ __forceinline__ uint32_t smem_u32(const void* p) {
    uint32_t a;
    asm("{ .reg .u64 t; cvta.to.shared.u64 t, %1; cvt.u32.u64 %0, t; }" : "=r"(a) : "l"(p));
    return a;
}
__device__ __forceinline__ void cpa16s(uint32_t s, const void* g) {
    asm volatile("cp.async.cg.shared.global [%0], [%1], 16;" :: "r"(s), "l"(g));
}
__device__ __forceinline__ void cpa16(void* s, const void* g) { cpa16s(smem_u32(s), g); }
#define CPA_COMMIT asm volatile("cp.async.commit_group;")
#define CPA_WAIT0  asm volatile("cp.async.wait_group 0;")
#define CPA_WAIT1  asm volatile("cp.async.wait_group 1;")
#define CPA_WAIT2  asm volatile("cp.async.wait_group 2;")

#define LDM4(r, addr) \
    asm volatile("ldmatrix.sync.aligned.m8n8.x4.shared.b16 {%0,%1,%2,%3}, [%4];" \
        : "=r"((r)[0]), "=r"((r)[1]), "=r"((r)[2]), "=r"((r)[3]) : "r"(addr))

#define MMAH(d, a, b0, b1) \
    asm volatile("mma.sync.aligned.m16n8k16.row.col.f32.f16.f16.f32 " \
        "{%0,%1,%2,%3}, {%4,%5,%6,%7}, {%8,%9}, {%0,%1,%2,%3};" \
        : "+f"((d)[0]), "+f"((d)[1]), "+f"((d)[2]), "+f"((d)[3]) \
        : "r"((a)[0]), "r"((a)[1]), "r"((a)[2]), "r"((a)[3]), "r"(b0), "r"(b1))

// packed fp32x2 (Blackwell base ISA, sm_100+)
#define FMA2(d, a, b, c) asm("fma.rn.f32x2 %0, %1, %2, %3;" : "=l"(d) : "l"(a), "l"(b), "l"(c))
#define MUL2(d, a, b)    asm("mul.rn.f32x2 %0, %1, %2;" : "=l"(d) : "l"(a), "l"(b))
#define ADD2(d, a, b)    asm("add.rn.f32x2 %0, %1, %2;" : "=l"(d) : "l"(a), "l"(b))
#define PACKF2(d, lo, hi) asm("mov.b64 %0, {%1, %2};" : "=l"(d) : "f"(lo), "f"(hi))
#define UNPACKF2(lo, hi, s) asm("mov.b64 {%0, %1}, %2;" : "=f"(lo), "=f"(hi) : "l"(s))
#define LDSV2U64(a, b, addr) \
    asm volatile("ld.shared.v2.b64 {%0, %1}, [%2];" : "=l"(a), "=l"(b) : "r"(addr))

// ---------------- seg ids + flags ----------------
__global__ void k_prep(const int* __restrict__ cu) {
    int t = blockIdx.x * 256 + threadIdx.x;
    if (t >= TT) return;
    int seg = 0;
#pragma unroll
    for (int s = 1; s <= NSEG; ++s) if (t >= cu[s]) seg = s;
    d_seg[t] = seg;
    int fl = (t == cu[seg]) ? 1 : 0;
#pragma unroll
    for (int s = 0; s < NSEG; ++s) if (t == cu[s + 1] - 1) fl |= ((s + 1) << 1);
    d_flags[t] = fl;
}

// ---------------- embed + rmsnorm + fp16 conversion ----------------
__global__ void k_embed(const float* __restrict__ x, const int* __restrict__ acidx,
                        const float* __restrict__ actab, const float* __restrict__ Win,
                        const float* __restrict__ bin, const float* __restrict__ nw) {
    __shared__ float sx[8][48];
    __shared__ float sps[8][256];
    __shared__ float srms[8];
    int t0 = blockIdx.x * 8;
    int tid = threadIdx.x;
    for (int idx = tid; idx < 8 * 48; idx += 256) {
        int r = idx / 48, i = idx % 48;
        int t = t0 + r;
        float v;
        if (i < DIN) v = x[t * DIN + i];
        else v = actab[acidx[d_seg[t]] * ACD + (i - DIN)];
        sx[r][i] = v;
    }
    __syncthreads();

    float hreg[4][8];
    float ps[8];
#pragma unroll
    for (int r = 0; r < 8; ++r) ps[r] = 0.f;

#pragma unroll
    for (int jj = 0; jj < 4; ++jj) {
        int j = tid + jj * 256;
        float acc[8];
        float bb = bin[j];
#pragma unroll
        for (int r = 0; r < 8; ++r) acc[r] = bb;
        for (int i = 0; i < 48; ++i) {
            float w = Win[i * HH + j];
#pragma unroll
            for (int r = 0; r < 8; ++r) acc[r] = fmaf(sx[r][i], w, acc[r]);
        }
#pragma unroll
        for (int r = 0; r < 8; ++r) { hreg[jj][r] = acc[r]; ps[r] = fmaf(acc[r], acc[r], ps[r]); }
    }
#pragma unroll
    for (int r = 0; r < 8; ++r) sps[r][tid] = ps[r];
    __syncthreads();
    int w = tid >> 5, lane = tid & 31;
    float s = sps[w][lane];
#pragma unroll
    for (int i = 1; i < 8; ++i) s += sps[w][lane + 32 * i];
#pragma unroll
    for (int off = 16; off; off >>= 1) s += __shfl_xor_sync(0xffffffffu, s, off);
    if (lane == 0) srms[w] = rsqrtf(s / (float)HH + 1e-6f);
    __syncthreads();

    int needr[8];
#pragma unroll
    for (int r = 0; r < 8; ++r) needr[r] = d_flags[t0 + r] >> 1;

#pragma unroll
    for (int jj = 0; jj < 4; ++jj) {
        int j = tid + jj * 256;
        float nwj = 1.0f + nw[j];
#pragma unroll
        for (int r = 0; r < 8; ++r) {
            int t = t0 + r;
            float val = hreg[jj][r] * srms[r] * nwj;
            d_hn[t * HH + j] = val;
            d_hnf[(size_t)t * HH + j] = __float2half(val);
            if (needr[r]) d_hrows[(needr[r] - 1) * HH + j] = hreg[jj][r];
        }
    }
}

// ---------------- weight transpose + fp16 ----------------
__global__ void k_wcvt(const float* __restrict__ W, __half* __restrict__ outw, int N) {
    __shared__ float tile[32][33];
    int n0 = blockIdx.x * 32, k0 = blockIdx.y * 32;
    int tx = threadIdx.x, ty = threadIdx.y;
    for (int i = ty; i < 32; i += 8)
        tile[i][tx] = W[(size_t)(k0 + i) * N + n0 + tx];
    __syncthreads();
    for (int i = ty; i < 32; i += 8)
        outw[(size_t)(n0 + i) * HH + k0 + tx] = __float2half(tile[tx][i]);
}

// ---------------- Wa/Wb transpose ----------------
__global__ void k_wt(const float* __restrict__ Wa, const float* __restrict__ Wb) {
    int c = blockIdx.x;
    int tid = threadIdx.x;
    const float* src = (c < NHH) ? Wa : Wb;
    int cc = (c < NHH) ? c : c - NHH;
    for (int k = tid; k < HH; k += 256)
        d_wt[c * HH + k] = src[(size_t)k * NHH + cc];
}

// ---------------- fp16 mma.sync GEMM: 4-stage, single barrier per chunk ----------------
#define MM_ROW   40
#define MM_ATEN  (128 * MM_ROW)
#define MM_BTEN  (128 * MM_ROW)
#define MM_STG   (MM_ATEN + MM_BTEN)
#define MM_NSTG  4
#define MM_SMEM  (MM_NSTG * MM_STG * 2)    // 81920 bytes
#define MM_NCH   (HH / 32)

__global__ void __launch_bounds__(256, 2)
k_mma(const __half* __restrict__ A_, const __half* __restrict__ B_,
      float* __restrict__ C, int N) {
    extern __shared__ __align__(128) __half sm[];
    uint32_t sb = smem_u32(sm);
    int tid = threadIdx.x, lane = tid & 31, wid = tid >> 5;
    int wm = wid & 1, wn = wid >> 1;
    int ntile = blockIdx.x, mtile = blockIdx.y;

    const __half* Af = A_ + (size_t)(mtile * 128) * HH;
    const __half* Bf = B_ + (size_t)(ntile * 128) * HH;

    float acc[4][4][4];
#pragma unroll
    for (int m = 0; m < 4; ++m)
#pragma unroll
        for (int n = 0; n < 4; ++n)
#pragma unroll
            for (int i = 0; i < 4; ++i) acc[m][n][i] = 0.f;

    int ab[4];
#pragma unroll
    for (int m = 0; m < 4; ++m)
        ab[m] = (wm * 64 + m * 16 + (lane & 15)) * MM_ROW + (lane >> 4) * 8;
    int bb[2];
#pragma unroll
    for (int p = 0; p < 2; ++p)
        bb[p] = (wn * 32 + p * 16 + (lane & 7) + ((lane >> 4) & 1) * 8) * MM_ROW + ((lane >> 3) & 1) * 8;

    auto load_stage = [&](int stg, int k0) {
        uint32_t base = sb + 2 * (stg * MM_STG);
#pragma unroll
        for (int it = 0; it < 2; ++it) {
            int idx = tid + it * 256;
            int r = idx >> 2, cc = idx & 3;
            cpa16s(base + 2 * (r * MM_ROW + cc * 8), Af + (size_t)r * HH + k0 + cc * 8);
        }
#pragma unroll
        for (int it = 0; it < 2; ++it) {
            int idx = tid + it * 256;
            int r = idx >> 2, cc = idx & 3;
            cpa16s(base + 2 * (MM_ATEN + r * MM_ROW + cc * 8), Bf + (size_t)r * HH + k0 + cc * 8);
        }
    };

    load_stage(0, 0);  CPA_COMMIT;
    load_stage(1, 32); CPA_COMMIT;
    load_stage(2, 64); CPA_COMMIT;

    for (int c = 0; c < MM_NCH; ++c) {
        int stg = c & 3;
        CPA_WAIT2;              // stage c landed (always-commit keeps group count aligned)
        __syncthreads();        // all warps finished reading stage (c-1)%4 == (c+3)%4
        if (c + 3 < MM_NCH) load_stage((c + 3) & 3, (c + 3) * 32);
        CPA_COMMIT;             // commit (possibly empty group)

        uint32_t base = sb + 2 * (stg * MM_STG);
#pragma unroll
        for (int ks = 0; ks < 2; ++ks) {
            uint32_t a4[4][4];
#pragma unroll
            for (int m = 0; m < 4; ++m) LDM4(a4[m], base + 2 * (ab[m] + ks * 16));
#pragma unroll
            for (int p = 0; p < 2; ++p) {
                uint32_t rb[4];
                LDM4(rb, base + 2 * (MM_ATEN + bb[p] + ks * 16));
#pragma unroll
                for (int m = 0; m < 4; ++m) {
                    MMAH(acc[m][2 * p],     a4[m], rb[0], rb[1]);
                    MMAH(acc[m][2 * p + 1], a4[m], rb[2], rb[3]);
                }
            }
        }
    }

#pragma unroll
    for (int m = 0; m < 4; ++m) {
        int row = mtile * 128 + wm * 64 + m * 16 + (lane >> 2);
#pragma unroll
        for (int n = 0; n < 4; ++n) {
            int col = ntile * 128 + wn * 32 + n * 8 + (lane & 3) * 2;
            float2 v0 = make_float2(acc[m][n][0], acc[m][n][1]);
            float2 v1 = make_float2(acc[m][n][2], acc[m][n][3]);
            *(float2*)&C[(size_t)row * N + col] = v0;
            *(float2*)&C[(size_t)(row + 8) * N + col] = v1;
        }
    }
}

// ---------------- hn@[Wa|Wb] with coalesced transposed weights ----------------
__global__ void k_ab2(const float* __restrict__ Alog, const float* __restrict__ dtb) {
    int row = blockIdx.x * 8 + (threadIdx.x >> 5);
    int lane = threadIdx.x & 31;
    float4 hv[8];
    const float4* hp = (const float4*)(d_hn + (size_t)row * HH);
#pragma unroll
    for (int i = 0; i < 8; ++i) hv[i] = hp[lane + 32 * i];

    float res[24];
#pragma unroll
    for (int c = 0; c < 24; ++c) {
        const float4* wp = (const float4*)(d_wt + c * HH);
        float a0 = 0.f, a1 = 0.f, a2 = 0.f, a3 = 0.f;
#pragma unroll
        for (int i = 0; i < 8; ++i) {
            float4 w = wp[lane + 32 * i];
            a0 = fmaf(hv[i].x, w.x, a0);
            a1 = fmaf(hv[i].y, w.y, a1);
            a2 = fmaf(hv[i].z, w.z, a2);
            a3 = fmaf(hv[i].w, w.w, a3);
        }
        res[c] = (a0 + a1) + (a2 + a3);
    }
#pragma unroll
    for (int c = 0; c < 24; ++c) {
#pragma unroll
        for (int off = 16; off; off >>= 1)
            res[c] += __shfl_xor_sync(0xffffffffu, res[c], off);
    }
    if (lane < NHH) {
        float xx = res[lane] + dtb[lane];
        float sp = (xx > 20.f) ? xx : log1pf(expf(xx));
        float g = -expf(Alog[lane]) * sp;
        int fl = d_flags[row];
        float4 o;
        o.x = (fl & 1) ? 0.f : expf(g);
        o.y = sigmoidf_(res[12 + lane]);
        o.z = (float)(fl >> 1);
        o.w = 0.f;
        d_scd[(size_t)row * NHH + lane] = o;
    }
}

// ---------------- k-path conv + silu + l2norm, float4, 8 timesteps ----------------
#define KTCH 8
__global__ void __launch_bounds__(192) k_convk(const float* __restrict__ cw) {
    int tid = threadIdx.x;
    int c = tid * 4;
    int t0 = blockIdx.x * KTCH;
    float4 w0, w1, w2, w3;
    {
        const float4* cwp = (const float4*)(cw + c * 4);
        float4 a = cwp[0], b = cwp[1], cc2 = cwp[2], d = cwp[3];
        w0 = make_float4(a.x, b.x, cc2.x, d.x);
        w1 = make_float4(a.y, b.y, cc2.y, d.y);
        w2 = make_float4(a.z, b.z, cc2.z, d.z);
        w3 = make_float4(a.w, b.w, cc2.w, d.w);
    }
    float4 xm1 = {0,0,0,0}, xm2 = {0,0,0,0}, xm3 = {0,0,0,0};
    int st1 = 1, st2 = 1;
    if (t0 >= 1) { xm1 = *(const float4*)&d_kpre[(size_t)(t0 - 1) * KDIM + c]; st1 = d_flags[t0 - 1] & 1; }
    if (t0 >= 2) { xm2 = *(const float4*)&d_kpre[(size_t)(t0 - 2) * KDIM + c]; st2 = d_flags[t0 - 2] & 1; }
    if (t0 >= 3) { xm3 = *(const float4*)&d_kpre[(size_t)(t0 - 3) * KDIM + c]; }

    float4 val[KTCH];
    float ssq[KTCH];
#pragma unroll
    for (int tt = 0; tt < KTCH; ++tt) {
        int t = t0 + tt;
        float4 xt = *(const float4*)&d_kpre[(size_t)t * KDIM + c];
        int st = d_flags[t] & 1;
        float4 a;
        a.x = xt.x * w3.x; a.y = xt.y * w3.y; a.z = xt.z * w3.z; a.w = xt.w * w3.w;
        if (!st) {
            a.x = fmaf(xm1.x, w2.x, a.x); a.y = fmaf(xm1.y, w2.y, a.y);
            a.z = fmaf(xm1.z, w2.z, a.z); a.w = fmaf(xm1.w, w2.w, a.w);
            if (!st1) {
                a.x = fmaf(xm2.x, w1.x, a.x); a.y = fmaf(xm2.y, w1.y, a.y);
                a.z = fmaf(xm2.z, w1.z, a.z); a.w = fmaf(xm2.w, w1.w, a.w);
                if (!st2) {
                    a.x = fmaf(xm3.x, w0.x, a.x); a.y = fmaf(xm3.y, w0.y, a.y);
                    a.z = fmaf(xm3.z, w0.z, a.z); a.w = fmaf(xm3.w, w0.w, a.w);
                }
            }
        }
        float4 v;
        v.x = a.x * sigmoidf_(a.x); v.y = a.y * sigmoidf_(a.y);
        v.z = a.z * sigmoidf_(a.z); v.w = a.w * sigmoidf_(a.w);
        val[tt] = v;
        ssq[tt] = fmaf(v.x, v.x, fmaf(v.y, v.y, fmaf(v.z, v.z, v.w * v.w)));
        xm3 = xm2; xm2 = xm1; xm1 = xt;
        st2 = st1; st1 = st;
    }
#pragma unroll
    for (int tt = 0; tt < KTCH; ++tt) {
        float s = ssq[tt];
        s += __shfl_xor_sync(0xffffffffu, s, 1);
        s += __shfl_xor_sync(0xffffffffu, s, 2);
        s += __shfl_xor_sync(0xffffffffu, s, 4);
        s += __shfl_xor_sync(0xffffffffu, s, 8);
        float r = rsqrtf(s + 1e-6f);
        float4 v = val[tt];
        v.x *= r; v.y *= r; v.z *= r; v.w *= r;
        *(float4*)&d_k[(size_t)(t0 + tt) * KDIM + c] = v;
    }
}

// ---------------- v-path conv + silu, float4, immediate store ----------------
#define VTCH 16
__global__ void __launch_bounds__(192) k_conv2(const float* __restrict__ cw) {
    int c = (blockIdx.x * 192 + threadIdx.x) * 4;
    int t0 = blockIdx.y * VTCH;
    float4 w0, w1, w2, w3;
    {
        const float4* cwp = (const float4*)(cw + c * 4);
        float4 a = cwp[0], b = cwp[1], cc2 = cwp[2], d = cwp[3];
        w0 = make_float4(a.x, b.x, cc2.x, d.x);
        w1 = make_float4(a.y, b.y, cc2.y, d.y);
        w2 = make_float4(a.z, b.z, cc2.z, d.z);
        w3 = make_float4(a.w, b.w, cc2.w, d.w);
    }
    float4 xm1 = {0,0,0,0}, xm2 = {0,0,0,0}, xm3 = {0,0,0,0};
    int st1 = 1, st2 = 1;
    if (t0 >= 1) { xm1 = *(const float4*)&d_vpre[(size_t)(t0 - 1) * VDIM + c]; st1 = d_flags[t0 - 1] & 1; }
    if (t0 >= 2) { xm2 = *(const float4*)&d_vpre[(size_t)(t0 - 2) * VDIM + c]; st2 = d_flags[t0 - 2] & 1; }
    if (t0 >= 3) { xm3 = *(const float4*)&d_vpre[(size_t)(t0 - 3) * VDIM + c]; }
#pragma unroll 4
    for (int tt = 0; tt < VTCH; ++tt) {
        int t = t0 + tt;
        float4 xt = *(const float4*)&d_vpre[(size_t)t * VDIM + c];
        int st = d_flags[t] & 1;
        float4 a;
        a.x = xt.x * w3.x; a.y = xt.y * w3.y; a.z = xt.z * w3.z; a.w = xt.w * w3.w;
        if (!st) {
            a.x = fmaf(xm1.x, w2.x, a.x); a.y = fmaf(xm1.y, w2.y, a.y);
            a.z = fmaf(xm1.z, w2.z, a.z); a.w = fmaf(xm1.w, w2.w, a.w);
            if (!st1) {
                a.x = fmaf(xm2.x, w1.x, a.x); a.y = fmaf(xm2.y, w1.y, a.y);
                a.z = fmaf(xm2.z, w1.z, a.z); a.w = fmaf(xm2.w, w1.w, a.w);
                if (!st2) {
                    a.x = fmaf(xm3.x, w0.x, a.x); a.y = fmaf(xm3.y, w0.y, a.y);
                    a.z = fmaf(xm3.z, w0.z, a.z); a.w = fmaf(xm3.w, w0.w, a.w);
                }
            }
        }
        float4 v;
        v.x = a.x * sigmoidf_(a.x); v.y = a.y * sigmoidf_(a.y);
        v.z = a.z * sigmoidf_(a.z); v.w = a.w * sigmoidf_(a.w);
        *(float4*)&d_v[(size_t)t * VDIM + c] = v;
        xm3 = xm2; xm2 = xm1; xm1 = xt;
        st2 = st1; st1 = st;
    }
}

// ---------------- q at the 16 pooled positions ----------------
__global__ void k_q16(const int* __restrict__ cu, const float* __restrict__ Wq,
                      const float* __restrict__ cw) {
    __shared__ float shn[4][HH];
    __shared__ float sq[KDIM];
    int s = blockIdx.x;
    int pos = cu[s + 1] - 1;
    int seg = d_seg[pos];
    int tid = threadIdx.x;
    int valid[4];
#pragma unroll
    for (int r = 0; r < 4; ++r) {
        int t = pos - r;
        valid[r] = (t >= 0 && d_seg[t] == seg);
    }
#pragma unroll
    for (int r = 0; r < 4; ++r) {
        int t = pos - r;
        if (valid[r]) for (int i = tid; i < HH; i += 256) shn[r][i] = d_hn[(size_t)t * HH + i];
        else          for (int i = tid; i < HH; i += 256) shn[r][i] = 0.f;
    }
    __syncthreads();
    for (int c = tid; c < KDIM; c += 256) {
        float a0 = 0.f, a1 = 0.f, a2 = 0.f, a3 = 0.f;
        for (int i = 0; i < HH; ++i) {
            float wv = Wq[(size_t)i * KDIM + c];
            a0 = fmaf(shn[0][i], wv, a0);
            a1 = fmaf(shn[1][i], wv, a1);
            a2 = fmaf(shn[2][i], wv, a2);
            a3 = fmaf(shn[3][i], wv, a3);
        }
        float acc = a0 * cw[c * 4 + 3] + a1 * cw[c * 4 + 2] + a2 * cw[c * 4 + 1] + a3 * cw[c * 4 + 0];
        sq[c] = acc * sigmoidf_(acc);
    }
    __syncthreads();
    int w = tid >> 5, lane = tid & 31;
    for (int h = w; h < NHH; h += 8) {
        float ssq = 0.f;
        for (int i = lane; i < HKD; i += 32) { float v = sq[h * HKD + i]; ssq = fmaf(v, v, ssq); }
#pragma unroll
        for (int off = 16; off; off >>= 1) ssq += __shfl_xor_sync(0xffffffffu, ssq, off);
        float r = rsqrtf(ssq + 1e-6f) * 0.125f;
        for (int i = lane; i < HKD; i += 32)
            d_q[s * KDIM + h * HKD + i] = sq[h * HKD + i] * r;
    }
}

// ---------------- segment-parallel scan, packed f32x2, unroll-2 ----------------
__global__ void __launch_bounds__(128) k_scan(const int* __restrict__ cu) {
    __shared__ float  sk[2][SCH][64];
    __shared__ float  svv[2][SCH][64];
    __shared__ float4 scd[2][SCH];

    int half = blockIdx.x;
    int h    = blockIdx.y;
    int s    = blockIdx.z;
    int tid  = threadIdx.x;
    int colL = tid >> 1;
    int e    = tid & 1;
    int col  = half * 64 + colL;

    int start = cu[s];
    int end   = cu[s + 1];
    int len   = end - start;

    auto load_chunk = [&](int buf, int c0) {
        int rem = len - c0; if (rem > SCH) rem = SCH;
        for (int idx = tid; idx < rem * 16; idx += 128) {
            int i = idx >> 4, j = idx & 15;
            cpa16(&sk[buf][i][j * 4], d_k + (size_t)(start + c0 + i) * KDIM + h * HKD + j * 4);
        }
        for (int idx = tid; idx < rem * 16; idx += 128) {
            int i = idx >> 4, j = idx & 15;
            cpa16(&svv[buf][i][j * 4], d_v + (size_t)(start + c0 + i) * VDIM + h * HVD + half * 64 + j * 4);
        }
        if (tid < rem)
            cpa16(&scd[buf][tid], d_scd + (size_t)(start + c0 + tid) * NHH + h);
    };

    uint64_t S2[16];
#pragma unroll
    for (int i = 0; i < 16; ++i) S2[i] = 0ull;

    auto step = [&](const uint64_t* K2, float vv, float4 cd) {
        uint64_t a0 = 0ull, a1 = 0ull;
#pragma unroll
        for (int j = 0; j < 16; j += 2) {
            FMA2(a0, S2[j],     K2[j],     a0);
            FMA2(a1, S2[j + 1], K2[j + 1], a1);
        }
        ADD2(a0, a0, a1);
        float lo, hi;
        UNPACKF2(lo, hi, a0);
        float dot = lo + hi;
        dot += __shfl_xor_sync(0xffffffffu, dot, 1);

        float lam = cd.x;
        float delta = cd.y * fmaf(-lam, dot, vv);
        uint64_t lam2, d2;
        PACKF2(lam2, lam, lam);
        PACKF2(d2, delta, delta);
#pragma unroll
        for (int j = 0; j < 16; ++j) {
            uint64_t t;
            MUL2(t, K2[j], d2);
            FMA2(S2[j], lam2, S2[j], t);
        }

        if (cd.z != 0.f) {
            int need = (int)cd.z - 1;
            const float4* qp = (const float4*)(d_q + (size_t)need * KDIM + h * HKD + e * 32);
            uint64_t oa = 0ull;
#pragma unroll
            for (int j = 0; j < 8; ++j) {
                float4 qv = qp[j];
                uint64_t q0, q1;
                PACKF2(q0, qv.x, qv.y);
                PACKF2(q1, qv.z, qv.w);
                FMA2(oa, S2[2 * j],     q0, oa);
                FMA2(oa, S2[2 * j + 1], q1, oa);
            }
            float olo, ohi;
            UNPACKF2(olo, ohi, oa);
            float od = olo + ohi;
            od += __shfl_xor_sync(0xffffffffu, od, 1);
            if (e == 0) d_o[need * VDIM + h * HVD + col] = od;
        }
    };

    auto loadK = [&](uint64_t* K2, int buf, int i) {
#pragma unroll
        for (int j = 0; j < 8; ++j) {
            uint32_t addr = smem_u32(&sk[buf][i][e * 32 + j * 4]);
            LDSV2U64(K2[2 * j], K2[2 * j + 1], addr);
        }
    };

    load_chunk(0, 0);
    CPA_COMMIT;

    int buf = 0;
    for (int c0 = 0; c0 < len; c0 += SCH, buf ^= 1) {
        __syncthreads();
        if (c0 + SCH < len) load_chunk(buf ^ 1, c0 + SCH);
        CPA_COMMIT;
        CPA_WAIT1;
        __syncthreads();

        int rem = len - c0; if (rem > SCH) rem = SCH;

        uint64_t Ka[16], Kb[16];
        float  va, vb;
        float4 cda, cdb;
        loadK(Ka, buf, 0);
        va  = svv[buf][0][colL];
        cda = scd[buf][0];

        int i = 0;
        while (i < rem) {
            int ip = (i + 1 < rem) ? i + 1 : i;
            loadK(Kb, buf, ip);
            vb  = svv[buf][ip][colL];
            cdb = scd[buf][ip];
            step(Ka, va, cda);
            ++i;
            if (i >= rem) break;
            int ip2 = (i + 1 < rem) ? i + 1 : i;
            loadK(Ka, buf, ip2);
            va  = svv[buf][ip2][colL];
            cda = scd[buf][ip2];
            step(Kb, vb, cdb);
            ++i;
        }
    }
}

// ---------------- Wo @ W_head ----------------
__global__ void k_wowh(const float* __restrict__ Wo, const float* __restrict__ Wh) {
    int j = blockIdx.x * 8 + (threadIdx.x >> 5);
    int lane = threadIdx.x & 31;
    float a = 0.f;
    for (int k = lane; k < HH; k += 32) a = fmaf(Wo[(size_t)j * HH + k], Wh[k], a);
#pragma unroll
    for (int off = 16; off; off >>= 1) a += __shfl_xor_sync(0xffffffffu, a, off);
    if (lane == 0) d_wowh[j] = a;
}

// ---------------- gate precompute (scan-independent): d_og = gs ----------------
__global__ void k_gatepre(const int* __restrict__ cu, const float* __restrict__ Wg) {
    __shared__ float shn[HH];
    int hd = blockIdx.x;
    int s = blockIdx.y;
    int pos = cu[s + 1] - 1;
    int tid = threadIdx.x;
    for (int i = tid; i < HH; i += 128) shn[i] = d_hn[(size_t)pos * HH + i];
    __syncthreads();
    float gate = 0.f;
    for (int i = 0; i < HH; ++i)
        gate = fmaf(shn[i], Wg[(size_t)i * VDIM + hd * HVD + tid], gate);
    d_og[s * VDIM + hd * HVD + tid] = gate * sigmoidf_(gate);
}

// ---------------- final: o-rmsnorm + gate + head ----------------
__global__ void k_final(const float* __restrict__ Wh, const float* __restrict__ bh,
                        const float* __restrict__ onw, float* __restrict__ out) {
    __shared__ float so[VDIM];
    __shared__ float hs[NHH];
    __shared__ float sred[256];
    int s = blockIdx.x;
    int tid = threadIdx.x;
    if (tid < NHH) hs[tid] = 0.f;
    __syncthreads();
    for (int j = tid; j < VDIM; j += 256) {
        float ov = d_o[s * VDIM + j];
        so[j] = ov;
        atomicAdd(&hs[j >> 7], ov * ov);
    }
    __syncthreads();
    float a = 0.f;
    for (int j = tid; j < VDIM; j += 256) {
        float rms = rsqrtf(hs[j >> 7] / (float)HVD + 1e-5f);
        a = fmaf(so[j] * rms * onw[j & 127] * d_og[s * VDIM + j], d_wowh[j], a);
    }
    for (int k = tid; k < HH; k += 256) a = fmaf(d_hrows[s * HH + k], Wh[k], a);
    sred[tid] = a;
    __syncthreads();
    for (int st = 128; st; st >>= 1) {
        if (tid < st) sred[tid] += sred[tid + st];
        __syncthreads();
    }
    if (tid == 0) out[s] = sred[0] + bh[0];
}

// ---------------- launch ----------------
extern "C" void kernel_launch(void* const* d_in, const int* in_sizes, int n_in,
                              void* d_out, int out_size) {
    const float* x     = (const float*)d_in[0];
    const int*   cu    = (const int*)d_in[1];
    const int*   acidx = (const int*)d_in[2];
    const float* actab = (const float*)d_in[3];
    const float* Win   = (const float*)d_in[4];
    const float* bin   = (const float*)d_in[5];
    const float* nw    = (const float*)d_in[6];
    const float* Wq    = (const float*)d_in[7];
    const float* Wk    = (const float*)d_in[8];
    const float* Wv    = (const float*)d_in[9];
    const float* cqw   = (const float*)d_in[10];
    const float* ckw   = (const float*)d_in[11];
    const float* cvw   = (const float*)d_in[12];
    const float* Wb    = (const float*)d_in[13];
    const float* Wa    = (const float*)d_in[14];
    const float* Alog  = (const float*)d_in[15];
    const float* dtb   = (const float*)d_in[16];
    const float* Wg    = (const float*)d_in[17];
    const float* onw   = (const float*)d_in[18];
    const float* Wo    = (const float*)d_in[19];
    const float* Wh    = (const float*)d_in[20];
    const float* bh    = (const float*)d_in[21];
    float* out = (float*)d_out;

    cudaFuncSetAttribute(k_mma, cudaFuncAttributeMaxDynamicSharedMemorySize, MM_SMEM);

    __half *wkf, *wvf, *hnf;
    cudaGetSymbolAddress((void**)&wkf, d_wkf);
    cudaGetSymbolAddress((void**)&wvf, d_wvf);
    cudaGetSymbolAddress((void**)&hnf, d_hnf);
    float *kpre, *vpre;
    cudaGetSymbolAddress((void**)&kpre, d_kpre);
    cudaGetSymbolAddress((void**)&vpre, d_vpre);

    k_prep<<<TT / 256, 256>>>(cu);
    k_embed<<<TT / 8, 256>>>(x, acidx, actab, Win, bin, nw);

    k_wcvt<<<dim3(VDIM / 32, HH / 32), dim3(32, 8)>>>(Wv, wvf, VDIM);
    k_mma<<<dim3(VDIM / 128, TT / 128), 256, MM_SMEM>>>(hnf, wvf, vpre, VDIM);
    k_wcvt<<<dim3(KDIM / 32, HH / 32), dim3(32, 8)>>>(Wk, wkf, KDIM);
    k_mma<<<dim3(KDIM / 128, TT / 128), 256, MM_SMEM>>>(hnf, wkf, kpre, KDIM);

    k_wt<<<24, 256>>>(Wa, Wb);
    k_ab2<<<TT / 8, 256>>>(Alog, dtb);
    k_convk<<<TT / KTCH, 192>>>(ckw);
    k_conv2<<<dim3(VDIM / (192 * 4), TT / VTCH), 192>>>(cvw);
    k_q16<<<NSEG, 256>>>(cu, Wq, cqw);
    k_wowh<<<VDIM / 8, 256>>>(Wo, Wh);
    k_gatepre<<<dim3(NHH, NSEG), 128>>>(cu, Wg);

    k_scan<<<dim3(2, NHH, NSEG), 128>>>(cu);

    k_final<<<NSEG, 256>>>(Wh, bh, onw, out);
}

// round 15
// speedup vs baseline: 1.5823x; 1.0008x over previous
#include <cuda_runtime.h>
#include <cuda_fp16.h>
#include <math.h>
#include <stdint.h>

#define TT   32768
#define HH   1024
#define DIN  16
#define ACD  32
#define NHH  12
#define KDIM 768
#define VDIM 1536
#define HKD  64
#define HVD  128
#define NSEG 16
#define SCH  40

// ---------------- scratch ----------------
static __device__ float  d_hn   [TT * HH];
static __device__ __half d_hnf  [TT * HH];
static __device__ __half d_wkf  [KDIM * HH];
static __device__ __half d_wvf  [VDIM * HH];
static __device__ float  d_kpre [TT * KDIM];
static __device__ float  d_vpre [TT * VDIM];
static __device__ float  d_k    [TT * KDIM];
static __device__ float  d_v    [TT * VDIM];
static __device__ float4 d_scd  [TT * NHH];     // (lam, beta, needf, 0)
static __device__ float  d_wt   [24 * HH];      // [Wa^T | Wb^T]
static __device__ int    d_seg  [TT];
static __device__ int    d_flags[TT];
static __device__ float  d_hrows[NSEG * HH];
static __device__ float  d_q    [NSEG * KDIM];
static __device__ float  d_o    [NSEG * VDIM];
static __device__ float  d_og   [NSEG * VDIM];  // silu-gated gate values
static __device__ float  d_wowh [VDIM];

__device__ __forceinline__ float sigmoidf_(float x) { return 1.f / (1.f + expf(-x)); }

// ---------------- PTX helpers (base sm_103 features only) ----------------
__device__ __forceinline__ uint32_t smem_u32(const void* p) {
    uint32_t a;
    asm("{ .reg .u64 t; cvta.to.shared.u64 t, %1; cvt.u32.u64 %0, t; }" : "=r"(a) : "l"(p));
    return a;
}
__device__ __forceinline__ void cpa16s(uint32_t s, const void* g) {
    asm volatile("cp.async.cg.shared.global [%0], [%1], 16;" :: "r"(s), "l"(g));
}
__device__ __forceinline__ void cpa16(void* s, const void* g) { cpa16s(smem_u32(s), g); }
#define CPA_COMMIT asm volatile("cp.async.commit_group;")
#define CPA_WAIT0  asm volatile("cp.async.wait_group 0;")
#define CPA_WAIT1  asm volatile("cp.async.wait_group 1;")
#define CPA_WAIT2  asm volatile("cp.async.wait_group 2;")

#define LDM4(r, addr) \
    asm volatile("ldmatrix.sync.aligned.m8n8.x4.shared.b16 {%0,%1,%2,%3}, [%4];" \
        : "=r"((r)[0]), "=r"((r)[1]), "=r"((r)[2]), "=r"((r)[3]) : "r"(addr))

#define MMAH(d, a, b0, b1) \
    asm volatile("mma.sync.aligned.m16n8k16.row.col.f32.f16.f16.f32 " \
        "{%0,%1,%2,%3}, {%4,%5,%6,%7}, {%8,%9}, {%0,%1,%2,%3};" \
        : "+f"((d)[0]), "+f"((d)[1]), "+f"((d)[2]), "+f"((d)[3]) \
        : "r"((a)[0]), "r"((a)[1]), "r"((a)[2]), "r"((a)[3]), "r"(b0), "r"(b1))

// packed fp32x2 (Blackwell base ISA, sm_100+)
#define FMA2(d, a, b, c) asm("fma.rn.f32x2 %0, %1, %2, %3;" : "=l"(d) : "l"(a), "l"(b), "l"(c))
#define MUL2(d, a, b)    asm("mul.rn.f32x2 %0, %1, %2;" : "=l"(d) : "l"(a), "l"(b))
#define ADD2(d, a, b)    asm("add.rn.f32x2 %0, %1, %2;" : "=l"(d) : "l"(a), "l"(b))
#define PACKF2(d, lo, hi) asm("mov.b64 %0, {%1, %2};" : "=l"(d) : "f"(lo), "f"(hi))
#define UNPACKF2(lo, hi, s) asm("mov.b64 {%0, %1}, %2;" : "=f"(lo), "=f"(hi) : "l"(s))
#define LDSV2U64(a, b, addr) \
    asm volatile("ld.shared.v2.b64 {%0, %1}, [%2];" : "=l"(a), "=l"(b) : "r"(addr))

// ---------------- seg ids + flags ----------------
__global__ void k_prep(const int* __restrict__ cu) {
    int t = blockIdx.x * 256 + threadIdx.x;
    if (t >= TT) return;
    int seg = 0;
#pragma unroll
    for (int s = 1; s <= NSEG; ++s) if (t >= cu[s]) seg = s;
    d_seg[t] = seg;
    int fl = (t == cu[seg]) ? 1 : 0;
#pragma unroll
    for (int s = 0; s < NSEG; ++s) if (t == cu[s + 1] - 1) fl |= ((s + 1) << 1);
    d_flags[t] = fl;
}

// ---------------- embed + rmsnorm + fp16 conversion ----------------
__global__ void k_embed(const float* __restrict__ x, const int* __restrict__ acidx,
                        const float* __restrict__ actab, const float* __restrict__ Win,
                        const float* __restrict__ bin, const float* __restrict__ nw) {
    __shared__ float sx[8][48];
    __shared__ float sps[8][256];
    __shared__ float srms[8];
    int t0 = blockIdx.x * 8;
    int tid = threadIdx.x;
    for (int idx = tid; idx < 8 * 48; idx += 256) {
        int r = idx / 48, i = idx % 48;
        int t = t0 + r;
        float v;
        if (i < DIN) v = x[t * DIN + i];
        else v = actab[acidx[d_seg[t]] * ACD + (i - DIN)];
        sx[r][i] = v;
    }
    __syncthreads();

    float hreg[4][8];
    float ps[8];
#pragma unroll
    for (int r = 0; r < 8; ++r) ps[r] = 0.f;

#pragma unroll
    for (int jj = 0; jj < 4; ++jj) {
        int j = tid + jj * 256;
        float acc[8];
        float bb = bin[j];
#pragma unroll
        for (int r = 0; r < 8; ++r) acc[r] = bb;
        for (int i = 0; i < 48; ++i) {
            float w = Win[i * HH + j];
#pragma unroll
            for (int r = 0; r < 8; ++r) acc[r] = fmaf(sx[r][i], w, acc[r]);
        }
#pragma unroll
        for (int r = 0; r < 8; ++r) { hreg[jj][r] = acc[r]; ps[r] = fmaf(acc[r], acc[r], ps[r]); }
    }
#pragma unroll
    for (int r = 0; r < 8; ++r) sps[r][tid] = ps[r];
    __syncthreads();
    int w = tid >> 5, lane = tid & 31;
    float s = sps[w][lane];
#pragma unroll
    for (int i = 1; i < 8; ++i) s += sps[w][lane + 32 * i];
#pragma unroll
    for (int off = 16; off; off >>= 1) s += __shfl_xor_sync(0xffffffffu, s, off);
    if (lane == 0) srms[w] = rsqrtf(s / (float)HH + 1e-6f);
    __syncthreads();

    int needr[8];
#pragma unroll
    for (int r = 0; r < 8; ++r) needr[r] = d_flags[t0 + r] >> 1;

#pragma unroll
    for (int jj = 0; jj < 4; ++jj) {
        int j = tid + jj * 256;
        float nwj = 1.0f + nw[j];
#pragma unroll
        for (int r = 0; r < 8; ++r) {
            int t = t0 + r;
            float val = hreg[jj][r] * srms[r] * nwj;
            d_hn[t * HH + j] = val;
            d_hnf[(size_t)t * HH + j] = __float2half(val);
            if (needr[r]) d_hrows[(needr[r] - 1) * HH + j] = hreg[jj][r];
        }
    }
}

// ---------------- weight transpose + fp16 ----------------
__global__ void k_wcvt(const float* __restrict__ W, __half* __restrict__ outw, int N) {
    __shared__ float tile[32][33];
    int n0 = blockIdx.x * 32, k0 = blockIdx.y * 32;
    int tx = threadIdx.x, ty = threadIdx.y;
    for (int i = ty; i < 32; i += 8)
        tile[i][tx] = W[(size_t)(k0 + i) * N + n0 + tx];
    __syncthreads();
    for (int i = ty; i < 32; i += 8)
        outw[(size_t)(n0 + i) * HH + k0 + tx] = __float2half(tile[tx][i]);
}

// ---------------- Wa/Wb transpose ----------------
__global__ void k_wt(const float* __restrict__ Wa, const float* __restrict__ Wb) {
    int c = blockIdx.x;
    int tid = threadIdx.x;
    const float* src = (c < NHH) ? Wa : Wb;
    int cc = (c < NHH) ? c : c - NHH;
    for (int k = tid; k < HH; k += 256)
        d_wt[c * HH + k] = src[(size_t)k * NHH + cc];
}

// ---------------- fp16 mma.sync GEMM, merged K+V launch ----------------
// ntile < KDIM/128 -> K output, else V output. 4-stage, single barrier.
#define MM_ROW   40
#define MM_ATEN  (128 * MM_ROW)
#define MM_BTEN  (128 * MM_ROW)
#define MM_STG   (MM_ATEN + MM_BTEN)
#define MM_NSTG  4
#define MM_SMEM  (MM_NSTG * MM_STG * 2)    // 81920 bytes
#define MM_NCH   (HH / 32)
#define NKT      (KDIM / 128)              // 6 K tiles

__global__ void __launch_bounds__(256, 2)
k_mma(const __half* __restrict__ A_, const __half* __restrict__ Bk_,
      const __half* __restrict__ Bv_, float* __restrict__ Ck,
      float* __restrict__ Cv) {
    extern __shared__ __align__(128) __half sm[];
    uint32_t sb = smem_u32(sm);
    int tid = threadIdx.x, lane = tid & 31, wid = tid >> 5;
    int wm = wid & 1, wn = wid >> 1;
    int ntile = blockIdx.x, mtile = blockIdx.y;

    int isV = (ntile >= NKT);
    int nloc = isV ? (ntile - NKT) : ntile;
    const __half* Bsrc = isV ? Bv_ : Bk_;
    float* C = isV ? Cv : Ck;
    int N = isV ? VDIM : KDIM;

    const __half* Af = A_ + (size_t)(mtile * 128) * HH;
    const __half* Bf = Bsrc + (size_t)(nloc * 128) * HH;

    float acc[4][4][4];
#pragma unroll
    for (int m = 0; m < 4; ++m)
#pragma unroll
        for (int n = 0; n < 4; ++n)
#pragma unroll
            for (int i = 0; i < 4; ++i) acc[m][n][i] = 0.f;

    int ab[4];
#pragma unroll
    for (int m = 0; m < 4; ++m)
        ab[m] = (wm * 64 + m * 16 + (lane & 15)) * MM_ROW + (lane >> 4) * 8;
    int bb[2];
#pragma unroll
    for (int p = 0; p < 2; ++p)
        bb[p] = (wn * 32 + p * 16 + (lane & 7) + ((lane >> 4) & 1) * 8) * MM_ROW + ((lane >> 3) & 1) * 8;

    auto load_stage = [&](int stg, int k0) {
        uint32_t base = sb + 2 * (stg * MM_STG);
#pragma unroll
        for (int it = 0; it < 2; ++it) {
            int idx = tid + it * 256;
            int r = idx >> 2, cc = idx & 3;
            cpa16s(base + 2 * (r * MM_ROW + cc * 8), Af + (size_t)r * HH + k0 + cc * 8);
        }
#pragma unroll
        for (int it = 0; it < 2; ++it) {
            int idx = tid + it * 256;
            int r = idx >> 2, cc = idx & 3;
            cpa16s(base + 2 * (MM_ATEN + r * MM_ROW + cc * 8), Bf + (size_t)r * HH + k0 + cc * 8);
        }
    };

    load_stage(0, 0);  CPA_COMMIT;
    load_stage(1, 32); CPA_COMMIT;
    load_stage(2, 64); CPA_COMMIT;

    for (int c = 0; c < MM_NCH; ++c) {
        int stg = c & 3;
        CPA_WAIT2;
        __syncthreads();
        if (c + 3 < MM_NCH) load_stage((c + 3) & 3, (c + 3) * 32);
        CPA_COMMIT;

        uint32_t base = sb + 2 * (stg * MM_STG);
#pragma unroll
        for (int ks = 0; ks < 2; ++ks) {
            uint32_t a4[4][4];
#pragma unroll
            for (int m = 0; m < 4; ++m) LDM4(a4[m], base + 2 * (ab[m] + ks * 16));
#pragma unroll
            for (int p = 0; p < 2; ++p) {
                uint32_t rb[4];
                LDM4(rb, base + 2 * (MM_ATEN + bb[p] + ks * 16));
#pragma unroll
                for (int m = 0; m < 4; ++m) {
                    MMAH(acc[m][2 * p],     a4[m], rb[0], rb[1]);
                    MMAH(acc[m][2 * p + 1], a4[m], rb[2], rb[3]);
                }
            }
        }
    }

#pragma unroll
    for (int m = 0; m < 4; ++m) {
        int row = mtile * 128 + wm * 64 + m * 16 + (lane >> 2);
#pragma unroll
        for (int n = 0; n < 4; ++n) {
            int col = nloc * 128 + wn * 32 + n * 8 + (lane & 3) * 2;
            float2 v0 = make_float2(acc[m][n][0], acc[m][n][1]);
            float2 v1 = make_float2(acc[m][n][2], acc[m][n][3]);
            *(float2*)&C[(size_t)row * N + col] = v0;
            *(float2*)&C[(size_t)(row + 8) * N + col] = v1;
        }
    }
}

// ---------------- hn@[Wa|Wb] with coalesced transposed weights ----------------
__global__ void k_ab2(const float* __restrict__ Alog, const float* __restrict__ dtb) {
    int row = blockIdx.x * 8 + (threadIdx.x >> 5);
    int lane = threadIdx.x & 31;
    float4 hv[8];
    const float4* hp = (const float4*)(d_hn + (size_t)row * HH);
#pragma unroll
    for (int i = 0; i < 8; ++i) hv[i] = hp[lane + 32 * i];

    float res[24];
#pragma unroll
    for (int c = 0; c < 24; ++c) {
        const float4* wp = (const float4*)(d_wt + c * HH);
        float a0 = 0.f, a1 = 0.f, a2 = 0.f, a3 = 0.f;
#pragma unroll
        for (int i = 0; i < 8; ++i) {
            float4 w = wp[lane + 32 * i];
            a0 = fmaf(hv[i].x, w.x, a0);
            a1 = fmaf(hv[i].y, w.y, a1);
            a2 = fmaf(hv[i].z, w.z, a2);
            a3 = fmaf(hv[i].w, w.w, a3);
        }
        res[c] = (a0 + a1) + (a2 + a3);
    }
#pragma unroll
    for (int c = 0; c < 24; ++c) {
#pragma unroll
        for (int off = 16; off; off >>= 1)
            res[c] += __shfl_xor_sync(0xffffffffu, res[c], off);
    }
    if (lane < NHH) {
        float xx = res[lane] + dtb[lane];
        float sp = (xx > 20.f) ? xx : log1pf(expf(xx));
        float g = -expf(Alog[lane]) * sp;
        int fl = d_flags[row];
        float4 o;
        o.x = (fl & 1) ? 0.f : expf(g);
        o.y = sigmoidf_(res[12 + lane]);
        o.z = (float)(fl >> 1);
        o.w = 0.f;
        d_scd[(size_t)row * NHH + lane] = o;
    }
}

// ---------------- k-path conv + silu + l2norm, float4, 8 timesteps ----------------
#define KTCH 8
__global__ void __launch_bounds__(192) k_convk(const float* __restrict__ cw) {
    int tid = threadIdx.x;
    int c = tid * 4;
    int t0 = blockIdx.x * KTCH;
    float4 w0, w1, w2, w3;
    {
        const float4* cwp = (const float4*)(cw + c * 4);
        float4 a = cwp[0], b = cwp[1], cc2 = cwp[2], d = cwp[3];
        w0 = make_float4(a.x, b.x, cc2.x, d.x);
        w1 = make_float4(a.y, b.y, cc2.y, d.y);
        w2 = make_float4(a.z, b.z, cc2.z, d.z);
        w3 = make_float4(a.w, b.w, cc2.w, d.w);
    }
    float4 xm1 = {0,0,0,0}, xm2 = {0,0,0,0}, xm3 = {0,0,0,0};
    int st1 = 1, st2 = 1;
    if (t0 >= 1) { xm1 = *(const float4*)&d_kpre[(size_t)(t0 - 1) * KDIM + c]; st1 = d_flags[t0 - 1] & 1; }
    if (t0 >= 2) { xm2 = *(const float4*)&d_kpre[(size_t)(t0 - 2) * KDIM + c]; st2 = d_flags[t0 - 2] & 1; }
    if (t0 >= 3) { xm3 = *(const float4*)&d_kpre[(size_t)(t0 - 3) * KDIM + c]; }

    float4 val[KTCH];
    float ssq[KTCH];
#pragma unroll
    for (int tt = 0; tt < KTCH; ++tt) {
        int t = t0 + tt;
        float4 xt = *(const float4*)&d_kpre[(size_t)t * KDIM + c];
        int st = d_flags[t] & 1;
        float4 a;
        a.x = xt.x * w3.x; a.y = xt.y * w3.y; a.z = xt.z * w3.z; a.w = xt.w * w3.w;
        if (!st) {
            a.x = fmaf(xm1.x, w2.x, a.x); a.y = fmaf(xm1.y, w2.y, a.y);
            a.z = fmaf(xm1.z, w2.z, a.z); a.w = fmaf(xm1.w, w2.w, a.w);
            if (!st1) {
                a.x = fmaf(xm2.x, w1.x, a.x); a.y = fmaf(xm2.y, w1.y, a.y);
                a.z = fmaf(xm2.z, w1.z, a.z); a.w = fmaf(xm2.w, w1.w, a.w);
                if (!st2) {
                    a.x = fmaf(xm3.x, w0.x, a.x); a.y = fmaf(xm3.y, w0.y, a.y);
                    a.z = fmaf(xm3.z, w0.z, a.z); a.w = fmaf(xm3.w, w0.w, a.w);
                }
            }
        }
        float4 v;
        v.x = a.x * sigmoidf_(a.x); v.y = a.y * sigmoidf_(a.y);
        v.z = a.z * sigmoidf_(a.z); v.w = a.w * sigmoidf_(a.w);
        val[tt] = v;
        ssq[tt] = fmaf(v.x, v.x, fmaf(v.y, v.y, fmaf(v.z, v.z, v.w * v.w)));
        xm3 = xm2; xm2 = xm1; xm1 = xt;
        st2 = st1; st1 = st;
    }
#pragma unroll
    for (int tt = 0; tt < KTCH; ++tt) {
        float s = ssq[tt];
        s += __shfl_xor_sync(0xffffffffu, s, 1);
        s += __shfl_xor_sync(0xffffffffu, s, 2);
        s += __shfl_xor_sync(0xffffffffu, s, 4);
        s += __shfl_xor_sync(0xffffffffu, s, 8);
        float r = rsqrtf(s + 1e-6f);
        float4 v = val[tt];
        v.x *= r; v.y *= r; v.z *= r; v.w *= r;
        *(float4*)&d_k[(size_t)(t0 + tt) * KDIM + c] = v;
    }
}

// ---------------- v-path conv + silu, float4, immediate store ----------------
#define VTCH 16
__global__ void __launch_bounds__(192) k_conv2(const float* __restrict__ cw) {
    int c = (blockIdx.x * 192 + threadIdx.x) * 4;
    int t0 = blockIdx.y * VTCH;
    float4 w0, w1, w2, w3;
    {
        const float4* cwp = (const float4*)(cw + c * 4);
        float4 a = cwp[0], b = cwp[1], cc2 = cwp[2], d = cwp[3];
        w0 = make_float4(a.x, b.x, cc2.x, d.x);
        w1 = make_float4(a.y, b.y, cc2.y, d.y);
        w2 = make_float4(a.z, b.z, cc2.z, d.z);
        w3 = make_float4(a.w, b.w, cc2.w, d.w);
    }
    float4 xm1 = {0,0,0,0}, xm2 = {0,0,0,0}, xm3 = {0,0,0,0};
    int st1 = 1, st2 = 1;
    if (t0 >= 1) { xm1 = *(const float4*)&d_vpre[(size_t)(t0 - 1) * VDIM + c]; st1 = d_flags[t0 - 1] & 1; }
    if (t0 >= 2) { xm2 = *(const float4*)&d_vpre[(size_t)(t0 - 2) * VDIM + c]; st2 = d_flags[t0 - 2] & 1; }
    if (t0 >= 3) { xm3 = *(const float4*)&d_vpre[(size_t)(t0 - 3) * VDIM + c]; }
#pragma unroll 4
    for (int tt = 0; tt < VTCH; ++tt) {
        int t = t0 + tt;
        float4 xt = *(const float4*)&d_vpre[(size_t)t * VDIM + c];
        int st = d_flags[t] & 1;
        float4 a;
        a.x = xt.x * w3.x; a.y = xt.y * w3.y; a.z = xt.z * w3.z; a.w = xt.w * w3.w;
        if (!st) {
            a.x = fmaf(xm1.x, w2.x, a.x); a.y = fmaf(xm1.y, w2.y, a.y);
            a.z = fmaf(xm1.z, w2.z, a.z); a.w = fmaf(xm1.w, w2.w, a.w);
            if (!st1) {
                a.x = fmaf(xm2.x, w1.x, a.x); a.y = fmaf(xm2.y, w1.y, a.y);
                a.z = fmaf(xm2.z, w1.z, a.z); a.w = fmaf(xm2.w, w1.w, a.w);
                if (!st2) {
                    a.x = fmaf(xm3.x, w0.x, a.x); a.y = fmaf(xm3.y, w0.y, a.y);
                    a.z = fmaf(xm3.z, w0.z, a.z); a.w = fmaf(xm3.w, w0.w, a.w);
                }
            }
        }
        float4 v;
        v.x = a.x * sigmoidf_(a.x); v.y = a.y * sigmoidf_(a.y);
        v.z = a.z * sigmoidf_(a.z); v.w = a.w * sigmoidf_(a.w);
        *(float4*)&d_v[(size_t)t * VDIM + c] = v;
        xm3 = xm2; xm2 = xm1; xm1 = xt;
        st2 = st1; st1 = st;
    }
}

// ---------------- q at the 16 pooled positions ----------------
__global__ void k_q16(const int* __restrict__ cu, const float* __restrict__ Wq,
                      const float* __restrict__ cw) {
    __shared__ float shn[4][HH];
    __shared__ float sq[KDIM];
    int s = blockIdx.x;
    int pos = cu[s + 1] - 1;
    int seg = d_seg[pos];
    int tid = threadIdx.x;
    int valid[4];
#pragma unroll
    for (int r = 0; r < 4; ++r) {
        int t = pos - r;
        valid[r] = (t >= 0 && d_seg[t] == seg);
    }
#pragma unroll
    for (int r = 0; r < 4; ++r) {
        int t = pos - r;
        if (valid[r]) for (int i = tid; i < HH; i += 256) shn[r][i] = d_hn[(size_t)t * HH + i];
        else          for (int i = tid; i < HH; i += 256) shn[r][i] = 0.f;
    }
    __syncthreads();
    for (int c = tid; c < KDIM; c += 256) {
        float a0 = 0.f, a1 = 0.f, a2 = 0.f, a3 = 0.f;
        for (int i = 0; i < HH; ++i) {
            float wv = Wq[(size_t)i * KDIM + c];
            a0 = fmaf(shn[0][i], wv, a0);
            a1 = fmaf(shn[1][i], wv, a1);
            a2 = fmaf(shn[2][i], wv, a2);
            a3 = fmaf(shn[3][i], wv, a3);
        }
        float acc = a0 * cw[c * 4 + 3] + a1 * cw[c * 4 + 2] + a2 * cw[c * 4 + 1] + a3 * cw[c * 4 + 0];
        sq[c] = acc * sigmoidf_(acc);
    }
    __syncthreads();
    int w = tid >> 5, lane = tid & 31;
    for (int h = w; h < NHH; h += 8) {
        float ssq = 0.f;
        for (int i = lane; i < HKD; i += 32) { float v = sq[h * HKD + i]; ssq = fmaf(v, v, ssq); }
#pragma unroll
        for (int off = 16; off; off >>= 1) ssq += __shfl_xor_sync(0xffffffffu, ssq, off);
        float r = rsqrtf(ssq + 1e-6f) * 0.125f;
        for (int i = lane; i < HKD; i += 32)
            d_q[s * KDIM + h * HKD + i] = sq[h * HKD + i] * r;
    }
}

// ---------------- segment-parallel scan, packed f32x2, unroll-2, 4-acc dot ----------------
__global__ void __launch_bounds__(128) k_scan(const int* __restrict__ cu) {
    __shared__ float  sk[2][SCH][64];
    __shared__ float  svv[2][SCH][64];
    __shared__ float4 scd[2][SCH];

    int half = blockIdx.x;
    int h    = blockIdx.y;
    int s    = blockIdx.z;
    int tid  = threadIdx.x;
    int colL = tid >> 1;
    int e    = tid & 1;
    int col  = half * 64 + colL;

    int start = cu[s];
    int end   = cu[s + 1];
    int len   = end - start;

    auto load_chunk = [&](int buf, int c0) {
        int rem = len - c0; if (rem > SCH) rem = SCH;
        for (int idx = tid; idx < rem * 16; idx += 128) {
            int i = idx >> 4, j = idx & 15;
            cpa16(&sk[buf][i][j * 4], d_k + (size_t)(start + c0 + i) * KDIM + h * HKD + j * 4);
        }
        for (int idx = tid; idx < rem * 16; idx += 128) {
            int i = idx >> 4, j = idx & 15;
            cpa16(&svv[buf][i][j * 4], d_v + (size_t)(start + c0 + i) * VDIM + h * HVD + half * 64 + j * 4);
        }
        if (tid < rem)
            cpa16(&scd[buf][tid], d_scd + (size_t)(start + c0 + tid) * NHH + h);
    };

    uint64_t S2[16];
#pragma unroll
    for (int i = 0; i < 16; ++i) S2[i] = 0ull;

    auto step = [&](const uint64_t* K2, float vv, float4 cd) {
        // 4-accumulator dot: chain depth 4 instead of 8
        uint64_t a0 = 0ull, a1 = 0ull, a2 = 0ull, a3 = 0ull;
#pragma unroll
        for (int j = 0; j < 16; j += 4) {
            FMA2(a0, S2[j],     K2[j],     a0);
            FMA2(a1, S2[j + 1], K2[j + 1], a1);
            FMA2(a2, S2[j + 2], K2[j + 2], a2);
            FMA2(a3, S2[j + 3], K2[j + 3], a3);
        }
        ADD2(a0, a0, a1);
        ADD2(a2, a2, a3);
        ADD2(a0, a0, a2);
        float lo, hi;
        UNPACKF2(lo, hi, a0);
        float dot = lo + hi;
        dot += __shfl_xor_sync(0xffffffffu, dot, 1);

        float lam = cd.x;
        float delta = cd.y * fmaf(-lam, dot, vv);
        uint64_t lam2, d2;
        PACKF2(lam2, lam, lam);
        PACKF2(d2, delta, delta);
#pragma unroll
        for (int j = 0; j < 16; ++j) {
            uint64_t t;
            MUL2(t, K2[j], d2);
            FMA2(S2[j], lam2, S2[j], t);
        }

        if (cd.z != 0.f) {
            int need = (int)cd.z - 1;
            const float4* qp = (const float4*)(d_q + (size_t)need * KDIM + h * HKD + e * 32);
            uint64_t oa = 0ull;
#pragma unroll
            for (int j = 0; j < 8; ++j) {
                float4 qv = qp[j];
                uint64_t q0, q1;
                PACKF2(q0, qv.x, qv.y);
                PACKF2(q1, qv.z, qv.w);
                FMA2(oa, S2[2 * j],     q0, oa);
                FMA2(oa, S2[2 * j + 1], q1, oa);
            }
            float olo, ohi;
            UNPACKF2(olo, ohi, oa);
            float od = olo + ohi;
            od += __shfl_xor_sync(0xffffffffu, od, 1);
            if (e == 0) d_o[need * VDIM + h * HVD + col] = od;
        }
    };

    auto loadK = [&](uint64_t* K2, int buf, int i) {
#pragma unroll
        for (int j = 0; j < 8; ++j) {
            uint32_t addr = smem_u32(&sk[buf][i][e * 32 + j * 4]);
            LDSV2U64(K2[2 * j], K2[2 * j + 1], addr);
        }
    };

    load_chunk(0, 0);
    CPA_COMMIT;

    int buf = 0;
    for (int c0 = 0; c0 < len; c0 += SCH, buf ^= 1) {
        __syncthreads();
        if (c0 + SCH < len) load_chunk(buf ^ 1, c0 + SCH);
        CPA_COMMIT;
        CPA_WAIT1;
        __syncthreads();

        int rem = len - c0; if (rem > SCH) rem = SCH;

        uint64_t Ka[16], Kb[16];
        float  va, vb;
        float4 cda, cdb;
        loadK(Ka, buf, 0);
        va  = svv[buf][0][colL];
        cda = scd[buf][0];

        int i = 0;
        while (i < rem) {
            int ip = (i + 1 < rem) ? i + 1 : i;
            loadK(Kb, buf, ip);
            vb  = svv[buf][ip][colL];
            cdb = scd[buf][ip];
            step(Ka, va, cda);
            ++i;
            if (i >= rem) break;
            int ip2 = (i + 1 < rem) ? i + 1 : i;
            loadK(Ka, buf, ip2);
            va  = svv[buf][ip2][colL];
            cda = scd[buf][ip2];
            step(Kb, vb, cdb);
            ++i;
        }
    }
}

// ---------------- Wo @ W_head ----------------
__global__ void k_wowh(const float* __restrict__ Wo, const float* __restrict__ Wh) {
    int j = blockIdx.x * 8 + (threadIdx.x >> 5);
    int lane = threadIdx.x & 31;
    float a = 0.f;
    for (int k = lane; k < HH; k += 32) a = fmaf(Wo[(size_t)j * HH + k], Wh[k], a);
#pragma unroll
    for (int off = 16; off; off >>= 1) a += __shfl_xor_sync(0xffffffffu, a, off);
    if (lane == 0) d_wowh[j] = a;
}

// ---------------- gate precompute (scan-independent): d_og = gs ----------------
__global__ void k_gatepre(const int* __restrict__ cu, const float* __restrict__ Wg) {
    __shared__ float shn[HH];
    int hd = blockIdx.x;
    int s = blockIdx.y;
    int pos = cu[s + 1] - 1;
    int tid = threadIdx.x;
    for (int i = tid; i < HH; i += 128) shn[i] = d_hn[(size_t)pos * HH + i];
    __syncthreads();
    float gate = 0.f;
    for (int i = 0; i < HH; ++i)
        gate = fmaf(shn[i], Wg[(size_t)i * VDIM + hd * HVD + tid], gate);
    d_og[s * VDIM + hd * HVD + tid] = gate * sigmoidf_(gate);
}

// ---------------- final: o-rmsnorm + gate + head ----------------
__global__ void k_final(const float* __restrict__ Wh, const float* __restrict__ bh,
                        const float* __restrict__ onw, float* __restrict__ out) {
    __shared__ float so[VDIM];
    __shared__ float hs[NHH];
    __shared__ float sred[256];
    int s = blockIdx.x;
    int tid = threadIdx.x;
    if (tid < NHH) hs[tid] = 0.f;
    __syncthreads();
    for (int j = tid; j < VDIM; j += 256) {
        float ov = d_o[s * VDIM + j];
        so[j] = ov;
        atomicAdd(&hs[j >> 7], ov * ov);
    }
    __syncthreads();
    float a = 0.f;
    for (int j = tid; j < VDIM; j += 256) {
        float rms = rsqrtf(hs[j >> 7] / (float)HVD + 1e-5f);
        a = fmaf(so[j] * rms * onw[j & 127] * d_og[s * VDIM + j], d_wowh[j], a);
    }
    for (int k = tid; k < HH; k += 256) a = fmaf(d_hrows[s * HH + k], Wh[k], a);
    sred[tid] = a;
    __syncthreads();
    for (int st = 128; st; st >>= 1) {
        if (tid < st) sred[tid] += sred[tid + st];
        __syncthreads();
    }
    if (tid == 0) out[s] = sred[0] + bh[0];
}

// ---------------- launch ----------------
extern "C" void kernel_launch(void* const* d_in, const int* in_sizes, int n_in,
                              void* d_out, int out_size) {
    const float* x     = (const float*)d_in[0];
    const int*   cu    = (const int*)d_in[1];
    const int*   acidx = (const int*)d_in[2];
    const float* actab = (const float*)d_in[3];
    const float* Win   = (const float*)d_in[4];
    const float* bin   = (const float*)d_in[5];
    const float* nw    = (const float*)d_in[6];
    const float* Wq    = (const float*)d_in[7];
    const float* Wk    = (const float*)d_in[8];
    const float* Wv    = (const float*)d_in[9];
    const float* cqw   = (const float*)d_in[10];
    const float* ckw   = (const float*)d_in[11];
    const float* cvw   = (const float*)d_in[12];
    const float* Wb    = (const float*)d_in[13];
    const float* Wa    = (const float*)d_in[14];
    const float* Alog  = (const float*)d_in[15];
    const float* dtb   = (const float*)d_in[16];
    const float* Wg    = (const float*)d_in[17];
    const float* onw   = (const float*)d_in[18];
    const float* Wo    = (const float*)d_in[19];
    const float* Wh    = (const float*)d_in[20];
    const float* bh    = (const float*)d_in[21];
    float* out = (float*)d_out;

    cudaFuncSetAttribute(k_mma, cudaFuncAttributeMaxDynamicSharedMemorySize, MM_SMEM);

    __half *wkf, *wvf, *hnf;
    cudaGetSymbolAddress((void**)&wkf, d_wkf);
    cudaGetSymbolAddress((void**)&wvf, d_wvf);
    cudaGetSymbolAddress((void**)&hnf, d_hnf);
    float *kpre, *vpre;
    cudaGetSymbolAddress((void**)&kpre, d_kpre);
    cudaGetSymbolAddress((void**)&vpre, d_vpre);

    k_prep<<<TT / 256, 256>>>(cu);
    k_embed<<<TT / 8, 256>>>(x, acidx, actab, Win, bin, nw);

    k_wcvt<<<dim3(KDIM / 32, HH / 32), dim3(32, 8)>>>(Wk, wkf, KDIM);
    k_wcvt<<<dim3(VDIM / 32, HH / 32), dim3(32, 8)>>>(Wv, wvf, VDIM);

    k_mma<<<dim3((KDIM + VDIM) / 128, TT / 128), 256, MM_SMEM>>>(hnf, wkf, wvf, kpre, vpre);

    k_wt<<<24, 256>>>(Wa, Wb);
    k_ab2<<<TT / 8, 256>>>(Alog, dtb);
    k_convk<<<TT / KTCH, 192>>>(ckw);
    k_conv2<<<dim3(VDIM / (192 * 4), TT / VTCH), 192>>>(cvw);
    k_q16<<<NSEG, 256>>>(cu, Wq, cqw);
    k_wowh<<<VDIM / 8, 256>>>(Wo, Wh);
    k_gatepre<<<dim3(NHH, NSEG), 128>>>(cu, Wg);

    k_scan<<<dim3(2, NHH, NSEG), 128>>>(cu);

    k_final<<<NSEG, 256>>>(Wh, bh, onw, out);
}